// round 2
// baseline (speedup 1.0000x reference)
#include <cuda_runtime.h>
#include <math.h>

// ---- problem constants ----
#define BB 8
#define LL 512
#define EE 256
#define HH 8
#define HD 32
#define BD_ 64
#define TD_ 256
#define TE_ 128
#define ED_ 64
#define MM_ 512
#define NROWS (BB*LL)          // 4096 token rows

// ---- scratch (device globals; no runtime allocation) ----
__device__ float g_u[NROWS*TD_];                       // silu(s)         4 MB
__device__ float g_m[NROWS*6*EE];                      // modulations    25 MB
__device__ float g_x[NROWS*EE];                        // staging         4 MB
__device__ float g_bias[(size_t)BB*HH*LL*LL];          // attn bias      64 MB
__device__ float g_qkv[NROWS*3*EE];                    // qkv            12 MB
__device__ float g_scores[(size_t)BB*HH*LL*LL];        // scores/attn    64 MB
__device__ float g_o[NROWS*EE];                        // attn out        4 MB
__device__ float g_h1[NROWS*EE];                       // residual 1      4 MB
__device__ float g_t1[NROWS*MM_];                      // mlp hidden      8 MB
__device__ float g_h2[NROWS*EE];                       // residual 2      4 MB

// =====================================================================
// k_cond1: u = silu(s_a @ W_bp^T + b_bp + s_t)      [4096, 256]
// =====================================================================
__global__ void k_cond1(const float* __restrict__ s_a, const float* __restrict__ s_t,
                        const float* __restrict__ W_bp, const float* __restrict__ b_bp)
{
    int row = blockIdx.x;
    int t = threadIdx.x;                  // 256 threads = TD outputs
    __shared__ float sa[BD_];
    if (t < BD_) sa[t] = s_a[(size_t)row*BD_ + t];
    __syncthreads();
    float acc = b_bp[t];
    const float* w = W_bp + (size_t)t*BD_;
    #pragma unroll 16
    for (int k = 0; k < BD_; k++) acc += sa[k]*w[k];
    acc += s_t[(size_t)row*TD_ + t];
    g_u[(size_t)row*TD_ + t] = acc / (1.f + expf(-acc));   // silu
}

// =====================================================================
// Generic tiled SGEMM: C[M,N] = A[M,K] @ B[N,K]^T  (+ epilogues)
// BM=BN=64, BK=16, 256 threads, 4x4 per-thread tile
// =====================================================================
#define EPI_BIAS     0
#define EPI_SILU     1
#define EPI_GATE_RES 2
#define EPI_ADD_RES  3

template<int EPI>
__global__ void k_gemm(const float* __restrict__ A, const float* __restrict__ B,
                       float* __restrict__ C, int Md, int Nd, int Kd,
                       const float* __restrict__ bias,
                       const float* __restrict__ gate, int gstride, int goff,
                       const float* __restrict__ res)
{
    const int BK = 16;
    __shared__ __align__(16) float As[BK][64];
    __shared__ __align__(16) float Bs[BK][64];
    int bm = blockIdx.y*64, bn = blockIdx.x*64;
    int tid = threadIdx.x;
    int tx = tid & 15, ty = tid >> 4;
    float acc[4][4] = {};
    for (int k0 = 0; k0 < Kd; k0 += BK) {
        #pragma unroll
        for (int i = 0; i < 4; i++) {
            int lin = tid + i*256;
            int r = lin >> 4, kk = lin & 15;
            As[kk][r] = A[(size_t)(bm + r)*Kd + k0 + kk];
            Bs[kk][r] = B[(size_t)(bn + r)*Kd + k0 + kk];
        }
        __syncthreads();
        #pragma unroll
        for (int kk = 0; kk < BK; kk++) {
            float4 a4 = *(const float4*)&As[kk][ty*4];
            float4 b4 = *(const float4*)&Bs[kk][tx*4];
            float a[4] = {a4.x, a4.y, a4.z, a4.w};
            float b[4] = {b4.x, b4.y, b4.z, b4.w};
            #pragma unroll
            for (int i = 0; i < 4; i++)
                #pragma unroll
                for (int j = 0; j < 4; j++)
                    acc[i][j] += a[i]*b[j];
        }
        __syncthreads();
    }
    #pragma unroll
    for (int i = 0; i < 4; i++) {
        int m = bm + ty*4 + i;
        #pragma unroll
        for (int j = 0; j < 4; j++) {
            int n = bn + tx*4 + j;
            float v = acc[i][j] + bias[n];
            if (EPI == EPI_SILU)     v = v / (1.f + expf(-v));
            if (EPI == EPI_GATE_RES) v = v*gate[(size_t)m*gstride + goff + n] + res[(size_t)m*Nd + n];
            if (EPI == EPI_ADD_RES)  v = v + res[(size_t)m*Nd + n];
            C[(size_t)m*Nd + n] = v;
        }
    }
}

// =====================================================================
// k_xmod: dst = LN(src_row)*(1 + m[:,sc]) + m[:,sh]    (row = 256 wide)
// =====================================================================
__global__ void k_xmod(const float* __restrict__ src, int sh_off, int sc_off,
                       float* __restrict__ dst)
{
    int row = blockIdx.x, t = threadIdx.x;
    float v = src[(size_t)row*EE + t];
    __shared__ float s1[8], s2[8], bc[2];
    float a = v, b = v*v;
    #pragma unroll
    for (int o = 16; o > 0; o >>= 1) {
        a += __shfl_xor_sync(0xffffffffu, a, o);
        b += __shfl_xor_sync(0xffffffffu, b, o);
    }
    if ((t & 31) == 0) { s1[t>>5] = a; s2[t>>5] = b; }
    __syncthreads();
    if (t == 0) {
        float x = 0, y = 0;
        for (int i = 0; i < 8; i++) { x += s1[i]; y += s2[i]; }
        bc[0] = x*(1.f/EE); bc[1] = y*(1.f/EE);
    }
    __syncthreads();
    float mu = bc[0], var = bc[1] - mu*mu;
    float n = (v - mu)*rsqrtf(var + 1e-5f);
    const float* mrow = g_m + (size_t)row*(6*EE);
    dst[(size_t)row*EE + t] = n*(1.f + mrow[sc_off + t]) + mrow[sh_off + t];
}

// =====================================================================
// k_ln_affine: dst = LN(src_row)*g + bt
// =====================================================================
__global__ void k_ln_affine(const float* __restrict__ src, const float* __restrict__ g,
                            const float* __restrict__ bt, float* __restrict__ dst)
{
    int row = blockIdx.x, t = threadIdx.x;
    float v = src[(size_t)row*EE + t];
    __shared__ float s1[8], s2[8], bc[2];
    float a = v, b = v*v;
    #pragma unroll
    for (int o = 16; o > 0; o >>= 1) {
        a += __shfl_xor_sync(0xffffffffu, a, o);
        b += __shfl_xor_sync(0xffffffffu, b, o);
    }
    if ((t & 31) == 0) { s1[t>>5] = a; s2[t>>5] = b; }
    __syncthreads();
    if (t == 0) {
        float x = 0, y = 0;
        for (int i = 0; i < 8; i++) { x += s1[i]; y += s2[i]; }
        bc[0] = x*(1.f/EE); bc[1] = y*(1.f/EE);
    }
    __syncthreads();
    float mu = bc[0], var = bc[1] - mu*mu;
    float n = (v - mu)*rsqrtf(var + 1e-5f);
    dst[(size_t)row*EE + t] = n*g[t] + bt[t];
}

// =====================================================================
// k_bias: bias[b,h,l,m] = (LN(p[b,l,m,:])*g_eln + b_eln) @ W_e^T + b_e
// warp per (b,l,m) row of 64; smem-staged transposed write (coalesced)
// =====================================================================
__global__ void k_bias(const float* __restrict__ p, const float* __restrict__ g_eln,
                       const float* __restrict__ b_eln, const float* __restrict__ W_e,
                       const float* __restrict__ b_e)
{
    __shared__ float sWe[HH][ED_];
    __shared__ float sge[ED_], sbe[ED_], sbh[HH];
    __shared__ float sout[HH][8];
    int tid = threadIdx.x;
    // FIX: HH*ED_ = 512 > blockDim (256) -> strided load (was loading only half of W_e)
    for (int i = tid; i < HH*ED_; i += 256)
        sWe[i>>6][i & 63] = W_e[i];
    if (tid < ED_) { sge[tid] = g_eln[tid]; sbe[tid] = b_eln[tid]; }
    if (tid < HH) sbh[tid] = b_e[tid];
    __syncthreads();

    int warp = tid >> 5, lane = tid & 31;
    size_t row = (size_t)blockIdx.x*8 + warp;        // index over (b, l, m)
    const float* pr = p + row*ED_;
    float v0 = pr[lane], v1 = pr[lane + 32];
    float s = v0 + v1, q = v0*v0 + v1*v1;
    #pragma unroll
    for (int o = 16; o > 0; o >>= 1) {
        s += __shfl_xor_sync(0xffffffffu, s, o);
        q += __shfl_xor_sync(0xffffffffu, q, o);
    }
    float mu = s*(1.f/64.f);
    float var = q*(1.f/64.f) - mu*mu;
    float rstd = rsqrtf(var + 1e-5f);
    float n0 = (v0 - mu)*rstd*sge[lane] + sbe[lane];
    float n1 = (v1 - mu)*rstd*sge[lane + 32] + sbe[lane + 32];
    #pragma unroll
    for (int h = 0; h < HH; h++) {
        float ph = n0*sWe[h][lane] + n1*sWe[h][lane + 32];
        #pragma unroll
        for (int o = 16; o > 0; o >>= 1) ph += __shfl_xor_sync(0xffffffffu, ph, o);
        if (lane == 0) sout[h][warp] = ph + sbh[h];
    }
    __syncthreads();
    if (tid < HH*8) {
        size_t row0 = (size_t)blockIdx.x*8;
        int m0 = (int)(row0 & (LL - 1));
        int l  = (int)((row0 >> 9) & (LL - 1));
        int b  = (int)(row0 >> 18);
        int h = tid >> 3, w = tid & 7;
        g_bias[(((size_t)b*HH + h)*LL + l)*LL + m0 + w] = sout[h][w];
    }
}

// =====================================================================
// k_scores: scores[b,h,l,m] = (q.k)/sqrt(32) + bias     64x64 tiles
// =====================================================================
__global__ void k_scores()
{
    __shared__ __align__(16) float Qs[HD][64];
    __shared__ __align__(16) float Ks[HD][64];
    int bh = blockIdx.z;
    int b = bh >> 3, h = bh & 7;
    int l0 = blockIdx.y*64, m0 = blockIdx.x*64;
    int tid = threadIdx.x;
    #pragma unroll
    for (int i = 0; i < 8; i++) {
        int lin = tid + i*256;
        int r = lin >> 5, d = lin & 31;
        Qs[d][r] = g_qkv[(size_t)(b*LL + l0 + r)*768 + h*HD + d];
        Ks[d][r] = g_qkv[(size_t)(b*LL + m0 + r)*768 + 256 + h*HD + d];
    }
    __syncthreads();
    int tx = tid & 15, ty = tid >> 4;
    float acc[4][4] = {};
    #pragma unroll
    for (int d = 0; d < HD; d++) {
        float4 a4 = *(const float4*)&Qs[d][ty*4];
        float4 b4 = *(const float4*)&Ks[d][tx*4];
        float a[4] = {a4.x, a4.y, a4.z, a4.w};
        float bb[4] = {b4.x, b4.y, b4.z, b4.w};
        #pragma unroll
        for (int i = 0; i < 4; i++)
            #pragma unroll
            for (int j = 0; j < 4; j++)
                acc[i][j] += a[i]*bb[j];
    }
    const float sc = 0.17677669529663687f;   // 1/sqrt(32)
    #pragma unroll
    for (int i = 0; i < 4; i++) {
        int l = l0 + ty*4 + i;
        #pragma unroll
        for (int j = 0; j < 4; j++) {
            int m = m0 + tx*4 + j;
            size_t idx = (((size_t)b*HH + h)*LL + l)*LL + m;
            g_scores[idx] = acc[i][j]*sc + g_bias[idx];
        }
    }
}

// =====================================================================
// k_softmax: in-place over last dim (512) of g_scores
// =====================================================================
__global__ void k_softmax()
{
    size_t row = blockIdx.x;
    float* r = g_scores + row*LL;
    int t = threadIdx.x;
    float a = r[t], b = r[t + 256];
    __shared__ float sm[8];
    __shared__ float bc;
    float mx = fmaxf(a, b);
    #pragma unroll
    for (int o = 16; o > 0; o >>= 1) mx = fmaxf(mx, __shfl_xor_sync(0xffffffffu, mx, o));
    if ((t & 31) == 0) sm[t>>5] = mx;
    __syncthreads();
    if (t == 0) { float x = sm[0]; for (int i = 1; i < 8; i++) x = fmaxf(x, sm[i]); bc = x; }
    __syncthreads();
    mx = bc;
    float ea = expf(a - mx), eb = expf(b - mx);
    float s = ea + eb;
    #pragma unroll
    for (int o = 16; o > 0; o >>= 1) s += __shfl_xor_sync(0xffffffffu, s, o);
    __syncthreads();
    if ((t & 31) == 0) sm[t>>5] = s;
    __syncthreads();
    if (t == 0) { float x = 0; for (int i = 0; i < 8; i++) x += sm[i]; bc = x; }
    __syncthreads();
    float inv = 1.f/bc;
    r[t] = ea*inv;
    r[t + 256] = eb*inv;
}

// =====================================================================
// k_pv: o[b,l,h,:] = attn[b,h,l,:] @ v[b,:,h,:]     64x32 output tiles
// =====================================================================
__global__ void k_pv()
{
    __shared__ float Ps[64][65];                 // [m-chunk][l], padded
    __shared__ __align__(16) float Vs[64][32];   // [m-chunk][d]
    int bh = blockIdx.y;
    int b = bh >> 3, h = bh & 7;
    int l0 = blockIdx.x*64;
    int tid = threadIdx.x;
    int tx = tid & 7, ty = tid >> 3;             // tx: 8 col-groups, ty: 32 row-groups
    float acc[2][4] = {};
    for (int m0 = 0; m0 < LL; m0 += 64) {
        #pragma unroll
        for (int i = 0; i < 16; i++) {
            int lin = tid + i*256;               // 4096 attn elems
            int lr = lin >> 6, kk = lin & 63;
            Ps[kk][lr] = g_scores[(((size_t)b*HH + h)*LL + l0 + lr)*LL + m0 + kk];
        }
        #pragma unroll
        for (int i = 0; i < 8; i++) {
            int lin = tid + i*256;               // 2048 v elems
            int kk = lin >> 5, d = lin & 31;
            Vs[kk][d] = g_qkv[(size_t)(b*LL + m0 + kk)*768 + 512 + h*HD + d];
        }
        __syncthreads();
        #pragma unroll
        for (int kk = 0; kk < 64; kk++) {
            float4 b4 = *(const float4*)&Vs[kk][tx*4];
            float bb[4] = {b4.x, b4.y, b4.z, b4.w};
            #pragma unroll
            for (int i = 0; i < 2; i++) {
                float av = Ps[kk][ty*2 + i];
                #pragma unroll
                for (int j = 0; j < 4; j++) acc[i][j] += av*bb[j];
            }
        }
        __syncthreads();
    }
    #pragma unroll
    for (int i = 0; i < 2; i++) {
        int l = l0 + ty*2 + i;
        #pragma unroll
        for (int j = 0; j < 4; j++)
            g_o[(size_t)(b*LL + l)*EE + h*HD + tx*4 + j] = acc[i][j];
    }
}

// =====================================================================
// launch
// =====================================================================
extern "C" void kernel_launch(void* const* d_in, const int* in_sizes, int n_in,
                              void* d_out, int out_size)
{
    const float* h      = (const float*)d_in[0];
    const float* h_init = (const float*)d_in[1];
    const float* s_a    = (const float*)d_in[2];
    const float* s_t    = (const float*)d_in[3];
    const float* s_tem  = (const float*)d_in[4];
    const float* p      = (const float*)d_in[5];
    const float* W_bp   = (const float*)d_in[6];
    const float* b_bp   = (const float*)d_in[7];
    const float* W_ada  = (const float*)d_in[8];
    const float* b_ada  = (const float*)d_in[9];
    const float* g_eln  = (const float*)d_in[10];
    const float* b_eln  = (const float*)d_in[11];
    const float* W_e    = (const float*)d_in[12];
    const float* b_e    = (const float*)d_in[13];
    const float* W_in   = (const float*)d_in[14];
    const float* b_in   = (const float*)d_in[15];
    const float* W_out  = (const float*)d_in[16];
    const float* b_out  = (const float*)d_in[17];
    const float* W1     = (const float*)d_in[18];
    const float* b1     = (const float*)d_in[19];
    const float* W2     = (const float*)d_in[20];
    const float* b2     = (const float*)d_in[21];
    const float* W_tem  = (const float*)d_in[22];
    const float* b_tem  = (const float*)d_in[23];
    const float* g_tem  = (const float*)d_in[24];
    const float* bt_tem = (const float*)d_in[25];
    const float* W_init = (const float*)d_in[26];
    const float* b_init = (const float*)d_in[27];
    const float* g_init = (const float*)d_in[28];
    const float* bt_init= (const float*)d_in[29];
    float* out = (float*)d_out;

    float *pu, *pm, *px, *pqkv, *po, *ph1, *pt1, *ph2;
    cudaGetSymbolAddress((void**)&pu,   g_u);
    cudaGetSymbolAddress((void**)&pm,   g_m);
    cudaGetSymbolAddress((void**)&px,   g_x);
    cudaGetSymbolAddress((void**)&pqkv, g_qkv);
    cudaGetSymbolAddress((void**)&po,   g_o);
    cudaGetSymbolAddress((void**)&ph1,  g_h1);
    cudaGetSymbolAddress((void**)&pt1,  g_t1);
    cudaGetSymbolAddress((void**)&ph2,  g_h2);

    // 1) conditioning
    k_cond1<<<NROWS, 256>>>(s_a, s_t, W_bp, b_bp);
    k_gemm<EPI_BIAS><<<dim3(6*EE/64, NROWS/64), 256>>>(pu, W_ada, pm, NROWS, 6*EE, TD_,
                                                       b_ada, nullptr, 0, 0, nullptr);
    // 2) pair bias (memory-bound floor: 512MB read of p)
    k_bias<<<(BB*LL*LL)/8, 256>>>(p, g_eln, b_eln, W_e, b_e);

    // 3) attention branch
    k_xmod<<<NROWS, 256>>>(h, 0, EE, px);
    k_gemm<EPI_BIAS><<<dim3(3*EE/64, NROWS/64), 256>>>(px, W_in, pqkv, NROWS, 3*EE, EE,
                                                       b_in, nullptr, 0, 0, nullptr);
    k_scores<<<dim3(LL/64, LL/64, BB*HH), 256>>>();
    k_softmax<<<BB*HH*LL, 256>>>();
    k_pv<<<dim3(LL/64, BB*HH), 256>>>();
    k_gemm<EPI_GATE_RES><<<dim3(EE/64, NROWS/64), 256>>>(po, W_out, ph1, NROWS, EE, EE,
                                                         b_out, pm, 6*EE, 2*EE, h);
    // 4) MLP branch
    k_xmod<<<NROWS, 256>>>(ph1, 3*EE, 4*EE, px);
    k_gemm<EPI_SILU><<<dim3(MM_/64, NROWS/64), 256>>>(px, W1, pt1, NROWS, MM_, EE,
                                                      b1, nullptr, 0, 0, nullptr);
    k_gemm<EPI_GATE_RES><<<dim3(EE/64, NROWS/64), 256>>>(pt1, W2, ph2, NROWS, EE, MM_,
                                                         b2, pm, 6*EE, 5*EE, ph1);
    // 5) trailing conditioning LayerNorms
    k_gemm<EPI_ADD_RES><<<dim3(EE/64, NROWS/64), 256>>>(s_tem, W_tem, px, NROWS, EE, TE_,
                                                        b_tem, nullptr, 0, 0, ph2);
    k_ln_affine<<<NROWS, 256>>>(px, g_tem, bt_tem, ph1);
    k_gemm<EPI_ADD_RES><<<dim3(EE/64, NROWS/64), 256>>>(h_init, W_init, px, NROWS, EE, EE,
                                                        b_init, nullptr, 0, 0, ph1);
    k_ln_affine<<<NROWS, 256>>>(px, g_init, bt_init, out);
}

// round 3
// speedup vs baseline: 1.2214x; 1.2214x over previous
#include <cuda_runtime.h>
#include <math.h>

// ---- problem constants ----
#define BB 8
#define LL 512
#define EE 256
#define HH 8
#define HD 32
#define BD_ 64
#define TD_ 256
#define TE_ 128
#define ED_ 64
#define MM_ 512
#define NROWS (BB*LL)          // 4096 token rows

// ---- scratch (device globals; no runtime allocation) ----
__device__ float g_u[NROWS*TD_];                       // silu(s)         4 MB
__device__ float g_m[NROWS*6*EE];                      // modulations    25 MB
__device__ float g_x[NROWS*EE];                        // staging         4 MB
__device__ float g_bias[(size_t)BB*HH*LL*LL];          // attn bias      64 MB
__device__ float g_qkv[NROWS*3*EE];                    // qkv            12 MB
__device__ float g_o[NROWS*EE];                        // attn out        4 MB
__device__ float g_h1[NROWS*EE];                       // residual 1      4 MB
__device__ float g_t1[NROWS*MM_];                      // mlp hidden      8 MB
__device__ float g_h2[NROWS*EE];                       // residual 2      4 MB

// =====================================================================
// k_cond1: u = silu(s_a @ W_bp^T + b_bp + s_t)      [4096, 256]
// =====================================================================
__global__ void k_cond1(const float* __restrict__ s_a, const float* __restrict__ s_t,
                        const float* __restrict__ W_bp, const float* __restrict__ b_bp)
{
    int row = blockIdx.x;
    int t = threadIdx.x;                  // 256 threads = TD outputs
    __shared__ float sa[BD_];
    if (t < BD_) sa[t] = s_a[(size_t)row*BD_ + t];
    __syncthreads();
    float acc = b_bp[t];
    const float* w = W_bp + (size_t)t*BD_;
    #pragma unroll 16
    for (int k = 0; k < BD_; k++) acc += sa[k]*w[k];
    acc += s_t[(size_t)row*TD_ + t];
    g_u[(size_t)row*TD_ + t] = acc / (1.f + __expf(-acc));   // silu
}

// =====================================================================
// High-throughput SGEMM: C[M,N] = A[M,K] @ B[N,K]^T  (+ epilogues)
// BM=128, BN in {128,64}, BK=16, 256 threads, 8x(BN/16) per-thread tile,
// double-buffered smem. M%128==0, N%BN==0, K%16==0 assumed.
// =====================================================================
#define EPI_BIAS     0
#define EPI_SILU     1
#define EPI_GATE_RES 2
#define EPI_ADD_RES  3

template<int BN, int EPI>
__global__ void __launch_bounds__(256, 2) k_gemm128(
    const float* __restrict__ A, const float* __restrict__ B, float* __restrict__ C,
    int Nd, int Kd,
    const float* __restrict__ bias,
    const float* __restrict__ gate, int goff,
    const float* __restrict__ res)
{
    constexpr int TN = BN/16;            // 8 or 4
    __shared__ __align__(16) float As[2][16][128];
    __shared__ __align__(16) float Bs[2][16][BN];

    int bm = blockIdx.y*128, bn = blockIdx.x*BN;
    int tid = threadIdx.x;

    // global load mapping
    int ar = tid >> 1, ak = (tid & 1)*8;
    int br, bk;
    if (BN == 128) { br = tid >> 1; bk = (tid & 1)*8; }
    else           { br = tid >> 2; bk = (tid & 3)*4; }

    const float* Aptr = A + (size_t)(bm + ar)*Kd + ak;
    const float* Bptr = B + (size_t)(bn + br)*Kd + bk;

    float4 ra0, ra1, rb0, rb1;

    // microtile mapping
    int wid = tid >> 5, lane = tid & 31;
    int row0 = (wid & 1)*64 + (lane & 7)*8;
    int col0 = (wid >> 1)*(BN/4) + (lane >> 3)*TN;

    float acc[8][TN];
    #pragma unroll
    for (int i = 0; i < 8; i++)
        #pragma unroll
        for (int j = 0; j < TN; j++) acc[i][j] = 0.f;

    // prologue: load tile 0
    ra0 = *(const float4*)(Aptr);
    ra1 = *(const float4*)(Aptr + 4);
    rb0 = *(const float4*)(Bptr);
    if (BN == 128) rb1 = *(const float4*)(Bptr + 4);

    As[0][ak+0][ar]=ra0.x; As[0][ak+1][ar]=ra0.y; As[0][ak+2][ar]=ra0.z; As[0][ak+3][ar]=ra0.w;
    As[0][ak+4][ar]=ra1.x; As[0][ak+5][ar]=ra1.y; As[0][ak+6][ar]=ra1.z; As[0][ak+7][ar]=ra1.w;
    Bs[0][bk+0][br]=rb0.x; Bs[0][bk+1][br]=rb0.y; Bs[0][bk+2][br]=rb0.z; Bs[0][bk+3][br]=rb0.w;
    if (BN == 128) {
        Bs[0][bk+4][br]=rb1.x; Bs[0][bk+5][br]=rb1.y; Bs[0][bk+6][br]=rb1.z; Bs[0][bk+7][br]=rb1.w;
    }
    __syncthreads();

    int buf = 0;
    for (int k0 = 0; k0 < Kd; k0 += 16) {
        bool last = (k0 + 16 >= Kd);
        if (!last) {
            ra0 = *(const float4*)(Aptr + k0 + 16);
            ra1 = *(const float4*)(Aptr + k0 + 20);
            rb0 = *(const float4*)(Bptr + k0 + 16);
            if (BN == 128) rb1 = *(const float4*)(Bptr + k0 + 20);
        }
        #pragma unroll
        for (int kk = 0; kk < 16; kk++) {
            float af[8], bf[TN];
            *(float4*)&af[0] = *(const float4*)&As[buf][kk][row0];
            *(float4*)&af[4] = *(const float4*)&As[buf][kk][row0+4];
            *(float4*)&bf[0] = *(const float4*)&Bs[buf][kk][col0];
            if (TN == 8) *(float4*)&bf[4] = *(const float4*)&Bs[buf][kk][col0+4];
            #pragma unroll
            for (int i = 0; i < 8; i++)
                #pragma unroll
                for (int j = 0; j < TN; j++)
                    acc[i][j] += af[i]*bf[j];
        }
        if (!last) {
            int nb = buf ^ 1;
            As[nb][ak+0][ar]=ra0.x; As[nb][ak+1][ar]=ra0.y; As[nb][ak+2][ar]=ra0.z; As[nb][ak+3][ar]=ra0.w;
            As[nb][ak+4][ar]=ra1.x; As[nb][ak+5][ar]=ra1.y; As[nb][ak+6][ar]=ra1.z; As[nb][ak+7][ar]=ra1.w;
            Bs[nb][bk+0][br]=rb0.x; Bs[nb][bk+1][br]=rb0.y; Bs[nb][bk+2][br]=rb0.z; Bs[nb][bk+3][br]=rb0.w;
            if (BN == 128) {
                Bs[nb][bk+4][br]=rb1.x; Bs[nb][bk+5][br]=rb1.y; Bs[nb][bk+6][br]=rb1.z; Bs[nb][bk+7][br]=rb1.w;
            }
            __syncthreads();
            buf = nb;
        }
    }

    // epilogue
    #pragma unroll
    for (int i = 0; i < 8; i++) {
        int m = bm + row0 + i;
        #pragma unroll
        for (int j4 = 0; j4 < TN; j4 += 4) {
            float4 v;
            float vv[4];
            #pragma unroll
            for (int u = 0; u < 4; u++) {
                int n = bn + col0 + j4 + u;
                float x = acc[i][j4+u] + bias[n];
                if (EPI == EPI_SILU)     x = x / (1.f + __expf(-x));
                if (EPI == EPI_GATE_RES) x = x*gate[(size_t)m*(6*EE) + goff + n] + res[(size_t)m*Nd + n];
                if (EPI == EPI_ADD_RES)  x = x + res[(size_t)m*Nd + n];
                vv[u] = x;
            }
            v.x = vv[0]; v.y = vv[1]; v.z = vv[2]; v.w = vv[3];
            *(float4*)&C[(size_t)m*Nd + bn + col0 + j4] = v;
        }
    }
}

// =====================================================================
// k_xmod: dst = LN(src_row)*(1 + m[:,sc]) + m[:,sh]    (row = 256 wide)
// =====================================================================
__global__ void k_xmod(const float* __restrict__ src, int sh_off, int sc_off,
                       float* __restrict__ dst)
{
    int row = blockIdx.x, t = threadIdx.x;
    float v = src[(size_t)row*EE + t];
    __shared__ float s1[8], s2[8], bc[2];
    float a = v, b = v*v;
    #pragma unroll
    for (int o = 16; o > 0; o >>= 1) {
        a += __shfl_xor_sync(0xffffffffu, a, o);
        b += __shfl_xor_sync(0xffffffffu, b, o);
    }
    if ((t & 31) == 0) { s1[t>>5] = a; s2[t>>5] = b; }
    __syncthreads();
    if (t == 0) {
        float x = 0, y = 0;
        for (int i = 0; i < 8; i++) { x += s1[i]; y += s2[i]; }
        bc[0] = x*(1.f/EE); bc[1] = y*(1.f/EE);
    }
    __syncthreads();
    float mu = bc[0], var = bc[1] - mu*mu;
    float n = (v - mu)*rsqrtf(var + 1e-5f);
    const float* mrow = g_m + (size_t)row*(6*EE);
    dst[(size_t)row*EE + t] = n*(1.f + mrow[sc_off + t]) + mrow[sh_off + t];
}

// =====================================================================
// k_ln_affine: dst = LN(src_row)*g + bt
// =====================================================================
__global__ void k_ln_affine(const float* __restrict__ src, const float* __restrict__ g,
                            const float* __restrict__ bt, float* __restrict__ dst)
{
    int row = blockIdx.x, t = threadIdx.x;
    float v = src[(size_t)row*EE + t];
    __shared__ float s1[8], s2[8], bc[2];
    float a = v, b = v*v;
    #pragma unroll
    for (int o = 16; o > 0; o >>= 1) {
        a += __shfl_xor_sync(0xffffffffu, a, o);
        b += __shfl_xor_sync(0xffffffffu, b, o);
    }
    if ((t & 31) == 0) { s1[t>>5] = a; s2[t>>5] = b; }
    __syncthreads();
    if (t == 0) {
        float x = 0, y = 0;
        for (int i = 0; i < 8; i++) { x += s1[i]; y += s2[i]; }
        bc[0] = x*(1.f/EE); bc[1] = y*(1.f/EE);
    }
    __syncthreads();
    float mu = bc[0], var = bc[1] - mu*mu;
    float n = (v - mu)*rsqrtf(var + 1e-5f);
    dst[(size_t)row*EE + t] = n*g[t] + bt[t];
}

// =====================================================================
// k_bias: bias[b,h,l,m] = (LN(p[b,l,m,:])*g_eln + b_eln) @ W_e^T + b_e
// warp per (b,l,m) row of 64; smem-staged transposed write (coalesced)
// =====================================================================
__global__ void k_bias(const float* __restrict__ p, const float* __restrict__ g_eln,
                       const float* __restrict__ b_eln, const float* __restrict__ W_e,
                       const float* __restrict__ b_e)
{
    __shared__ float sWe[HH][ED_];
    __shared__ float sge[ED_], sbe[ED_], sbh[HH];
    __shared__ float sout[HH][8];
    int tid = threadIdx.x;
    for (int i = tid; i < HH*ED_; i += 256)
        sWe[i>>6][i & 63] = W_e[i];
    if (tid < ED_) { sge[tid] = g_eln[tid]; sbe[tid] = b_eln[tid]; }
    if (tid < HH) sbh[tid] = b_e[tid];
    __syncthreads();

    int warp = tid >> 5, lane = tid & 31;
    size_t row = (size_t)blockIdx.x*8 + warp;        // index over (b, l, m)
    const float* pr = p + row*ED_;
    float v0 = pr[lane], v1 = pr[lane + 32];
    float s = v0 + v1, q = v0*v0 + v1*v1;
    #pragma unroll
    for (int o = 16; o > 0; o >>= 1) {
        s += __shfl_xor_sync(0xffffffffu, s, o);
        q += __shfl_xor_sync(0xffffffffu, q, o);
    }
    float mu = s*(1.f/64.f);
    float var = q*(1.f/64.f) - mu*mu;
    float rstd = rsqrtf(var + 1e-5f);
    float n0 = (v0 - mu)*rstd*sge[lane] + sbe[lane];
    float n1 = (v1 - mu)*rstd*sge[lane + 32] + sbe[lane + 32];
    #pragma unroll
    for (int h = 0; h < HH; h++) {
        float ph = n0*sWe[h][lane] + n1*sWe[h][lane + 32];
        #pragma unroll
        for (int o = 16; o > 0; o >>= 1) ph += __shfl_xor_sync(0xffffffffu, ph, o);
        if (lane == 0) sout[h][warp] = ph + sbh[h];
    }
    __syncthreads();
    if (tid < HH*8) {
        size_t row0 = (size_t)blockIdx.x*8;
        int m0 = (int)(row0 & (LL - 1));
        int l  = (int)((row0 >> 9) & (LL - 1));
        int b  = (int)(row0 >> 18);
        int h = tid >> 3, w = tid & 7;
        g_bias[(((size_t)b*HH + h)*LL + l)*LL + m0 + w] = sout[h][w];
    }
}

// =====================================================================
// k_attn: fused flash attention per (b,h,l-tile of 64)
//   S = Q K^T / sqrt(32) + bias ; online softmax ; O = P V
// 256 threads. S mapping: 16x16 threads, 4x4 microtile.
// PV mapping: ty2=tid>>3 (2 rows), tx2=tid&7 (4 d-cols).
// =====================================================================
__global__ void __launch_bounds__(256) k_attn()
{
    __shared__ __align__(16) float Qs[HD][64];
    __shared__ __align__(16) float Ks[HD][64];
    __shared__ __align__(16) float Vs[64][HD];
    __shared__ __align__(16) float Ps[64][68];       // pad 68: 16B-aligned rows
    __shared__ float m_run[64], l_run[64], scl[64];

    int bh = blockIdx.y;
    int b = bh >> 3, h = bh & 7;
    int l0 = blockIdx.x*64;
    int tid = threadIdx.x;

    {   // load Q tile, transposed [d][l]
        int r = tid >> 2, c = (tid & 3)*8;
        const float* q = g_qkv + (size_t)(b*LL + l0 + r)*768 + h*HD + c;
        float4 v0 = *(const float4*)q, v1 = *(const float4*)(q+4);
        Qs[c+0][r]=v0.x; Qs[c+1][r]=v0.y; Qs[c+2][r]=v0.z; Qs[c+3][r]=v0.w;
        Qs[c+4][r]=v1.x; Qs[c+5][r]=v1.y; Qs[c+6][r]=v1.z; Qs[c+7][r]=v1.w;
    }
    if (tid < 64) { m_run[tid] = -1e30f; l_run[tid] = 0.f; }

    int tx = tid & 15, ty = tid >> 4;
    int tx2 = tid & 7, ty2 = tid >> 3;
    float oacc[2][4] = {};
    const float sc = 0.17677669529663687f;   // 1/sqrt(32)

    for (int m0 = 0; m0 < LL; m0 += 64) {
        __syncthreads();   // protects Qs(first iter)/Ks/Vs/stats vs prior phase
        {   // load K (transposed) + V tiles
            int r = tid >> 2, c = (tid & 3)*8;
            const float* kp = g_qkv + (size_t)(b*LL + m0 + r)*768 + 256 + h*HD + c;
            float4 v0 = *(const float4*)kp, v1 = *(const float4*)(kp+4);
            Ks[c+0][r]=v0.x; Ks[c+1][r]=v0.y; Ks[c+2][r]=v0.z; Ks[c+3][r]=v0.w;
            Ks[c+4][r]=v1.x; Ks[c+5][r]=v1.y; Ks[c+6][r]=v1.z; Ks[c+7][r]=v1.w;
            const float* vp = g_qkv + (size_t)(b*LL + m0 + r)*768 + 512 + h*HD + c;
            *(float4*)&Vs[r][c]   = *(const float4*)vp;
            *(float4*)&Vs[r][c+4] = *(const float4*)(vp+4);
        }
        __syncthreads();

        // --- S tile: QK + bias ---
        float s[4][4];
        {
            float qk[4][4] = {};
            #pragma unroll
            for (int d = 0; d < HD; d++) {
                float4 qa = *(const float4*)&Qs[d][ty*4];
                float4 kb = *(const float4*)&Ks[d][tx*4];
                float qv[4] = {qa.x, qa.y, qa.z, qa.w};
                float kv[4] = {kb.x, kb.y, kb.z, kb.w};
                #pragma unroll
                for (int i = 0; i < 4; i++)
                    #pragma unroll
                    for (int j = 0; j < 4; j++)
                        qk[i][j] += qv[i]*kv[j];
            }
            const float* bptr = g_bias + ((size_t)((b*HH + h)*LL + l0 + ty*4))*LL + m0 + tx*4;
            #pragma unroll
            for (int i = 0; i < 4; i++) {
                float4 bb = *(const float4*)(bptr + (size_t)i*LL);
                s[i][0] = qk[i][0]*sc + bb.x;
                s[i][1] = qk[i][1]*sc + bb.y;
                s[i][2] = qk[i][2]*sc + bb.z;
                s[i][3] = qk[i][3]*sc + bb.w;
            }
        }

        // --- online softmax (per row, reduced over 16-lane tx group) ---
        #pragma unroll
        for (int i = 0; i < 4; i++) {
            int row = ty*4 + i;
            float rm = fmaxf(fmaxf(s[i][0], s[i][1]), fmaxf(s[i][2], s[i][3]));
            #pragma unroll
            for (int o = 8; o > 0; o >>= 1)
                rm = fmaxf(rm, __shfl_xor_sync(0xffffffffu, rm, o));
            float mold = m_run[row];
            float mnew = fmaxf(mold, rm);
            float p0 = __expf(s[i][0] - mnew);
            float p1 = __expf(s[i][1] - mnew);
            float p2 = __expf(s[i][2] - mnew);
            float p3 = __expf(s[i][3] - mnew);
            float rs = p0 + p1 + p2 + p3;
            #pragma unroll
            for (int o = 8; o > 0; o >>= 1)
                rs += __shfl_xor_sync(0xffffffffu, rs, o);
            if (tx == 0) {
                float f = __expf(mold - mnew);
                m_run[row] = mnew;
                l_run[row] = l_run[row]*f + rs;
                scl[row] = f;
            }
            float4 pv4; pv4.x = p0; pv4.y = p1; pv4.z = p2; pv4.w = p3;
            *(float4*)&Ps[row][tx*4] = pv4;
        }
        __syncthreads();

        // --- PV accumulate with running rescale ---
        {
            int r0 = ty2*2;
            float f0 = scl[r0], f1 = scl[r0+1];
            #pragma unroll
            for (int j = 0; j < 4; j++) { oacc[0][j] *= f0; oacc[1][j] *= f1; }
            #pragma unroll
            for (int kk = 0; kk < 64; kk++) {
                float4 vv = *(const float4*)&Vs[kk][tx2*4];
                float pa = Ps[r0][kk], pb = Ps[r0+1][kk];
                oacc[0][0] += pa*vv.x; oacc[0][1] += pa*vv.y;
                oacc[0][2] += pa*vv.z; oacc[0][3] += pa*vv.w;
                oacc[1][0] += pb*vv.x; oacc[1][1] += pb*vv.y;
                oacc[1][2] += pb*vv.z; oacc[1][3] += pb*vv.w;
            }
        }
    }

    // finalize
    int r0 = ty2*2;
    float inv0 = 1.f/l_run[r0], inv1 = 1.f/l_run[r0+1];
    float4 o0, o1;
    o0.x = oacc[0][0]*inv0; o0.y = oacc[0][1]*inv0; o0.z = oacc[0][2]*inv0; o0.w = oacc[0][3]*inv0;
    o1.x = oacc[1][0]*inv1; o1.y = oacc[1][1]*inv1; o1.z = oacc[1][2]*inv1; o1.w = oacc[1][3]*inv1;
    *(float4*)&g_o[(size_t)(b*LL + l0 + r0    )*EE + h*HD + tx2*4] = o0;
    *(float4*)&g_o[(size_t)(b*LL + l0 + r0 + 1)*EE + h*HD + tx2*4] = o1;
}

// =====================================================================
// launch
// =====================================================================
extern "C" void kernel_launch(void* const* d_in, const int* in_sizes, int n_in,
                              void* d_out, int out_size)
{
    const float* h      = (const float*)d_in[0];
    const float* h_init = (const float*)d_in[1];
    const float* s_a    = (const float*)d_in[2];
    const float* s_t    = (const float*)d_in[3];
    const float* s_tem  = (const float*)d_in[4];
    const float* p      = (const float*)d_in[5];
    const float* W_bp   = (const float*)d_in[6];
    const float* b_bp   = (const float*)d_in[7];
    const float* W_ada  = (const float*)d_in[8];
    const float* b_ada  = (const float*)d_in[9];
    const float* g_eln  = (const float*)d_in[10];
    const float* b_eln  = (const float*)d_in[11];
    const float* W_e    = (const float*)d_in[12];
    const float* b_e    = (const float*)d_in[13];
    const float* W_in   = (const float*)d_in[14];
    const float* b_in   = (const float*)d_in[15];
    const float* W_out  = (const float*)d_in[16];
    const float* b_out  = (const float*)d_in[17];
    const float* W1     = (const float*)d_in[18];
    const float* b1     = (const float*)d_in[19];
    const float* W2     = (const float*)d_in[20];
    const float* b2     = (const float*)d_in[21];
    const float* W_tem  = (const float*)d_in[22];
    const float* b_tem  = (const float*)d_in[23];
    const float* g_tem  = (const float*)d_in[24];
    const float* bt_tem = (const float*)d_in[25];
    const float* W_init = (const float*)d_in[26];
    const float* b_init = (const float*)d_in[27];
    const float* g_init = (const float*)d_in[28];
    const float* bt_init= (const float*)d_in[29];
    float* out = (float*)d_out;

    float *pu, *pm, *px, *pqkv, *po, *ph1, *pt1, *ph2;
    cudaGetSymbolAddress((void**)&pu,   g_u);
    cudaGetSymbolAddress((void**)&pm,   g_m);
    cudaGetSymbolAddress((void**)&px,   g_x);
    cudaGetSymbolAddress((void**)&pqkv, g_qkv);
    cudaGetSymbolAddress((void**)&po,   g_o);
    cudaGetSymbolAddress((void**)&ph1,  g_h1);
    cudaGetSymbolAddress((void**)&pt1,  g_t1);
    cudaGetSymbolAddress((void**)&ph2,  g_h2);

    // 1) conditioning
    k_cond1<<<NROWS, 256>>>(s_a, s_t, W_bp, b_bp);
    k_gemm128<128, EPI_BIAS><<<dim3(6*EE/128, NROWS/128), 256>>>(
        pu, W_ada, pm, 6*EE, TD_, b_ada, nullptr, 0, nullptr);

    // 2) pair bias (memory-bound floor: 512MB read of p)
    k_bias<<<(BB*LL*LL)/8, 256>>>(p, g_eln, b_eln, W_e, b_e);

    // 3) attention branch
    k_xmod<<<NROWS, 256>>>(h, 0, EE, px);
    k_gemm128<128, EPI_BIAS><<<dim3(3*EE/128, NROWS/128), 256>>>(
        px, W_in, pqkv, 3*EE, EE, b_in, nullptr, 0, nullptr);
    k_attn<<<dim3(LL/64, BB*HH), 256>>>();
    k_gemm128<64, EPI_GATE_RES><<<dim3(EE/64, NROWS/128), 256>>>(
        po, W_out, ph1, EE, EE, b_out, pm, 2*EE, h);

    // 4) MLP branch
    k_xmod<<<NROWS, 256>>>(ph1, 3*EE, 4*EE, px);
    k_gemm128<128, EPI_SILU><<<dim3(MM_/128, NROWS/128), 256>>>(
        px, W1, pt1, MM_, EE, b1, nullptr, 0, nullptr);
    k_gemm128<64, EPI_GATE_RES><<<dim3(EE/64, NROWS/128), 256>>>(
        pt1, W2, ph2, EE, MM_, b2, pm, 5*EE, ph1);

    // 5) trailing conditioning LayerNorms
    k_gemm128<64, EPI_ADD_RES><<<dim3(EE/64, NROWS/128), 256>>>(
        s_tem, W_tem, px, EE, TE_, b_tem, nullptr, 0, ph2);
    k_ln_affine<<<NROWS, 256>>>(px, g_tem, bt_tem, ph1);
    k_gemm128<64, EPI_ADD_RES><<<dim3(EE/64, NROWS/128), 256>>>(
        h_init, W_init, px, EE, EE, b_init, nullptr, 0, ph1);
    k_ln_affine<<<NROWS, 256>>>(px, g_init, bt_init, out);
}

// round 5
// speedup vs baseline: 2.2251x; 1.8218x over previous
#include <cuda_runtime.h>
#include <math.h>

// ---- problem constants ----
#define BB 8
#define LL 512
#define EE 256
#define HH 8
#define HD 32
#define BD_ 64
#define TD_ 256
#define TE_ 128
#define ED_ 64
#define MM_ 512
#define NROWS (BB*LL)          // 4096 token rows

// ---- scratch (device globals; no runtime allocation) ----
__device__ float g_u[NROWS*TD_];                       // silu(s)         4 MB
__device__ float g_m[NROWS*6*EE];                      // modulations    25 MB
__device__ float g_x[NROWS*EE];                        // staging         4 MB
__device__ float g_bias[(size_t)BB*HH*LL*LL];          // attn bias      64 MB
__device__ float g_qkv[NROWS*3*EE];                    // qkv            12 MB
__device__ float g_o[NROWS*EE];                        // attn out        4 MB
__device__ float g_h1[NROWS*EE];                       // residual 1      4 MB
__device__ float g_t1[NROWS*MM_];                      // mlp hidden      8 MB
__device__ float g_h2[NROWS*EE];                       // residual 2      4 MB

// =====================================================================
// High-throughput SGEMM: C[M,N] = A[M,K] @ B[N,K]^T  (+ epilogues)
// BM=128, BN in {128,64}, BK=16, 256 threads, 8x(BN/16) per-thread tile,
// double-buffered smem. M%128==0, N%BN==0, K%16==0 assumed.
// =====================================================================
#define EPI_BIAS     0
#define EPI_SILU     1
#define EPI_GATE_RES 2
#define EPI_ADD_RES  3
#define EPI_ADD_SILU 4

template<int BN, int EPI>
__global__ void __launch_bounds__(256) k_gemm128(
    const float* __restrict__ A, const float* __restrict__ B, float* __restrict__ C,
    int Nd, int Kd,
    const float* __restrict__ bias,
    const float* __restrict__ gate, int goff,
    const float* __restrict__ res)
{
    constexpr int TN = BN/16;            // 8 or 4
    __shared__ __align__(16) float As[2][16][128];
    __shared__ __align__(16) float Bs[2][16][BN];

    int bm = blockIdx.y*128, bn = blockIdx.x*BN;
    int tid = threadIdx.x;

    // global load mapping
    int ar = tid >> 1, ak = (tid & 1)*8;
    int br, bk;
    if (BN == 128) { br = tid >> 1; bk = (tid & 1)*8; }
    else           { br = tid >> 2; bk = (tid & 3)*4; }

    const float* Aptr = A + (size_t)(bm + ar)*Kd + ak;
    const float* Bptr = B + (size_t)(bn + br)*Kd + bk;

    float4 ra0, ra1, rb0, rb1;

    // microtile mapping
    int wid = tid >> 5, lane = tid & 31;
    int row0 = (wid & 1)*64 + (lane & 7)*8;
    int col0 = (wid >> 1)*(BN/4) + (lane >> 3)*TN;

    float acc[8][TN];
    #pragma unroll
    for (int i = 0; i < 8; i++)
        #pragma unroll
        for (int j = 0; j < TN; j++) acc[i][j] = 0.f;

    // prologue: load tile 0
    ra0 = *(const float4*)(Aptr);
    ra1 = *(const float4*)(Aptr + 4);
    rb0 = *(const float4*)(Bptr);
    if (BN == 128) rb1 = *(const float4*)(Bptr + 4);

    As[0][ak+0][ar]=ra0.x; As[0][ak+1][ar]=ra0.y; As[0][ak+2][ar]=ra0.z; As[0][ak+3][ar]=ra0.w;
    As[0][ak+4][ar]=ra1.x; As[0][ak+5][ar]=ra1.y; As[0][ak+6][ar]=ra1.z; As[0][ak+7][ar]=ra1.w;
    Bs[0][bk+0][br]=rb0.x; Bs[0][bk+1][br]=rb0.y; Bs[0][bk+2][br]=rb0.z; Bs[0][bk+3][br]=rb0.w;
    if (BN == 128) {
        Bs[0][bk+4][br]=rb1.x; Bs[0][bk+5][br]=rb1.y; Bs[0][bk+6][br]=rb1.z; Bs[0][bk+7][br]=rb1.w;
    }
    __syncthreads();

    int buf = 0;
    for (int k0 = 0; k0 < Kd; k0 += 16) {
        bool last = (k0 + 16 >= Kd);
        if (!last) {
            ra0 = *(const float4*)(Aptr + k0 + 16);
            ra1 = *(const float4*)(Aptr + k0 + 20);
            rb0 = *(const float4*)(Bptr + k0 + 16);
            if (BN == 128) rb1 = *(const float4*)(Bptr + k0 + 20);
        }
        #pragma unroll
        for (int kk = 0; kk < 16; kk++) {
            float af[8], bf[TN];
            *(float4*)&af[0] = *(const float4*)&As[buf][kk][row0];
            *(float4*)&af[4] = *(const float4*)&As[buf][kk][row0+4];
            *(float4*)&bf[0] = *(const float4*)&Bs[buf][kk][col0];
            if (TN == 8) *(float4*)&bf[4] = *(const float4*)&Bs[buf][kk][col0+4];
            #pragma unroll
            for (int i = 0; i < 8; i++)
                #pragma unroll
                for (int j = 0; j < TN; j++)
                    acc[i][j] += af[i]*bf[j];
        }
        if (!last) {
            int nb = buf ^ 1;
            As[nb][ak+0][ar]=ra0.x; As[nb][ak+1][ar]=ra0.y; As[nb][ak+2][ar]=ra0.z; As[nb][ak+3][ar]=ra0.w;
            As[nb][ak+4][ar]=ra1.x; As[nb][ak+5][ar]=ra1.y; As[nb][ak+6][ar]=ra1.z; As[nb][ak+7][ar]=ra1.w;
            Bs[nb][bk+0][br]=rb0.x; Bs[nb][bk+1][br]=rb0.y; Bs[nb][bk+2][br]=rb0.z; Bs[nb][bk+3][br]=rb0.w;
            if (BN == 128) {
                Bs[nb][bk+4][br]=rb1.x; Bs[nb][bk+5][br]=rb1.y; Bs[nb][bk+6][br]=rb1.z; Bs[nb][bk+7][br]=rb1.w;
            }
            __syncthreads();
            buf = nb;
        }
    }

    // epilogue
    #pragma unroll
    for (int i = 0; i < 8; i++) {
        int m = bm + row0 + i;
        #pragma unroll
        for (int j4 = 0; j4 < TN; j4 += 4) {
            float4 v;
            float vv[4];
            #pragma unroll
            for (int u = 0; u < 4; u++) {
                int n = bn + col0 + j4 + u;
                float x = acc[i][j4+u] + bias[n];
                if (EPI == EPI_SILU)     x = x / (1.f + __expf(-x));
                if (EPI == EPI_GATE_RES) x = x*gate[(size_t)m*(6*EE) + goff + n] + res[(size_t)m*Nd + n];
                if (EPI == EPI_ADD_RES)  x = x + res[(size_t)m*Nd + n];
                if (EPI == EPI_ADD_SILU) { x = x + res[(size_t)m*Nd + n]; x = x / (1.f + __expf(-x)); }
                vv[u] = x;
            }
            v.x = vv[0]; v.y = vv[1]; v.z = vv[2]; v.w = vv[3];
            *(float4*)&C[(size_t)m*Nd + bn + col0 + j4] = v;
        }
    }
}

// =====================================================================
// k_xmod: dst = LN(src_row)*(1 + m[:,sc]) + m[:,sh]    (row = 256 wide)
// =====================================================================
__global__ void k_xmod(const float* __restrict__ src, int sh_off, int sc_off,
                       float* __restrict__ dst)
{
    int row = blockIdx.x, t = threadIdx.x;
    float v = src[(size_t)row*EE + t];
    __shared__ float s1[8], s2[8], bc[2];
    float a = v, b = v*v;
    #pragma unroll
    for (int o = 16; o > 0; o >>= 1) {
        a += __shfl_xor_sync(0xffffffffu, a, o);
        b += __shfl_xor_sync(0xffffffffu, b, o);
    }
    if ((t & 31) == 0) { s1[t>>5] = a; s2[t>>5] = b; }
    __syncthreads();
    if (t == 0) {
        float x = 0, y = 0;
        for (int i = 0; i < 8; i++) { x += s1[i]; y += s2[i]; }
        bc[0] = x*(1.f/EE); bc[1] = y*(1.f/EE);
    }
    __syncthreads();
    float mu = bc[0], var = bc[1] - mu*mu;
    float n = (v - mu)*rsqrtf(var + 1e-5f);
    const float* mrow = g_m + (size_t)row*(6*EE);
    dst[(size_t)row*EE + t] = n*(1.f + mrow[sc_off + t]) + mrow[sh_off + t];
}

// =====================================================================
// k_ln_affine: dst = LN(src_row)*g + bt
// =====================================================================
__global__ void k_ln_affine(const float* __restrict__ src, const float* __restrict__ g,
                            const float* __restrict__ bt, float* __restrict__ dst)
{
    int row = blockIdx.x, t = threadIdx.x;
    float v = src[(size_t)row*EE + t];
    __shared__ float s1[8], s2[8], bc[2];
    float a = v, b = v*v;
    #pragma unroll
    for (int o = 16; o > 0; o >>= 1) {
        a += __shfl_xor_sync(0xffffffffu, a, o);
        b += __shfl_xor_sync(0xffffffffu, b, o);
    }
    if ((t & 31) == 0) { s1[t>>5] = a; s2[t>>5] = b; }
    __syncthreads();
    if (t == 0) {
        float x = 0, y = 0;
        for (int i = 0; i < 8; i++) { x += s1[i]; y += s2[i]; }
        bc[0] = x*(1.f/EE); bc[1] = y*(1.f/EE);
    }
    __syncthreads();
    float mu = bc[0], var = bc[1] - mu*mu;
    float n = (v - mu)*rsqrtf(var + 1e-5f);
    dst[(size_t)row*EE + t] = n*g[t] + bt[t];
}

// =====================================================================
// k_bias2: bias[b,h,l,m] = (LN(p[b,l,m,:])*g_eln + b_eln) @ W_e^T + b_e
// Block = 256 m-rows of one (b,l) staged in dynamic smem (coalesced),
// thread = 1 row. LN folded into GEMV.
// =====================================================================
#define BIAS_SMEM (256*68*4 + 512*4 + 16*4)
__global__ void __launch_bounds__(256) k_bias2(
        const float* __restrict__ p, const float* __restrict__ g_eln,
        const float* __restrict__ b_eln, const float* __restrict__ W_e,
        const float* __restrict__ b_e)
{
    extern __shared__ float sm[];
    float* srow = sm;                    // [256][68]
    float* sW   = sm + 256*68;           // [8][64]  (W' = g*W)
    float* scs  = sW + 512;              // [8] column sums of W'
    float* sct  = scs + 8;               // [8] constants
    int tid = threadIdx.x;

    for (int i = tid; i < 512; i += 256) sW[i] = g_eln[i & 63]*W_e[i];
    if (tid < 8) {
        float ct = 0.f;
        for (int k = 0; k < 64; k++) ct += b_eln[k]*W_e[tid*64 + k];
        sct[tid] = ct + b_e[tid];
    }
    __syncthreads();
    if (tid < 8) {
        float cs = 0.f;
        for (int k = 0; k < 64; k++) cs += sW[tid*64 + k];
        scs[tid] = cs;
    }

    // stage 256 rows of p (coalesced float4)
    int blk = blockIdx.x;
    const float4* src = (const float4*)(p + (size_t)blk*256*64);
    for (int i = tid; i < 256*16; i += 256) {
        int r = i >> 4, c4 = i & 15;
        *(float4*)&srow[r*68 + c4*4] = src[i];
    }
    __syncthreads();

    // one row per thread
    float P[8] = {};
    float s = 0.f, q = 0.f;
    const float* rp = srow + tid*68;
    #pragma unroll
    for (int c = 0; c < 16; c++) {
        float4 a = *(const float4*)&rp[c*4];
        s += a.x + a.y + a.z + a.w;
        q += a.x*a.x + a.y*a.y + a.z*a.z + a.w*a.w;
        #pragma unroll
        for (int hh = 0; hh < 8; hh++) {
            float4 w = *(const float4*)&sW[hh*64 + c*4];
            P[hh] += a.x*w.x + a.y*w.y + a.z*w.z + a.w*w.w;
        }
    }
    float mu = s*(1.f/64.f);
    float var = q*(1.f/64.f) - mu*mu;
    float rstd = rsqrtf(var + 1e-5f);

    int b = blk >> 10, l = (blk >> 1) & 511, m = (blk & 1)*256 + tid;
    #pragma unroll
    for (int hh = 0; hh < 8; hh++) {
        float o = rstd*(P[hh] - mu*scs[hh]) + sct[hh];
        g_bias[(((size_t)b*HH + hh)*LL + l)*LL + m] = o;
    }
}

// =====================================================================
// k_attn: fused flash attention per (b,h,l-tile of 64)
//   S = Q K^T / sqrt(32) + bias ; online softmax ; O = P V
// =====================================================================
__global__ void __launch_bounds__(256) k_attn()
{
    __shared__ __align__(16) float Qs[HD][64];
    __shared__ __align__(16) float Ks[HD][64];
    __shared__ __align__(16) float Vs[64][HD];
    __shared__ __align__(16) float Ps[64][68];       // pad 68: 16B-aligned rows
    __shared__ float m_run[64], l_run[64], scl[64];

    int bh = blockIdx.y;
    int b = bh >> 3, h = bh & 7;
    int l0 = blockIdx.x*64;
    int tid = threadIdx.x;

    {   // load Q tile, transposed [d][l]
        int r = tid >> 2, c = (tid & 3)*8;
        const float* q = g_qkv + (size_t)(b*LL + l0 + r)*768 + h*HD + c;
        float4 v0 = *(const float4*)q, v1 = *(const float4*)(q+4);
        Qs[c+0][r]=v0.x; Qs[c+1][r]=v0.y; Qs[c+2][r]=v0.z; Qs[c+3][r]=v0.w;
        Qs[c+4][r]=v1.x; Qs[c+5][r]=v1.y; Qs[c+6][r]=v1.z; Qs[c+7][r]=v1.w;
    }
    if (tid < 64) { m_run[tid] = -1e30f; l_run[tid] = 0.f; }

    int tx = tid & 15, ty = tid >> 4;
    int tx2 = tid & 7, ty2 = tid >> 3;
    float oacc[2][4] = {};
    const float sc = 0.17677669529663687f;   // 1/sqrt(32)

    for (int m0 = 0; m0 < LL; m0 += 64) {
        __syncthreads();
        {   // load K (transposed) + V tiles
            int r = tid >> 2, c = (tid & 3)*8;
            const float* kp = g_qkv + (size_t)(b*LL + m0 + r)*768 + 256 + h*HD + c;
            float4 v0 = *(const float4*)kp, v1 = *(const float4*)(kp+4);
            Ks[c+0][r]=v0.x; Ks[c+1][r]=v0.y; Ks[c+2][r]=v0.z; Ks[c+3][r]=v0.w;
            Ks[c+4][r]=v1.x; Ks[c+5][r]=v1.y; Ks[c+6][r]=v1.z; Ks[c+7][r]=v1.w;
            const float* vp = g_qkv + (size_t)(b*LL + m0 + r)*768 + 512 + h*HD + c;
            *(float4*)&Vs[r][c]   = *(const float4*)vp;
            *(float4*)&Vs[r][c+4] = *(const float4*)(vp+4);
        }
        __syncthreads();

        // --- S tile: QK + bias ---
        float s[4][4];
        {
            float qk[4][4] = {};
            #pragma unroll
            for (int d = 0; d < HD; d++) {
                float4 qa = *(const float4*)&Qs[d][ty*4];
                float4 kb = *(const float4*)&Ks[d][tx*4];
                float qv[4] = {qa.x, qa.y, qa.z, qa.w};
                float kv[4] = {kb.x, kb.y, kb.z, kb.w};
                #pragma unroll
                for (int i = 0; i < 4; i++)
                    #pragma unroll
                    for (int j = 0; j < 4; j++)
                        qk[i][j] += qv[i]*kv[j];
            }
            const float* bptr = g_bias + ((size_t)((b*HH + h)*LL + l0 + ty*4))*LL + m0 + tx*4;
            #pragma unroll
            for (int i = 0; i < 4; i++) {
                float4 bb = *(const float4*)(bptr + (size_t)i*LL);
                s[i][0] = qk[i][0]*sc + bb.x;
                s[i][1] = qk[i][1]*sc + bb.y;
                s[i][2] = qk[i][2]*sc + bb.z;
                s[i][3] = qk[i][3]*sc + bb.w;
            }
        }

        // --- online softmax (per row, reduced over 16-lane tx group) ---
        #pragma unroll
        for (int i = 0; i < 4; i++) {
            int row = ty*4 + i;
            float rm = fmaxf(fmaxf(s[i][0], s[i][1]), fmaxf(s[i][2], s[i][3]));
            #pragma unroll
            for (int o = 8; o > 0; o >>= 1)
                rm = fmaxf(rm, __shfl_xor_sync(0xffffffffu, rm, o));
            float mold = m_run[row];
            float mnew = fmaxf(mold, rm);
            float p0 = __expf(s[i][0] - mnew);
            float p1 = __expf(s[i][1] - mnew);
            float p2 = __expf(s[i][2] - mnew);
            float p3 = __expf(s[i][3] - mnew);
            float rs = p0 + p1 + p2 + p3;
            #pragma unroll
            for (int o = 8; o > 0; o >>= 1)
                rs += __shfl_xor_sync(0xffffffffu, rs, o);
            if (tx == 0) {
                float f = __expf(mold - mnew);
                m_run[row] = mnew;
                l_run[row] = l_run[row]*f + rs;
                scl[row] = f;
            }
            float4 pv4; pv4.x = p0; pv4.y = p1; pv4.z = p2; pv4.w = p3;
            *(float4*)&Ps[row][tx*4] = pv4;
        }
        __syncthreads();

        // --- PV accumulate with running rescale (float4 Ps loads) ---
        {
            int r0 = ty2*2;
            float f0 = scl[r0], f1 = scl[r0+1];
            #pragma unroll
            for (int j = 0; j < 4; j++) { oacc[0][j] *= f0; oacc[1][j] *= f1; }
            #pragma unroll
            for (int kk = 0; kk < 64; kk += 4) {
                float4 pa4 = *(const float4*)&Ps[r0][kk];
                float4 pb4 = *(const float4*)&Ps[r0+1][kk];
                float pa[4] = {pa4.x, pa4.y, pa4.z, pa4.w};
                float pb[4] = {pb4.x, pb4.y, pb4.z, pb4.w};
                #pragma unroll
                for (int u = 0; u < 4; u++) {
                    float4 vv = *(const float4*)&Vs[kk+u][tx2*4];
                    oacc[0][0] += pa[u]*vv.x; oacc[0][1] += pa[u]*vv.y;
                    oacc[0][2] += pa[u]*vv.z; oacc[0][3] += pa[u]*vv.w;
                    oacc[1][0] += pb[u]*vv.x; oacc[1][1] += pb[u]*vv.y;
                    oacc[1][2] += pb[u]*vv.z; oacc[1][3] += pb[u]*vv.w;
                }
            }
        }
    }

    // finalize
    int r0 = ty2*2;
    float inv0 = 1.f/l_run[r0], inv1 = 1.f/l_run[r0+1];
    float4 o0, o1;
    o0.x = oacc[0][0]*inv0; o0.y = oacc[0][1]*inv0; o0.z = oacc[0][2]*inv0; o0.w = oacc[0][3]*inv0;
    o1.x = oacc[1][0]*inv1; o1.y = oacc[1][1]*inv1; o1.z = oacc[1][2]*inv1; o1.w = oacc[1][3]*inv1;
    *(float4*)&g_o[(size_t)(b*LL + l0 + r0    )*EE + h*HD + tx2*4] = o0;
    *(float4*)&g_o[(size_t)(b*LL + l0 + r0 + 1)*EE + h*HD + tx2*4] = o1;
}

// =====================================================================
// launch
// =====================================================================
extern "C" void kernel_launch(void* const* d_in, const int* in_sizes, int n_in,
                              void* d_out, int out_size)
{
    const float* h      = (const float*)d_in[0];
    const float* h_init = (const float*)d_in[1];
    const float* s_a    = (const float*)d_in[2];
    const float* s_t    = (const float*)d_in[3];
    const float* s_tem  = (const float*)d_in[4];
    const float* p      = (const float*)d_in[5];
    const float* W_bp   = (const float*)d_in[6];
    const float* b_bp   = (const float*)d_in[7];
    const float* W_ada  = (const float*)d_in[8];
    const float* b_ada  = (const float*)d_in[9];
    const float* g_eln  = (const float*)d_in[10];
    const float* b_eln  = (const float*)d_in[11];
    const float* W_e    = (const float*)d_in[12];
    const float* b_e    = (const float*)d_in[13];
    const float* W_in   = (const float*)d_in[14];
    const float* b_in   = (const float*)d_in[15];
    const float* W_out  = (const float*)d_in[16];
    const float* b_out  = (const float*)d_in[17];
    const float* W1     = (const float*)d_in[18];
    const float* b1     = (const float*)d_in[19];
    const float* W2     = (const float*)d_in[20];
    const float* b2     = (const float*)d_in[21];
    const float* W_tem  = (const float*)d_in[22];
    const float* b_tem  = (const float*)d_in[23];
    const float* g_tem  = (const float*)d_in[24];
    const float* bt_tem = (const float*)d_in[25];
    const float* W_init = (const float*)d_in[26];
    const float* b_init = (const float*)d_in[27];
    const float* g_init = (const float*)d_in[28];
    const float* bt_init= (const float*)d_in[29];
    float* out = (float*)d_out;

    float *pu, *pm, *px, *pqkv, *po, *ph1, *pt1, *ph2;
    cudaGetSymbolAddress((void**)&pu,   g_u);
    cudaGetSymbolAddress((void**)&pm,   g_m);
    cudaGetSymbolAddress((void**)&px,   g_x);
    cudaGetSymbolAddress((void**)&pqkv, g_qkv);   // FIX: was host-shadow `(float*)g_qkv`
    cudaGetSymbolAddress((void**)&po,   g_o);
    cudaGetSymbolAddress((void**)&ph1,  g_h1);
    cudaGetSymbolAddress((void**)&pt1,  g_t1);
    cudaGetSymbolAddress((void**)&ph2,  g_h2);

    cudaFuncSetAttribute(k_bias2, cudaFuncAttributeMaxDynamicSharedMemorySize, BIAS_SMEM);

    // 1) conditioning: u = silu(s_a @ W_bp^T + b_bp + s_t)
    k_gemm128<128, EPI_ADD_SILU><<<dim3(TD_/128, NROWS/128), 256>>>(
        s_a, W_bp, pu, TD_, BD_, b_bp, nullptr, 0, s_t);
    k_gemm128<128, EPI_BIAS><<<dim3(6*EE/128, NROWS/128), 256>>>(
        pu, W_ada, pm, 6*EE, TD_, b_ada, nullptr, 0, nullptr);

    // 2) pair bias (memory-bound floor: 512MB read of p)
    k_bias2<<<(BB*LL*LL)/256, 256, BIAS_SMEM>>>(p, g_eln, b_eln, W_e, b_e);

    // 3) attention branch
    k_xmod<<<NROWS, 256>>>(h, 0, EE, px);
    k_gemm128<128, EPI_BIAS><<<dim3(3*EE/128, NROWS/128), 256>>>(
        px, W_in, pqkv, 3*EE, EE, b_in, nullptr, 0, nullptr);
    k_attn<<<dim3(LL/64, BB*HH), 256>>>();
    k_gemm128<64, EPI_GATE_RES><<<dim3(EE/64, NROWS/128), 256>>>(
        po, W_out, ph1, EE, EE, b_out, pm, 2*EE, h);

    // 4) MLP branch
    k_xmod<<<NROWS, 256>>>(ph1, 3*EE, 4*EE, px);
    k_gemm128<128, EPI_SILU><<<dim3(MM_/128, NROWS/128), 256>>>(
        px, W1, pt1, MM_, EE, b1, nullptr, 0, nullptr);
    k_gemm128<64, EPI_GATE_RES><<<dim3(EE/64, NROWS/128), 256>>>(
        pt1, W2, ph2, EE, MM_, b2, pm, 5*EE, ph1);

    // 5) trailing conditioning LayerNorms
    k_gemm128<64, EPI_ADD_RES><<<dim3(EE/64, NROWS/128), 256>>>(
        s_tem, W_tem, px, EE, TE_, b_tem, nullptr, 0, ph2);
    k_ln_affine<<<NROWS, 256>>>(px, g_tem, bt_tem, ph1);
    k_gemm128<64, EPI_ADD_RES><<<dim3(EE/64, NROWS/128), 256>>>(
        h_init, W_init, px, EE, EE, b_init, nullptr, 0, ph1);
    k_ln_affine<<<NROWS, 256>>>(px, g_init, bt_init, out);
}

// round 6
// speedup vs baseline: 2.2522x; 1.0121x over previous
#include <cuda_runtime.h>
#include <math.h>

// ---- problem constants ----
#define BB 8
#define LL 512
#define EE 256
#define HH 8
#define HD 32
#define BD_ 64
#define TD_ 256
#define TE_ 128
#define ED_ 64
#define MM_ 512
#define NROWS (BB*LL)          // 4096 token rows

typedef unsigned long long u64;

// ---- packed fp32x2 helpers (Blackwell f32x2 pipe; exact fp32 semantics) ----
__device__ __forceinline__ u64 pk2(float x, float y) {
    u64 r; asm("mov.b64 %0,{%1,%2};" : "=l"(r) : "f"(x), "f"(y)); return r;
}
__device__ __forceinline__ void fma2(u64& d, u64 a, u64 b) {
    asm("fma.rn.f32x2 %0,%1,%2,%0;" : "+l"(d) : "l"(a), "l"(b));
}
__device__ __forceinline__ void mul2(u64& d, u64 f) {
    asm("mul.rn.f32x2 %0,%0,%1;" : "+l"(d) : "l"(f));
}
__device__ __forceinline__ void unpk2(u64 v, float& x, float& y) {
    asm("mov.b64 {%0,%1},%2;" : "=f"(x), "=f"(y) : "l"(v));
}

// ---- scratch (device globals; no runtime allocation) ----
__device__ float g_u[NROWS*TD_];                       // silu(s)         4 MB
__device__ float g_m[NROWS*6*EE];                      // modulations    25 MB
__device__ float g_x[NROWS*EE];                        // staging         4 MB
__device__ float g_bias[(size_t)BB*HH*LL*LL];          // attn bias      64 MB
__device__ float g_qkv[NROWS*3*EE];                    // qkv            12 MB
__device__ float g_o[NROWS*EE];                        // attn out        4 MB
__device__ float g_h1[NROWS*EE];                       // residual 1      4 MB
__device__ float g_t1[NROWS*MM_];                      // mlp hidden      8 MB
__device__ float g_h2[NROWS*EE];                       // residual 2      4 MB

// =====================================================================
// High-throughput SGEMM: C[M,N] = A[M,K] @ B[N,K]^T  (+ epilogues)
// BM=128, BN in {128,64}, BK=16, 256 threads, 8x(BN/16) per-thread tile,
// double-buffered smem, packed f32x2 FMA inner loop.
// =====================================================================
#define EPI_BIAS     0
#define EPI_SILU     1
#define EPI_GATE_RES 2
#define EPI_ADD_RES  3
#define EPI_ADD_SILU 4

template<int BN, int EPI>
__global__ void __launch_bounds__(256) k_gemm128(
    const float* __restrict__ A, const float* __restrict__ B, float* __restrict__ C,
    int Nd, int Kd,
    const float* __restrict__ bias,
    const float* __restrict__ gate, int goff,
    const float* __restrict__ res)
{
    constexpr int TN = BN/16;            // 8 or 4
    constexpr int TN2 = TN/2;            // 4 or 2
    __shared__ __align__(16) float As[2][16][128];
    __shared__ __align__(16) float Bs[2][16][BN];

    int bm = blockIdx.y*128, bn = blockIdx.x*BN;
    int tid = threadIdx.x;

    // global load mapping
    int ar = tid >> 1, ak = (tid & 1)*8;
    int br, bk;
    if (BN == 128) { br = tid >> 1; bk = (tid & 1)*8; }
    else           { br = tid >> 2; bk = (tid & 3)*4; }

    const float* Aptr = A + (size_t)(bm + ar)*Kd + ak;
    const float* Bptr = B + (size_t)(bn + br)*Kd + bk;

    float4 ra0, ra1, rb0, rb1;

    // microtile mapping
    int wid = tid >> 5, lane = tid & 31;
    int row0 = (wid & 1)*64 + (lane & 7)*8;
    int col0 = (wid >> 1)*(BN/4) + (lane >> 3)*TN;

    u64 acc2[8][TN2] = {};               // packed pairs along n

    // prologue: load tile 0
    ra0 = *(const float4*)(Aptr);
    ra1 = *(const float4*)(Aptr + 4);
    rb0 = *(const float4*)(Bptr);
    if (BN == 128) rb1 = *(const float4*)(Bptr + 4);

    As[0][ak+0][ar]=ra0.x; As[0][ak+1][ar]=ra0.y; As[0][ak+2][ar]=ra0.z; As[0][ak+3][ar]=ra0.w;
    As[0][ak+4][ar]=ra1.x; As[0][ak+5][ar]=ra1.y; As[0][ak+6][ar]=ra1.z; As[0][ak+7][ar]=ra1.w;
    Bs[0][bk+0][br]=rb0.x; Bs[0][bk+1][br]=rb0.y; Bs[0][bk+2][br]=rb0.z; Bs[0][bk+3][br]=rb0.w;
    if (BN == 128) {
        Bs[0][bk+4][br]=rb1.x; Bs[0][bk+5][br]=rb1.y; Bs[0][bk+6][br]=rb1.z; Bs[0][bk+7][br]=rb1.w;
    }
    __syncthreads();

    int buf = 0;
    for (int k0 = 0; k0 < Kd; k0 += 16) {
        bool last = (k0 + 16 >= Kd);
        if (!last) {
            ra0 = *(const float4*)(Aptr + k0 + 16);
            ra1 = *(const float4*)(Aptr + k0 + 20);
            rb0 = *(const float4*)(Bptr + k0 + 16);
            if (BN == 128) rb1 = *(const float4*)(Bptr + k0 + 20);
        }
        #pragma unroll
        for (int kk = 0; kk < 16; kk++) {
            float af[8];
            *(float4*)&af[0] = *(const float4*)&As[buf][kk][row0];
            *(float4*)&af[4] = *(const float4*)&As[buf][kk][row0+4];
            u64 bv[TN2];
            {
                float4 b4a = *(const float4*)&Bs[buf][kk][col0];
                bv[0] = ((const u64*)&b4a)[0];
                bv[1] = ((const u64*)&b4a)[1];
                if (TN == 8) {
                    float4 b4b = *(const float4*)&Bs[buf][kk][col0+4];
                    bv[2] = ((const u64*)&b4b)[0];
                    bv[3] = ((const u64*)&b4b)[1];
                }
            }
            #pragma unroll
            for (int i = 0; i < 8; i++) {
                u64 ad = pk2(af[i], af[i]);
                #pragma unroll
                for (int j = 0; j < TN2; j++)
                    fma2(acc2[i][j], ad, bv[j]);
            }
        }
        if (!last) {
            int nb = buf ^ 1;
            As[nb][ak+0][ar]=ra0.x; As[nb][ak+1][ar]=ra0.y; As[nb][ak+2][ar]=ra0.z; As[nb][ak+3][ar]=ra0.w;
            As[nb][ak+4][ar]=ra1.x; As[nb][ak+5][ar]=ra1.y; As[nb][ak+6][ar]=ra1.z; As[nb][ak+7][ar]=ra1.w;
            Bs[nb][bk+0][br]=rb0.x; Bs[nb][bk+1][br]=rb0.y; Bs[nb][bk+2][br]=rb0.z; Bs[nb][bk+3][br]=rb0.w;
            if (BN == 128) {
                Bs[nb][bk+4][br]=rb1.x; Bs[nb][bk+5][br]=rb1.y; Bs[nb][bk+6][br]=rb1.z; Bs[nb][bk+7][br]=rb1.w;
            }
            __syncthreads();
            buf = nb;
        }
    }

    // epilogue (unpack, then fused op)
    #pragma unroll
    for (int i = 0; i < 8; i++) {
        int m = bm + row0 + i;
        float accf[TN];
        #pragma unroll
        for (int j = 0; j < TN2; j++) unpk2(acc2[i][j], accf[2*j], accf[2*j+1]);
        #pragma unroll
        for (int j4 = 0; j4 < TN; j4 += 4) {
            float4 v;
            float vv[4];
            #pragma unroll
            for (int u = 0; u < 4; u++) {
                int n = bn + col0 + j4 + u;
                float x = accf[j4+u] + bias[n];
                if (EPI == EPI_SILU)     x = x / (1.f + __expf(-x));
                if (EPI == EPI_GATE_RES) x = x*gate[(size_t)m*(6*EE) + goff + n] + res[(size_t)m*Nd + n];
                if (EPI == EPI_ADD_RES)  x = x + res[(size_t)m*Nd + n];
                if (EPI == EPI_ADD_SILU) { x = x + res[(size_t)m*Nd + n]; x = x / (1.f + __expf(-x)); }
                vv[u] = x;
            }
            v.x = vv[0]; v.y = vv[1]; v.z = vv[2]; v.w = vv[3];
            *(float4*)&C[(size_t)m*Nd + bn + col0 + j4] = v;
        }
    }
}

// =====================================================================
// k_xmod: dst = LN(src_row)*(1 + m[:,sc]) + m[:,sh]    (row = 256 wide)
// =====================================================================
__global__ void k_xmod(const float* __restrict__ src, int sh_off, int sc_off,
                       float* __restrict__ dst)
{
    int row = blockIdx.x, t = threadIdx.x;
    float v = src[(size_t)row*EE + t];
    __shared__ float s1[8], s2[8], bc[2];
    float a = v, b = v*v;
    #pragma unroll
    for (int o = 16; o > 0; o >>= 1) {
        a += __shfl_xor_sync(0xffffffffu, a, o);
        b += __shfl_xor_sync(0xffffffffu, b, o);
    }
    if ((t & 31) == 0) { s1[t>>5] = a; s2[t>>5] = b; }
    __syncthreads();
    if (t == 0) {
        float x = 0, y = 0;
        for (int i = 0; i < 8; i++) { x += s1[i]; y += s2[i]; }
        bc[0] = x*(1.f/EE); bc[1] = y*(1.f/EE);
    }
    __syncthreads();
    float mu = bc[0], var = bc[1] - mu*mu;
    float n = (v - mu)*rsqrtf(var + 1e-5f);
    const float* mrow = g_m + (size_t)row*(6*EE);
    dst[(size_t)row*EE + t] = n*(1.f + mrow[sc_off + t]) + mrow[sh_off + t];
}

// =====================================================================
// k_ln_affine: dst = LN(src_row)*g + bt
// =====================================================================
__global__ void k_ln_affine(const float* __restrict__ src, const float* __restrict__ g,
                            const float* __restrict__ bt, float* __restrict__ dst)
{
    int row = blockIdx.x, t = threadIdx.x;
    float v = src[(size_t)row*EE + t];
    __shared__ float s1[8], s2[8], bc[2];
    float a = v, b = v*v;
    #pragma unroll
    for (int o = 16; o > 0; o >>= 1) {
        a += __shfl_xor_sync(0xffffffffu, a, o);
        b += __shfl_xor_sync(0xffffffffu, b, o);
    }
    if ((t & 31) == 0) { s1[t>>5] = a; s2[t>>5] = b; }
    __syncthreads();
    if (t == 0) {
        float x = 0, y = 0;
        for (int i = 0; i < 8; i++) { x += s1[i]; y += s2[i]; }
        bc[0] = x*(1.f/EE); bc[1] = y*(1.f/EE);
    }
    __syncthreads();
    float mu = bc[0], var = bc[1] - mu*mu;
    float n = (v - mu)*rsqrtf(var + 1e-5f);
    dst[(size_t)row*EE + t] = n*g[t] + bt[t];
}

// =====================================================================
// k_bias2: bias[b,h,l,m] = (LN(p[b,l,m,:])*g_eln + b_eln) @ W_e^T + b_e
// Block = 256 m-rows staged in dynamic smem, thread = 1 row; LN folded
// into GEMV. (unchanged this round; profiled via launch-order slot)
// =====================================================================
#define BIAS_SMEM (256*68*4 + 512*4 + 16*4)
__global__ void __launch_bounds__(256) k_bias2(
        const float* __restrict__ p, const float* __restrict__ g_eln,
        const float* __restrict__ b_eln, const float* __restrict__ W_e,
        const float* __restrict__ b_e)
{
    extern __shared__ float sm[];
    float* srow = sm;                    // [256][68]
    float* sW   = sm + 256*68;           // [8][64]  (W' = g*W)
    float* scs  = sW + 512;              // [8] column sums of W'
    float* sct  = scs + 8;               // [8] constants
    int tid = threadIdx.x;

    for (int i = tid; i < 512; i += 256) sW[i] = g_eln[i & 63]*W_e[i];
    if (tid < 8) {
        float ct = 0.f;
        for (int k = 0; k < 64; k++) ct += b_eln[k]*W_e[tid*64 + k];
        sct[tid] = ct + b_e[tid];
    }
    __syncthreads();
    if (tid < 8) {
        float cs = 0.f;
        for (int k = 0; k < 64; k++) cs += sW[tid*64 + k];
        scs[tid] = cs;
    }

    // stage 256 rows of p (coalesced float4)
    int blk = blockIdx.x;
    const float4* src = (const float4*)(p + (size_t)blk*256*64);
    for (int i = tid; i < 256*16; i += 256) {
        int r = i >> 4, c4 = i & 15;
        *(float4*)&srow[r*68 + c4*4] = src[i];
    }
    __syncthreads();

    // one row per thread; packed f32x2 GEMV
    u64 P2[8] = {};
    u64 s2 = 0, q2 = 0;
    u64 one2 = pk2(1.f, 1.f);
    const float* rp = srow + tid*68;
    #pragma unroll
    for (int c = 0; c < 16; c++) {
        float4 a4 = *(const float4*)&rp[c*4];
        u64 a01 = ((const u64*)&a4)[0];
        u64 a23 = ((const u64*)&a4)[1];
        fma2(s2, a01, one2); fma2(s2, a23, one2);
        fma2(q2, a01, a01);  fma2(q2, a23, a23);
        #pragma unroll
        for (int hh = 0; hh < 8; hh++) {
            float4 w4 = *(const float4*)&sW[hh*64 + c*4];
            u64 w01 = ((const u64*)&w4)[0];
            u64 w23 = ((const u64*)&w4)[1];
            fma2(P2[hh], a01, w01);
            fma2(P2[hh], a23, w23);
        }
    }
    float sx, sy, qx, qy;
    unpk2(s2, sx, sy); unpk2(q2, qx, qy);
    float s = sx + sy, q = qx + qy;
    float mu = s*(1.f/64.f);
    float var = q*(1.f/64.f) - mu*mu;
    float rstd = rsqrtf(var + 1e-5f);

    int b = blk >> 10, l = (blk >> 1) & 511, m = (blk & 1)*256 + tid;
    #pragma unroll
    for (int hh = 0; hh < 8; hh++) {
        float px, py;
        unpk2(P2[hh], px, py);
        float o = rstd*((px + py) - mu*scs[hh]) + sct[hh];
        g_bias[(((size_t)b*HH + hh)*LL + l)*LL + m] = o;
    }
}

// =====================================================================
// k_attn: fused flash attention per (b,h,l-tile of 64), f32x2 FMA
// =====================================================================
__global__ void __launch_bounds__(256) k_attn()
{
    __shared__ __align__(16) float Qs[HD][64];
    __shared__ __align__(16) float Ks[HD][64];
    __shared__ __align__(16) float Vs[64][HD];
    __shared__ __align__(16) float Ps[64][68];       // pad 68: 16B-aligned rows
    __shared__ float m_run[64], l_run[64], scl[64];

    int bh = blockIdx.y;
    int b = bh >> 3, h = bh & 7;
    int l0 = blockIdx.x*64;
    int tid = threadIdx.x;

    {   // load Q tile, transposed [d][l]
        int r = tid >> 2, c = (tid & 3)*8;
        const float* q = g_qkv + (size_t)(b*LL + l0 + r)*768 + h*HD + c;
        float4 v0 = *(const float4*)q, v1 = *(const float4*)(q+4);
        Qs[c+0][r]=v0.x; Qs[c+1][r]=v0.y; Qs[c+2][r]=v0.z; Qs[c+3][r]=v0.w;
        Qs[c+4][r]=v1.x; Qs[c+5][r]=v1.y; Qs[c+6][r]=v1.z; Qs[c+7][r]=v1.w;
    }
    if (tid < 64) { m_run[tid] = -1e30f; l_run[tid] = 0.f; }

    int tx = tid & 15, ty = tid >> 4;
    int tx2 = tid & 7, ty2 = tid >> 3;
    u64 o2[2][2] = {};                     // packed output accumulators
    const float sc = 0.17677669529663687f; // 1/sqrt(32)

    for (int m0 = 0; m0 < LL; m0 += 64) {
        __syncthreads();
        {   // load K (transposed) + V tiles
            int r = tid >> 2, c = (tid & 3)*8;
            const float* kp = g_qkv + (size_t)(b*LL + m0 + r)*768 + 256 + h*HD + c;
            float4 v0 = *(const float4*)kp, v1 = *(const float4*)(kp+4);
            Ks[c+0][r]=v0.x; Ks[c+1][r]=v0.y; Ks[c+2][r]=v0.z; Ks[c+3][r]=v0.w;
            Ks[c+4][r]=v1.x; Ks[c+5][r]=v1.y; Ks[c+6][r]=v1.z; Ks[c+7][r]=v1.w;
            const float* vp = g_qkv + (size_t)(b*LL + m0 + r)*768 + 512 + h*HD + c;
            *(float4*)&Vs[r][c]   = *(const float4*)vp;
            *(float4*)&Vs[r][c+4] = *(const float4*)(vp+4);
        }
        __syncthreads();

        // --- S tile: QK (f32x2) + bias ---
        float s[4][4];
        {
            u64 qk2[4][2] = {};
            #pragma unroll
            for (int d = 0; d < HD; d++) {
                float4 qa = *(const float4*)&Qs[d][ty*4];
                float4 kb = *(const float4*)&Ks[d][tx*4];
                u64 k01 = ((const u64*)&kb)[0];
                u64 k23 = ((const u64*)&kb)[1];
                float qv[4] = {qa.x, qa.y, qa.z, qa.w};
                #pragma unroll
                for (int i = 0; i < 4; i++) {
                    u64 qd = pk2(qv[i], qv[i]);
                    fma2(qk2[i][0], qd, k01);
                    fma2(qk2[i][1], qd, k23);
                }
            }
            const float* bptr = g_bias + ((size_t)((b*HH + h)*LL + l0 + ty*4))*LL + m0 + tx*4;
            #pragma unroll
            for (int i = 0; i < 4; i++) {
                float q0, q1, q2v, q3;
                unpk2(qk2[i][0], q0, q1);
                unpk2(qk2[i][1], q2v, q3);
                float4 bb = *(const float4*)(bptr + (size_t)i*LL);
                s[i][0] = q0*sc + bb.x;
                s[i][1] = q1*sc + bb.y;
                s[i][2] = q2v*sc + bb.z;
                s[i][3] = q3*sc + bb.w;
            }
        }

        // --- online softmax (per row, reduced over 16-lane tx group) ---
        #pragma unroll
        for (int i = 0; i < 4; i++) {
            int row = ty*4 + i;
            float rm = fmaxf(fmaxf(s[i][0], s[i][1]), fmaxf(s[i][2], s[i][3]));
            #pragma unroll
            for (int o = 8; o > 0; o >>= 1)
                rm = fmaxf(rm, __shfl_xor_sync(0xffffffffu, rm, o));
            float mold = m_run[row];
            float mnew = fmaxf(mold, rm);
            float p0 = __expf(s[i][0] - mnew);
            float p1 = __expf(s[i][1] - mnew);
            float p2 = __expf(s[i][2] - mnew);
            float p3 = __expf(s[i][3] - mnew);
            float rs = p0 + p1 + p2 + p3;
            #pragma unroll
            for (int o = 8; o > 0; o >>= 1)
                rs += __shfl_xor_sync(0xffffffffu, rs, o);
            if (tx == 0) {
                float f = __expf(mold - mnew);
                m_run[row] = mnew;
                l_run[row] = l_run[row]*f + rs;
                scl[row] = f;
            }
            float4 pv4; pv4.x = p0; pv4.y = p1; pv4.z = p2; pv4.w = p3;
            *(float4*)&Ps[row][tx*4] = pv4;
        }
        __syncthreads();

        // --- PV accumulate with running rescale (f32x2) ---
        {
            int r0 = ty2*2;
            u64 f0d = pk2(scl[r0],   scl[r0]);
            u64 f1d = pk2(scl[r0+1], scl[r0+1]);
            mul2(o2[0][0], f0d); mul2(o2[0][1], f0d);
            mul2(o2[1][0], f1d); mul2(o2[1][1], f1d);
            #pragma unroll
            for (int kk = 0; kk < 64; kk += 4) {
                float4 pa4 = *(const float4*)&Ps[r0][kk];
                float4 pb4 = *(const float4*)&Ps[r0+1][kk];
                float pa[4] = {pa4.x, pa4.y, pa4.z, pa4.w};
                float pb[4] = {pb4.x, pb4.y, pb4.z, pb4.w};
                #pragma unroll
                for (int u = 0; u < 4; u++) {
                    float4 vv = *(const float4*)&Vs[kk+u][tx2*4];
                    u64 v01 = ((const u64*)&vv)[0];
                    u64 v23 = ((const u64*)&vv)[1];
                    u64 pad = pk2(pa[u], pa[u]);
                    u64 pbd = pk2(pb[u], pb[u]);
                    fma2(o2[0][0], pad, v01); fma2(o2[0][1], pad, v23);
                    fma2(o2[1][0], pbd, v01); fma2(o2[1][1], pbd, v23);
                }
            }
        }
    }

    // finalize
    int r0 = ty2*2;
    float inv0 = 1.f/l_run[r0], inv1 = 1.f/l_run[r0+1];
    float4 o0, o1;
    unpk2(o2[0][0], o0.x, o0.y); unpk2(o2[0][1], o0.z, o0.w);
    unpk2(o2[1][0], o1.x, o1.y); unpk2(o2[1][1], o1.z, o1.w);
    o0.x *= inv0; o0.y *= inv0; o0.z *= inv0; o0.w *= inv0;
    o1.x *= inv1; o1.y *= inv1; o1.z *= inv1; o1.w *= inv1;
    *(float4*)&g_o[(size_t)(b*LL + l0 + r0    )*EE + h*HD + tx2*4] = o0;
    *(float4*)&g_o[(size_t)(b*LL + l0 + r0 + 1)*EE + h*HD + tx2*4] = o1;
}

// =====================================================================
// launch
// =====================================================================
extern "C" void kernel_launch(void* const* d_in, const int* in_sizes, int n_in,
                              void* d_out, int out_size)
{
    const float* h      = (const float*)d_in[0];
    const float* h_init = (const float*)d_in[1];
    const float* s_a    = (const float*)d_in[2];
    const float* s_t    = (const float*)d_in[3];
    const float* s_tem  = (const float*)d_in[4];
    const float* p      = (const float*)d_in[5];
    const float* W_bp   = (const float*)d_in[6];
    const float* b_bp   = (const float*)d_in[7];
    const float* W_ada  = (const float*)d_in[8];
    const float* b_ada  = (const float*)d_in[9];
    const float* g_eln  = (const float*)d_in[10];
    const float* b_eln  = (const float*)d_in[11];
    const float* W_e    = (const float*)d_in[12];
    const float* b_e    = (const float*)d_in[13];
    const float* W_in   = (const float*)d_in[14];
    const float* b_in   = (const float*)d_in[15];
    const float* W_out  = (const float*)d_in[16];
    const float* b_out  = (const float*)d_in[17];
    const float* W1     = (const float*)d_in[18];
    const float* b1     = (const float*)d_in[19];
    const float* W2     = (const float*)d_in[20];
    const float* b2     = (const float*)d_in[21];
    const float* W_tem  = (const float*)d_in[22];
    const float* b_tem  = (const float*)d_in[23];
    const float* g_tem  = (const float*)d_in[24];
    const float* bt_tem = (const float*)d_in[25];
    const float* W_init = (const float*)d_in[26];
    const float* b_init = (const float*)d_in[27];
    const float* g_init = (const float*)d_in[28];
    const float* bt_init= (const float*)d_in[29];
    float* out = (float*)d_out;

    float *pu, *pm, *px, *pqkv, *po, *ph1, *pt1, *ph2;
    cudaGetSymbolAddress((void**)&pu,   g_u);
    cudaGetSymbolAddress((void**)&pm,   g_m);
    cudaGetSymbolAddress((void**)&px,   g_x);
    cudaGetSymbolAddress((void**)&pqkv, g_qkv);
    cudaGetSymbolAddress((void**)&po,   g_o);
    cudaGetSymbolAddress((void**)&ph1,  g_h1);
    cudaGetSymbolAddress((void**)&pt1,  g_t1);
    cudaGetSymbolAddress((void**)&ph2,  g_h2);

    cudaFuncSetAttribute(k_bias2, cudaFuncAttributeMaxDynamicSharedMemorySize, BIAS_SMEM);

    // 1) conditioning: u = silu(s_a @ W_bp^T + b_bp + s_t)
    k_gemm128<128, EPI_ADD_SILU><<<dim3(TD_/128, NROWS/128), 256>>>(
        s_a, W_bp, pu, TD_, BD_, b_bp, nullptr, 0, s_t);
    k_gemm128<128, EPI_BIAS><<<dim3(6*EE/128, NROWS/128), 256>>>(
        pu, W_ada, pm, 6*EE, TD_, b_ada, nullptr, 0, nullptr);

    // 2+3) attention branch.  NOTE: k_xmod moved before k_bias2 (both legal
    // orderings; this puts k_bias2 into ncu's fixed capture slot).
    k_xmod<<<NROWS, 256>>>(h, 0, EE, px);
    k_bias2<<<(BB*LL*LL)/256, 256, BIAS_SMEM>>>(p, g_eln, b_eln, W_e, b_e);
    k_gemm128<128, EPI_BIAS><<<dim3(3*EE/128, NROWS/128), 256>>>(
        px, W_in, pqkv, 3*EE, EE, b_in, nullptr, 0, nullptr);
    k_attn<<<dim3(LL/64, BB*HH), 256>>>();
    k_gemm128<64, EPI_GATE_RES><<<dim3(EE/64, NROWS/128), 256>>>(
        po, W_out, ph1, EE, EE, b_out, pm, 2*EE, h);

    // 4) MLP branch
    k_xmod<<<NROWS, 256>>>(ph1, 3*EE, 4*EE, px);
    k_gemm128<128, EPI_SILU><<<dim3(MM_/128, NROWS/128), 256>>>(
        px, W1, pt1, MM_, EE, b1, nullptr, 0, nullptr);
    k_gemm128<64, EPI_GATE_RES><<<dim3(EE/64, NROWS/128), 256>>>(
        pt1, W2, ph2, EE, MM_, b2, pm, 5*EE, ph1);

    // 5) trailing conditioning LayerNorms
    k_gemm128<64, EPI_ADD_RES><<<dim3(EE/64, NROWS/128), 256>>>(
        s_tem, W_tem, px, EE, TE_, b_tem, nullptr, 0, ph2);
    k_ln_affine<<<NROWS, 256>>>(px, g_tem, bt_tem, ph1);
    k_gemm128<64, EPI_ADD_RES><<<dim3(EE/64, NROWS/128), 256>>>(
        h_init, W_init, px, EE, EE, b_init, nullptr, 0, ph1);
    k_ln_affine<<<NROWS, 256>>>(px, g_init, bt_init, out);
}

// round 7
// speedup vs baseline: 2.3920x; 1.0621x over previous
#include <cuda_runtime.h>
#include <math.h>

// ---- problem constants ----
#define BB 8
#define LL 512
#define EE 256
#define HH 8
#define HD 32
#define BD_ 64
#define TD_ 256
#define TE_ 128
#define ED_ 64
#define MM_ 512
#define NROWS (BB*LL)          // 4096 token rows

typedef unsigned long long u64;

// ---- packed fp32x2 helpers (Blackwell f32x2 pipe; exact fp32 semantics) ----
__device__ __forceinline__ u64 pk2(float x, float y) {
    u64 r; asm("mov.b64 %0,{%1,%2};" : "=l"(r) : "f"(x), "f"(y)); return r;
}
__device__ __forceinline__ void fma2(u64& d, u64 a, u64 b) {
    asm("fma.rn.f32x2 %0,%1,%2,%0;" : "+l"(d) : "l"(a), "l"(b));
}
__device__ __forceinline__ void mul2(u64& d, u64 f) {
    asm("mul.rn.f32x2 %0,%0,%1;" : "+l"(d) : "l"(f));
}
__device__ __forceinline__ void unpk2(u64 v, float& x, float& y) {
    asm("mov.b64 {%0,%1},%2;" : "=f"(x), "=f"(y) : "l"(v));
}

// ---- scratch (device globals; no runtime allocation) ----
__device__ float g_u[NROWS*TD_];                       // silu(s)         4 MB
__device__ float g_m[NROWS*6*EE];                      // modulations    25 MB
__device__ float g_x[NROWS*EE];                        // staging         4 MB
__device__ float g_bias[(size_t)BB*HH*LL*LL];          // attn bias      64 MB
__device__ float g_qkv[NROWS*3*EE];                    // qkv            12 MB
__device__ float g_o[NROWS*EE];                        // attn out        4 MB
__device__ float g_h1[NROWS*EE];                       // residual 1      4 MB
__device__ float g_t1[NROWS*MM_];                      // mlp hidden      8 MB
__device__ float g_h2[NROWS*EE];                       // residual 2      4 MB

// =====================================================================
// High-throughput SGEMM: C[M,N] = A[M,K] @ B[N,K]^T  (+ epilogues)
// BM=128, BN in {128,64}, BK=16, 256 threads, 8x(BN/16) per-thread tile,
// double-buffered smem, packed f32x2 FMA inner loop.
// =====================================================================
#define EPI_BIAS     0
#define EPI_SILU     1
#define EPI_GATE_RES 2
#define EPI_ADD_RES  3
#define EPI_ADD_SILU 4

template<int BN, int EPI>
__global__ void __launch_bounds__(256) k_gemm128(
    const float* __restrict__ A, const float* __restrict__ B, float* __restrict__ C,
    int Nd, int Kd,
    const float* __restrict__ bias,
    const float* __restrict__ gate, int goff,
    const float* __restrict__ res)
{
    constexpr int TN = BN/16;            // 8 or 4
    constexpr int TN2 = TN/2;            // 4 or 2
    __shared__ __align__(16) float As[2][16][128];
    __shared__ __align__(16) float Bs[2][16][BN];

    int bm = blockIdx.y*128, bn = blockIdx.x*BN;
    int tid = threadIdx.x;

    // global load mapping
    int ar = tid >> 1, ak = (tid & 1)*8;
    int br, bk;
    if (BN == 128) { br = tid >> 1; bk = (tid & 1)*8; }
    else           { br = tid >> 2; bk = (tid & 3)*4; }

    const float* Aptr = A + (size_t)(bm + ar)*Kd + ak;
    const float* Bptr = B + (size_t)(bn + br)*Kd + bk;

    float4 ra0, ra1, rb0, rb1;

    // microtile mapping
    int wid = tid >> 5, lane = tid & 31;
    int row0 = (wid & 1)*64 + (lane & 7)*8;
    int col0 = (wid >> 1)*(BN/4) + (lane >> 3)*TN;

    u64 acc2[8][TN2] = {};               // packed pairs along n

    // prologue: load tile 0
    ra0 = *(const float4*)(Aptr);
    ra1 = *(const float4*)(Aptr + 4);
    rb0 = *(const float4*)(Bptr);
    if (BN == 128) rb1 = *(const float4*)(Bptr + 4);

    As[0][ak+0][ar]=ra0.x; As[0][ak+1][ar]=ra0.y; As[0][ak+2][ar]=ra0.z; As[0][ak+3][ar]=ra0.w;
    As[0][ak+4][ar]=ra1.x; As[0][ak+5][ar]=ra1.y; As[0][ak+6][ar]=ra1.z; As[0][ak+7][ar]=ra1.w;
    Bs[0][bk+0][br]=rb0.x; Bs[0][bk+1][br]=rb0.y; Bs[0][bk+2][br]=rb0.z; Bs[0][bk+3][br]=rb0.w;
    if (BN == 128) {
        Bs[0][bk+4][br]=rb1.x; Bs[0][bk+5][br]=rb1.y; Bs[0][bk+6][br]=rb1.z; Bs[0][bk+7][br]=rb1.w;
    }
    __syncthreads();

    int buf = 0;
    for (int k0 = 0; k0 < Kd; k0 += 16) {
        bool last = (k0 + 16 >= Kd);
        if (!last) {
            ra0 = *(const float4*)(Aptr + k0 + 16);
            ra1 = *(const float4*)(Aptr + k0 + 20);
            rb0 = *(const float4*)(Bptr + k0 + 16);
            if (BN == 128) rb1 = *(const float4*)(Bptr + k0 + 20);
        }
        #pragma unroll
        for (int kk = 0; kk < 16; kk++) {
            float af[8];
            *(float4*)&af[0] = *(const float4*)&As[buf][kk][row0];
            *(float4*)&af[4] = *(const float4*)&As[buf][kk][row0+4];
            u64 bv[TN2];
            {
                float4 b4a = *(const float4*)&Bs[buf][kk][col0];
                bv[0] = ((const u64*)&b4a)[0];
                bv[1] = ((const u64*)&b4a)[1];
                if (TN == 8) {
                    float4 b4b = *(const float4*)&Bs[buf][kk][col0+4];
                    bv[2] = ((const u64*)&b4b)[0];
                    bv[3] = ((const u64*)&b4b)[1];
                }
            }
            #pragma unroll
            for (int i = 0; i < 8; i++) {
                u64 ad = pk2(af[i], af[i]);
                #pragma unroll
                for (int j = 0; j < TN2; j++)
                    fma2(acc2[i][j], ad, bv[j]);
            }
        }
        if (!last) {
            int nb = buf ^ 1;
            As[nb][ak+0][ar]=ra0.x; As[nb][ak+1][ar]=ra0.y; As[nb][ak+2][ar]=ra0.z; As[nb][ak+3][ar]=ra0.w;
            As[nb][ak+4][ar]=ra1.x; As[nb][ak+5][ar]=ra1.y; As[nb][ak+6][ar]=ra1.z; As[nb][ak+7][ar]=ra1.w;
            Bs[nb][bk+0][br]=rb0.x; Bs[nb][bk+1][br]=rb0.y; Bs[nb][bk+2][br]=rb0.z; Bs[nb][bk+3][br]=rb0.w;
            if (BN == 128) {
                Bs[nb][bk+4][br]=rb1.x; Bs[nb][bk+5][br]=rb1.y; Bs[nb][bk+6][br]=rb1.z; Bs[nb][bk+7][br]=rb1.w;
            }
            __syncthreads();
            buf = nb;
        }
    }

    // epilogue (unpack, then fused op)
    #pragma unroll
    for (int i = 0; i < 8; i++) {
        int m = bm + row0 + i;
        float accf[TN];
        #pragma unroll
        for (int j = 0; j < TN2; j++) unpk2(acc2[i][j], accf[2*j], accf[2*j+1]);
        #pragma unroll
        for (int j4 = 0; j4 < TN; j4 += 4) {
            float4 v;
            float vv[4];
            #pragma unroll
            for (int u = 0; u < 4; u++) {
                int n = bn + col0 + j4 + u;
                float x = accf[j4+u] + bias[n];
                if (EPI == EPI_SILU)     x = x / (1.f + __expf(-x));
                if (EPI == EPI_GATE_RES) x = x*gate[(size_t)m*(6*EE) + goff + n] + res[(size_t)m*Nd + n];
                if (EPI == EPI_ADD_RES)  x = x + res[(size_t)m*Nd + n];
                if (EPI == EPI_ADD_SILU) { x = x + res[(size_t)m*Nd + n]; x = x / (1.f + __expf(-x)); }
                vv[u] = x;
            }
            v.x = vv[0]; v.y = vv[1]; v.z = vv[2]; v.w = vv[3];
            *(float4*)&C[(size_t)m*Nd + bn + col0 + j4] = v;
        }
    }
}

// =====================================================================
// k_xmod: dst = LN(src_row)*(1 + m[:,sc]) + m[:,sh]    (row = 256 wide)
// =====================================================================
__global__ void k_xmod(const float* __restrict__ src, int sh_off, int sc_off,
                       float* __restrict__ dst)
{
    int row = blockIdx.x, t = threadIdx.x;
    float v = src[(size_t)row*EE + t];
    __shared__ float s1[8], s2[8], bc[2];
    float a = v, b = v*v;
    #pragma unroll
    for (int o = 16; o > 0; o >>= 1) {
        a += __shfl_xor_sync(0xffffffffu, a, o);
        b += __shfl_xor_sync(0xffffffffu, b, o);
    }
    if ((t & 31) == 0) { s1[t>>5] = a; s2[t>>5] = b; }
    __syncthreads();
    if (t == 0) {
        float x = 0, y = 0;
        for (int i = 0; i < 8; i++) { x += s1[i]; y += s2[i]; }
        bc[0] = x*(1.f/EE); bc[1] = y*(1.f/EE);
    }
    __syncthreads();
    float mu = bc[0], var = bc[1] - mu*mu;
    float n = (v - mu)*rsqrtf(var + 1e-5f);
    const float* mrow = g_m + (size_t)row*(6*EE);
    dst[(size_t)row*EE + t] = n*(1.f + mrow[sc_off + t]) + mrow[sh_off + t];
}

// =====================================================================
// k_ln_affine: dst = LN(src_row)*g + bt
// =====================================================================
__global__ void k_ln_affine(const float* __restrict__ src, const float* __restrict__ g,
                            const float* __restrict__ bt, float* __restrict__ dst)
{
    int row = blockIdx.x, t = threadIdx.x;
    float v = src[(size_t)row*EE + t];
    __shared__ float s1[8], s2[8], bc[2];
    float a = v, b = v*v;
    #pragma unroll
    for (int o = 16; o > 0; o >>= 1) {
        a += __shfl_xor_sync(0xffffffffu, a, o);
        b += __shfl_xor_sync(0xffffffffu, b, o);
    }
    if ((t & 31) == 0) { s1[t>>5] = a; s2[t>>5] = b; }
    __syncthreads();
    if (t == 0) {
        float x = 0, y = 0;
        for (int i = 0; i < 8; i++) { x += s1[i]; y += s2[i]; }
        bc[0] = x*(1.f/EE); bc[1] = y*(1.f/EE);
    }
    __syncthreads();
    float mu = bc[0], var = bc[1] - mu*mu;
    float n = (v - mu)*rsqrtf(var + 1e-5f);
    dst[(size_t)row*EE + t] = n*g[t] + bt[t];
}

// =====================================================================
// k_bias3: bias[b,h,l,m] = (LN(p[b,l,m,:])*g_eln + b_eln) @ W_e^T + b_e
// Block = 512 m-rows of one (b,l), 2 pipelined halves of 256 rows.
// XOR-swizzled smem (row stride 64 floats, chunk c at c^(r&15)) =>
// conflict-free LDS.128 on store AND per-thread row reads.
// LDGs for half 1 issued before half-0 compute (DRAM/compute overlap).
// =====================================================================
#define BIAS_SMEM (2*256*64*4 + 512*4 + 16*4)
__global__ void __launch_bounds__(256) k_bias3(
        const float* __restrict__ p, const float* __restrict__ g_eln,
        const float* __restrict__ b_eln, const float* __restrict__ W_e,
        const float* __restrict__ b_e)
{
    extern __shared__ float sm[];
    float* sW   = sm + 2*256*64;         // [8][64]  (W' = g*W)
    float* scs  = sW + 512;              // [8] column sums of W'
    float* sct  = scs + 8;               // [8] constants
    int tid = threadIdx.x;

    for (int i = tid; i < 512; i += 256) sW[i] = g_eln[i & 63]*W_e[i];
    if (tid < 8) {
        float ct = 0.f;
        for (int k = 0; k < 64; k++) ct += b_eln[k]*W_e[tid*64 + k];
        sct[tid] = ct + b_e[tid];
    }
    __syncthreads();
    if (tid < 8) {
        float cs = 0.f;
        for (int k = 0; k < 64; k++) cs += sW[tid*64 + k];
        scs[tid] = cs;
    }

    int blk = blockIdx.x;                 // one (b,l): all 512 m-rows
    int b = blk >> 9, l = blk & 511;
    const float4* src = (const float4*)(p + (size_t)blk*512*64);

    // prologue: stage half 0 (rows 0..255), swizzled
    float4 st[16];
    #pragma unroll
    for (int j = 0; j < 16; j++) st[j] = src[j*256 + tid];
    #pragma unroll
    for (int j = 0; j < 16; j++) {
        int lin = j*256 + tid;
        int r = lin >> 4, c = lin & 15;
        *(float4*)&sm[r*64 + ((c ^ (r & 15)) << 2)] = st[j];
    }
    __syncthreads();   // also publishes sW/scs/sct

    u64 one2 = pk2(1.f, 1.f);
    int swz = tid & 15;

    #pragma unroll
    for (int half = 0; half < 2; half++) {
        if (half == 0) {   // issue half-1 loads; they fly during compute
            #pragma unroll
            for (int j = 0; j < 16; j++) st[j] = src[(16 + j)*256 + tid];
        }
        const float* base = sm + half*(256*64) + tid*64;

        u64 P2[8] = {};
        u64 s2 = 0, q2 = 0;
        #pragma unroll
        for (int c = 0; c < 16; c++) {
            float4 a4 = *(const float4*)&base[(c ^ swz) << 2];
            u64 a01 = ((const u64*)&a4)[0];
            u64 a23 = ((const u64*)&a4)[1];
            fma2(s2, a01, one2); fma2(s2, a23, one2);
            fma2(q2, a01, a01);  fma2(q2, a23, a23);
            #pragma unroll
            for (int hh = 0; hh < 8; hh++) {
                float4 w4 = *(const float4*)&sW[hh*64 + c*4];   // broadcast
                u64 w01 = ((const u64*)&w4)[0];
                u64 w23 = ((const u64*)&w4)[1];
                fma2(P2[hh], a01, w01);
                fma2(P2[hh], a23, w23);
            }
        }
        float sx, sy, qx, qy;
        unpk2(s2, sx, sy); unpk2(q2, qx, qy);
        float s = sx + sy, q = qx + qy;
        float mu = s*(1.f/64.f);
        float var = q*(1.f/64.f) - mu*mu;
        float rstd = rsqrtf(var + 1e-5f);

        int m = half*256 + tid;
        #pragma unroll
        for (int hh = 0; hh < 8; hh++) {
            float px, py;
            unpk2(P2[hh], px, py);
            float o = rstd*((px + py) - mu*scs[hh]) + sct[hh];
            g_bias[(((size_t)b*HH + hh)*LL + l)*LL + m] = o;
        }

        if (half == 0) {   // stage half 1 into second buffer (no read overlap)
            #pragma unroll
            for (int j = 0; j < 16; j++) {
                int lin = j*256 + tid;
                int r = lin >> 4, c = lin & 15;
                *(float4*)&sm[256*64 + r*64 + ((c ^ (r & 15)) << 2)] = st[j];
            }
            __syncthreads();
        }
    }
}

// =====================================================================
// k_attn: fused flash attention per (b,h,l-tile of 64), f32x2 FMA
// =====================================================================
__global__ void __launch_bounds__(256) k_attn()
{
    __shared__ __align__(16) float Qs[HD][64];
    __shared__ __align__(16) float Ks[HD][64];
    __shared__ __align__(16) float Vs[64][HD];
    __shared__ __align__(16) float Ps[64][68];       // pad 68: 16B-aligned rows
    __shared__ float m_run[64], l_run[64], scl[64];

    int bh = blockIdx.y;
    int b = bh >> 3, h = bh & 7;
    int l0 = blockIdx.x*64;
    int tid = threadIdx.x;

    {   // load Q tile, transposed [d][l]
        int r = tid >> 2, c = (tid & 3)*8;
        const float* q = g_qkv + (size_t)(b*LL + l0 + r)*768 + h*HD + c;
        float4 v0 = *(const float4*)q, v1 = *(const float4*)(q+4);
        Qs[c+0][r]=v0.x; Qs[c+1][r]=v0.y; Qs[c+2][r]=v0.z; Qs[c+3][r]=v0.w;
        Qs[c+4][r]=v1.x; Qs[c+5][r]=v1.y; Qs[c+6][r]=v1.z; Qs[c+7][r]=v1.w;
    }
    if (tid < 64) { m_run[tid] = -1e30f; l_run[tid] = 0.f; }

    int tx = tid & 15, ty = tid >> 4;
    int tx2 = tid & 7, ty2 = tid >> 3;
    u64 o2[2][2] = {};                     // packed output accumulators
    const float sc = 0.17677669529663687f; // 1/sqrt(32)

    for (int m0 = 0; m0 < LL; m0 += 64) {
        __syncthreads();
        {   // load K (transposed) + V tiles
            int r = tid >> 2, c = (tid & 3)*8;
            const float* kp = g_qkv + (size_t)(b*LL + m0 + r)*768 + 256 + h*HD + c;
            float4 v0 = *(const float4*)kp, v1 = *(const float4*)(kp+4);
            Ks[c+0][r]=v0.x; Ks[c+1][r]=v0.y; Ks[c+2][r]=v0.z; Ks[c+3][r]=v0.w;
            Ks[c+4][r]=v1.x; Ks[c+5][r]=v1.y; Ks[c+6][r]=v1.z; Ks[c+7][r]=v1.w;
            const float* vp = g_qkv + (size_t)(b*LL + m0 + r)*768 + 512 + h*HD + c;
            *(float4*)&Vs[r][c]   = *(const float4*)vp;
            *(float4*)&Vs[r][c+4] = *(const float4*)(vp+4);
        }
        __syncthreads();

        // --- S tile: QK (f32x2) + bias ---
        float s[4][4];
        {
            u64 qk2[4][2] = {};
            #pragma unroll
            for (int d = 0; d < HD; d++) {
                float4 qa = *(const float4*)&Qs[d][ty*4];
                float4 kb = *(const float4*)&Ks[d][tx*4];
                u64 k01 = ((const u64*)&kb)[0];
                u64 k23 = ((const u64*)&kb)[1];
                float qv[4] = {qa.x, qa.y, qa.z, qa.w};
                #pragma unroll
                for (int i = 0; i < 4; i++) {
                    u64 qd = pk2(qv[i], qv[i]);
                    fma2(qk2[i][0], qd, k01);
                    fma2(qk2[i][1], qd, k23);
                }
            }
            const float* bptr = g_bias + ((size_t)((b*HH + h)*LL + l0 + ty*4))*LL + m0 + tx*4;
            #pragma unroll
            for (int i = 0; i < 4; i++) {
                float q0, q1, q2v, q3;
                unpk2(qk2[i][0], q0, q1);
                unpk2(qk2[i][1], q2v, q3);
                float4 bb = *(const float4*)(bptr + (size_t)i*LL);
                s[i][0] = q0*sc + bb.x;
                s[i][1] = q1*sc + bb.y;
                s[i][2] = q2v*sc + bb.z;
                s[i][3] = q3*sc + bb.w;
            }
        }

        // --- online softmax (per row, reduced over 16-lane tx group) ---
        #pragma unroll
        for (int i = 0; i < 4; i++) {
            int row = ty*4 + i;
            float rm = fmaxf(fmaxf(s[i][0], s[i][1]), fmaxf(s[i][2], s[i][3]));
            #pragma unroll
            for (int o = 8; o > 0; o >>= 1)
                rm = fmaxf(rm, __shfl_xor_sync(0xffffffffu, rm, o));
            float mold = m_run[row];
            float mnew = fmaxf(mold, rm);
            float p0 = __expf(s[i][0] - mnew);
            float p1 = __expf(s[i][1] - mnew);
            float p2 = __expf(s[i][2] - mnew);
            float p3 = __expf(s[i][3] - mnew);
            float rs = p0 + p1 + p2 + p3;
            #pragma unroll
            for (int o = 8; o > 0; o >>= 1)
                rs += __shfl_xor_sync(0xffffffffu, rs, o);
            if (tx == 0) {
                float f = __expf(mold - mnew);
                m_run[row] = mnew;
                l_run[row] = l_run[row]*f + rs;
                scl[row] = f;
            }
            float4 pv4; pv4.x = p0; pv4.y = p1; pv4.z = p2; pv4.w = p3;
            *(float4*)&Ps[row][tx*4] = pv4;
        }
        __syncthreads();

        // --- PV accumulate with running rescale (f32x2) ---
        {
            int r0 = ty2*2;
            u64 f0d = pk2(scl[r0],   scl[r0]);
            u64 f1d = pk2(scl[r0+1], scl[r0+1]);
            mul2(o2[0][0], f0d); mul2(o2[0][1], f0d);
            mul2(o2[1][0], f1d); mul2(o2[1][1], f1d);
            #pragma unroll
            for (int kk = 0; kk < 64; kk += 4) {
                float4 pa4 = *(const float4*)&Ps[r0][kk];
                float4 pb4 = *(const float4*)&Ps[r0+1][kk];
                float pa[4] = {pa4.x, pa4.y, pa4.z, pa4.w};
                float pb[4] = {pb4.x, pb4.y, pb4.z, pb4.w};
                #pragma unroll
                for (int u = 0; u < 4; u++) {
                    float4 vv = *(const float4*)&Vs[kk+u][tx2*4];
                    u64 v01 = ((const u64*)&vv)[0];
                    u64 v23 = ((const u64*)&vv)[1];
                    u64 pad = pk2(pa[u], pa[u]);
                    u64 pbd = pk2(pb[u], pb[u]);
                    fma2(o2[0][0], pad, v01); fma2(o2[0][1], pad, v23);
                    fma2(o2[1][0], pbd, v01); fma2(o2[1][1], pbd, v23);
                }
            }
        }
    }

    // finalize
    int r0 = ty2*2;
    float inv0 = 1.f/l_run[r0], inv1 = 1.f/l_run[r0+1];
    float4 o0, o1;
    unpk2(o2[0][0], o0.x, o0.y); unpk2(o2[0][1], o0.z, o0.w);
    unpk2(o2[1][0], o1.x, o1.y); unpk2(o2[1][1], o1.z, o1.w);
    o0.x *= inv0; o0.y *= inv0; o0.z *= inv0; o0.w *= inv0;
    o1.x *= inv1; o1.y *= inv1; o1.z *= inv1; o1.w *= inv1;
    *(float4*)&g_o[(size_t)(b*LL + l0 + r0    )*EE + h*HD + tx2*4] = o0;
    *(float4*)&g_o[(size_t)(b*LL + l0 + r0 + 1)*EE + h*HD + tx2*4] = o1;
}

// =====================================================================
// launch
// =====================================================================
extern "C" void kernel_launch(void* const* d_in, const int* in_sizes, int n_in,
                              void* d_out, int out_size)
{
    const float* h      = (const float*)d_in[0];
    const float* h_init = (const float*)d_in[1];
    const float* s_a    = (const float*)d_in[2];
    const float* s_t    = (const float*)d_in[3];
    const float* s_tem  = (const float*)d_in[4];
    const float* p      = (const float*)d_in[5];
    const float* W_bp   = (const float*)d_in[6];
    const float* b_bp   = (const float*)d_in[7];
    const float* W_ada  = (const float*)d_in[8];
    const float* b_ada  = (const float*)d_in[9];
    const float* g_eln  = (const float*)d_in[10];
    const float* b_eln  = (const float*)d_in[11];
    const float* W_e    = (const float*)d_in[12];
    const float* b_e    = (const float*)d_in[13];
    const float* W_in   = (const float*)d_in[14];
    const float* b_in   = (const float*)d_in[15];
    const float* W_out  = (const float*)d_in[16];
    const float* b_out  = (const float*)d_in[17];
    const float* W1     = (const float*)d_in[18];
    const float* b1     = (const float*)d_in[19];
    const float* W2     = (const float*)d_in[20];
    const float* b2     = (const float*)d_in[21];
    const float* W_tem  = (const float*)d_in[22];
    const float* b_tem  = (const float*)d_in[23];
    const float* g_tem  = (const float*)d_in[24];
    const float* bt_tem = (const float*)d_in[25];
    const float* W_init = (const float*)d_in[26];
    const float* b_init = (const float*)d_in[27];
    const float* g_init = (const float*)d_in[28];
    const float* bt_init= (const float*)d_in[29];
    float* out = (float*)d_out;

    float *pu, *pm, *px, *pqkv, *po, *ph1, *pt1, *ph2;
    cudaGetSymbolAddress((void**)&pu,   g_u);
    cudaGetSymbolAddress((void**)&pm,   g_m);
    cudaGetSymbolAddress((void**)&px,   g_x);
    cudaGetSymbolAddress((void**)&pqkv, g_qkv);
    cudaGetSymbolAddress((void**)&po,   g_o);
    cudaGetSymbolAddress((void**)&ph1,  g_h1);
    cudaGetSymbolAddress((void**)&pt1,  g_t1);
    cudaGetSymbolAddress((void**)&ph2,  g_h2);

    cudaFuncSetAttribute(k_bias3, cudaFuncAttributeMaxDynamicSharedMemorySize, BIAS_SMEM);

    // 1) conditioning: u = silu(s_a @ W_bp^T + b_bp + s_t)
    k_gemm128<128, EPI_ADD_SILU><<<dim3(TD_/128, NROWS/128), 256>>>(
        s_a, W_bp, pu, TD_, BD_, b_bp, nullptr, 0, s_t);
    k_gemm128<128, EPI_BIAS><<<dim3(6*EE/128, NROWS/128), 256>>>(
        pu, W_ada, pm, 6*EE, TD_, b_ada, nullptr, 0, nullptr);

    // 2+3) attention branch.  qkv GEMM placed 4th => lands in ncu slot.
    k_xmod<<<NROWS, 256>>>(h, 0, EE, px);
    k_gemm128<128, EPI_BIAS><<<dim3(3*EE/128, NROWS/128), 256>>>(
        px, W_in, pqkv, 3*EE, EE, b_in, nullptr, 0, nullptr);
    k_bias3<<<BB*LL, 256, BIAS_SMEM>>>(p, g_eln, b_eln, W_e, b_e);
    k_attn<<<dim3(LL/64, BB*HH), 256>>>();
    k_gemm128<64, EPI_GATE_RES><<<dim3(EE/64, NROWS/128), 256>>>(
        po, W_out, ph1, EE, EE, b_out, pm, 2*EE, h);

    // 4) MLP branch
    k_xmod<<<NROWS, 256>>>(ph1, 3*EE, 4*EE, px);
    k_gemm128<128, EPI_SILU><<<dim3(MM_/128, NROWS/128), 256>>>(
        px, W1, pt1, MM_, EE, b1, nullptr, 0, nullptr);
    k_gemm128<64, EPI_GATE_RES><<<dim3(EE/64, NROWS/128), 256>>>(
        pt1, W2, ph2, EE, MM_, b2, pm, 5*EE, ph1);

    // 5) trailing conditioning LayerNorms
    k_gemm128<64, EPI_ADD_RES><<<dim3(EE/64, NROWS/128), 256>>>(
        s_tem, W_tem, px, EE, TE_, b_tem, nullptr, 0, ph2);
    k_ln_affine<<<NROWS, 256>>>(px, g_tem, bt_tem, ph1);
    k_gemm128<64, EPI_ADD_RES><<<dim3(EE/64, NROWS/128), 256>>>(
        h_init, W_init, px, EE, EE, b_init, nullptr, 0, ph1);
    k_ln_affine<<<NROWS, 256>>>(px, g_init, bt_init, out);
}

// round 8
// speedup vs baseline: 2.9522x; 1.2342x over previous
#include <cuda_runtime.h>
#include <math.h>

// ---- problem constants ----
#define BB 8
#define LL 512
#define EE 256
#define HH 8
#define HD 32
#define BD_ 64
#define TD_ 256
#define TE_ 128
#define ED_ 64
#define MM_ 512
#define NROWS (BB*LL)          // 4096 token rows

typedef unsigned long long u64;

// ---- packed fp32x2 helpers (Blackwell f32x2 pipe; exact fp32 semantics) ----
__device__ __forceinline__ u64 pk2(float x, float y) {
    u64 r; asm("mov.b64 %0,{%1,%2};" : "=l"(r) : "f"(x), "f"(y)); return r;
}
__device__ __forceinline__ void fma2(u64& d, u64 a, u64 b) {
    asm("fma.rn.f32x2 %0,%1,%2,%0;" : "+l"(d) : "l"(a), "l"(b));
}
__device__ __forceinline__ void mul2(u64& d, u64 f) {
    asm("mul.rn.f32x2 %0,%0,%1;" : "+l"(d) : "l"(f));
}
__device__ __forceinline__ void unpk2(u64 v, float& x, float& y) {
    asm("mov.b64 {%0,%1},%2;" : "=f"(x), "=f"(y) : "l"(v));
}

// ---- scratch (device globals; no runtime allocation) ----
__device__ float g_u[NROWS*TD_];                       // silu(s)         4 MB
__device__ float g_m[NROWS*6*EE];                      // modulations    25 MB
__device__ float g_x[NROWS*EE];                        // staging         4 MB
__device__ float g_bias[(size_t)BB*HH*LL*LL];          // attn bias      64 MB
__device__ float g_qkv[NROWS*3*EE];                    // qkv            12 MB
__device__ float g_o[NROWS*EE];                        // attn out        4 MB
__device__ float g_h1[NROWS*EE];                       // residual 1      4 MB
__device__ float g_t1[NROWS*MM_];                      // mlp hidden      8 MB
__device__ float g_h2[NROWS*EE];                       // residual 2      4 MB

// =====================================================================
// GEMM body: C[M,N] = A[M,K] @ B[N,K]^T  (+ epilogues)
// BM=128, BN in {128,64}, BK=16, 256 threads, 8x(BN/16) per-thread tile,
// double-buffered dynamic smem, packed f32x2 FMA inner loop.
// =====================================================================
#define EPI_BIAS     0
#define EPI_SILU     1
#define EPI_GATE_RES 2
#define EPI_ADD_RES  3
#define EPI_ADD_SILU 4

template<int BN, int EPI>
__device__ __forceinline__ void gemm_body(
    float* dsm, int bm, int bn,
    const float* __restrict__ A, const float* __restrict__ B, float* __restrict__ C,
    int Nd, int Kd,
    const float* __restrict__ bias,
    const float* __restrict__ gate, int goff,
    const float* __restrict__ res)
{
    constexpr int TN = BN/16;            // 8 or 4
    constexpr int TN2 = TN/2;            // 4 or 2
    float* AsP = dsm;                    // [2][16][128]
    float* BsP = dsm + 2*16*128;         // [2][16][BN]

    int tid = threadIdx.x;

    // global load mapping
    int ar = tid >> 1, ak = (tid & 1)*8;
    int br, bk;
    if (BN == 128) { br = tid >> 1; bk = (tid & 1)*8; }
    else           { br = tid >> 2; bk = (tid & 3)*4; }

    const float* Aptr = A + (size_t)(bm + ar)*Kd + ak;
    const float* Bptr = B + (size_t)(bn + br)*Kd + bk;

    float4 ra0, ra1, rb0, rb1;

    // microtile mapping
    int wid = tid >> 5, lane = tid & 31;
    int row0 = (wid & 1)*64 + (lane & 7)*8;
    int col0 = (wid >> 1)*(BN/4) + (lane >> 3)*TN;

    u64 acc2[8][TN2];
    #pragma unroll
    for (int i = 0; i < 8; i++)
        #pragma unroll
        for (int j = 0; j < TN2; j++) acc2[i][j] = 0;

    // prologue: load tile 0
    ra0 = *(const float4*)(Aptr);
    ra1 = *(const float4*)(Aptr + 4);
    rb0 = *(const float4*)(Bptr);
    if (BN == 128) rb1 = *(const float4*)(Bptr + 4);

    AsP[(ak+0)*128+ar]=ra0.x; AsP[(ak+1)*128+ar]=ra0.y; AsP[(ak+2)*128+ar]=ra0.z; AsP[(ak+3)*128+ar]=ra0.w;
    AsP[(ak+4)*128+ar]=ra1.x; AsP[(ak+5)*128+ar]=ra1.y; AsP[(ak+6)*128+ar]=ra1.z; AsP[(ak+7)*128+ar]=ra1.w;
    BsP[(bk+0)*BN+br]=rb0.x; BsP[(bk+1)*BN+br]=rb0.y; BsP[(bk+2)*BN+br]=rb0.z; BsP[(bk+3)*BN+br]=rb0.w;
    if (BN == 128) {
        BsP[(bk+4)*BN+br]=rb1.x; BsP[(bk+5)*BN+br]=rb1.y; BsP[(bk+6)*BN+br]=rb1.z; BsP[(bk+7)*BN+br]=rb1.w;
    }
    __syncthreads();

    int buf = 0;
    for (int k0 = 0; k0 < Kd; k0 += 16) {
        bool last = (k0 + 16 >= Kd);
        if (!last) {
            ra0 = *(const float4*)(Aptr + k0 + 16);
            ra1 = *(const float4*)(Aptr + k0 + 20);
            rb0 = *(const float4*)(Bptr + k0 + 16);
            if (BN == 128) rb1 = *(const float4*)(Bptr + k0 + 20);
        }
        const float* Ab = AsP + buf*2048;
        const float* Bb = BsP + buf*16*BN;
        #pragma unroll
        for (int kk = 0; kk < 16; kk++) {
            float af[8];
            *(float4*)&af[0] = *(const float4*)&Ab[kk*128 + row0];
            *(float4*)&af[4] = *(const float4*)&Ab[kk*128 + row0+4];
            u64 bv[TN2];
            {
                float4 b4a = *(const float4*)&Bb[kk*BN + col0];
                bv[0] = ((const u64*)&b4a)[0];
                bv[1] = ((const u64*)&b4a)[1];
                if (TN == 8) {
                    float4 b4b = *(const float4*)&Bb[kk*BN + col0+4];
                    bv[2] = ((const u64*)&b4b)[0];
                    bv[3] = ((const u64*)&b4b)[1];
                }
            }
            #pragma unroll
            for (int i = 0; i < 8; i++) {
                u64 ad = pk2(af[i], af[i]);
                #pragma unroll
                for (int j = 0; j < TN2; j++)
                    fma2(acc2[i][j], ad, bv[j]);
            }
        }
        if (!last) {
            int nb = buf ^ 1;
            float* An = AsP + nb*2048;
            float* Bn = BsP + nb*16*BN;
            An[(ak+0)*128+ar]=ra0.x; An[(ak+1)*128+ar]=ra0.y; An[(ak+2)*128+ar]=ra0.z; An[(ak+3)*128+ar]=ra0.w;
            An[(ak+4)*128+ar]=ra1.x; An[(ak+5)*128+ar]=ra1.y; An[(ak+6)*128+ar]=ra1.z; An[(ak+7)*128+ar]=ra1.w;
            Bn[(bk+0)*BN+br]=rb0.x; Bn[(bk+1)*BN+br]=rb0.y; Bn[(bk+2)*BN+br]=rb0.z; Bn[(bk+3)*BN+br]=rb0.w;
            if (BN == 128) {
                Bn[(bk+4)*BN+br]=rb1.x; Bn[(bk+5)*BN+br]=rb1.y; Bn[(bk+6)*BN+br]=rb1.z; Bn[(bk+7)*BN+br]=rb1.w;
            }
            __syncthreads();
            buf = nb;
        }
    }

    // epilogue (unpack, then fused op)
    #pragma unroll
    for (int i = 0; i < 8; i++) {
        int m = bm + row0 + i;
        float accf[TN];
        #pragma unroll
        for (int j = 0; j < TN2; j++) unpk2(acc2[i][j], accf[2*j], accf[2*j+1]);
        #pragma unroll
        for (int j4 = 0; j4 < TN; j4 += 4) {
            float4 v;
            float vv[4];
            #pragma unroll
            for (int u = 0; u < 4; u++) {
                int n = bn + col0 + j4 + u;
                float x = accf[j4+u] + bias[n];
                if (EPI == EPI_SILU)     x = x / (1.f + __expf(-x));
                if (EPI == EPI_GATE_RES) x = x*gate[(size_t)m*(6*EE) + goff + n] + res[(size_t)m*Nd + n];
                if (EPI == EPI_ADD_RES)  x = x + res[(size_t)m*Nd + n];
                if (EPI == EPI_ADD_SILU) { x = x + res[(size_t)m*Nd + n]; x = x / (1.f + __expf(-x)); }
                vv[u] = x;
            }
            v.x = vv[0]; v.y = vv[1]; v.z = vv[2]; v.w = vv[3];
            *(float4*)&C[(size_t)m*Nd + bn + col0 + j4] = v;
        }
    }
}

// plain GEMM kernel (dynamic smem = (4096 + 2*16*BN)*4 bytes)
template<int BN, int EPI>
__global__ void __launch_bounds__(256, 2) k_gemmD(
    const float* __restrict__ A, const float* __restrict__ B, float* __restrict__ C,
    int Nd, int Kd,
    const float* __restrict__ bias,
    const float* __restrict__ gate, int goff,
    const float* __restrict__ res)
{
    extern __shared__ float dsm[];
    gemm_body<BN, EPI>(dsm, blockIdx.y*128, blockIdx.x*BN,
                       A, B, C, Nd, Kd, bias, gate, goff, res);
}

// =====================================================================
// bias body: bias[b,h,l,m] = (LN(p[b,l,m,:])*g_eln + b_eln) @ W_e^T + b_e
// One block = one (b,l): 512 m-rows in 2 chunks of 256 rows staged in a
// 64KB XOR-swizzled buffer (conflict-free LDS.128); LN folded into GEMV.
// smem: 256*64 staging + 512 sW + 8 + 8  => 67648 B
// =====================================================================
#define FAT_SMEM ((256*64 + 512 + 16)*4)
__device__ __forceinline__ void bias_body(
        float* sm, int blk,
        const float* __restrict__ p, const float* __restrict__ g_eln,
        const float* __restrict__ b_eln, const float* __restrict__ W_e,
        const float* __restrict__ b_e)
{
    float* sW   = sm + 256*64;           // [8][64]  (W' = g*W)
    float* scs  = sW + 512;              // [8] column sums of W'
    float* sct  = scs + 8;               // [8] constants
    int tid = threadIdx.x;

    for (int i = tid; i < 512; i += 256) sW[i] = g_eln[i & 63]*W_e[i];
    if (tid < 8) {
        float ct = 0.f;
        for (int k = 0; k < 64; k++) ct += b_eln[k]*W_e[tid*64 + k];
        sct[tid] = ct + b_e[tid];
    }
    __syncthreads();
    if (tid < 8) {
        float cs = 0.f;
        for (int k = 0; k < 64; k++) cs += sW[tid*64 + k];
        scs[tid] = cs;
    }

    int b = blk >> 9, l = blk & 511;
    const float4* src = (const float4*)(p + (size_t)blk*512*64);
    u64 one2 = pk2(1.f, 1.f);
    int swz = tid & 15;

    for (int ch = 0; ch < 2; ch++) {
        __syncthreads();       // buffer reuse (also publishes scs on ch=0)
        #pragma unroll
        for (int j = 0; j < 16; j++) {
            float4 v = src[ch*4096 + j*256 + tid];
            int lin = j*256 + tid;
            int r = lin >> 4, c = lin & 15;
            *(float4*)&sm[r*64 + ((c ^ (r & 15)) << 2)] = v;
        }
        __syncthreads();

        const float* base = sm + tid*64;
        u64 P2[8] = {};
        u64 s2 = 0, q2 = 0;
        #pragma unroll
        for (int c = 0; c < 16; c++) {
            float4 a4 = *(const float4*)&base[(c ^ swz) << 2];
            u64 a01 = ((const u64*)&a4)[0];
            u64 a23 = ((const u64*)&a4)[1];
            fma2(s2, a01, one2); fma2(s2, a23, one2);
            fma2(q2, a01, a01);  fma2(q2, a23, a23);
            #pragma unroll
            for (int hh = 0; hh < 8; hh++) {
                float4 w4 = *(const float4*)&sW[hh*64 + c*4];   // broadcast
                u64 w01 = ((const u64*)&w4)[0];
                u64 w23 = ((const u64*)&w4)[1];
                fma2(P2[hh], a01, w01);
                fma2(P2[hh], a23, w23);
            }
        }
        float sx, sy, qx, qy;
        unpk2(s2, sx, sy); unpk2(q2, qx, qy);
        float s = sx + sy, q = qx + qy;
        float mu = s*(1.f/64.f);
        float var = q*(1.f/64.f) - mu*mu;
        float rstd = rsqrtf(var + 1e-5f);

        int m = ch*256 + tid;
        #pragma unroll
        for (int hh = 0; hh < 8; hh++) {
            float px, py;
            unpk2(P2[hh], px, py);
            float o = rstd*((px + py) - mu*scs[hh]) + sct[hh];
            g_bias[(((size_t)b*HH + hh)*LL + l)*LL + m] = o;
        }
    }
}

// =====================================================================
// FAT kernel: gemm blocks (BN=128) + bias blocks in ONE launch.
// Overlaps the DRAM-bound bias with the issue-bound GEMM chain.
// =====================================================================
template<int EPI>
__global__ void __launch_bounds__(256, 2) k_fat(
    int nTilesX, int gemmBlocks,
    const float* __restrict__ A, const float* __restrict__ B, float* __restrict__ C,
    int Nd, int Kd,
    const float* __restrict__ bias,
    const float* __restrict__ gate, int goff,
    const float* __restrict__ res,
    const float* __restrict__ p, const float* __restrict__ g_eln,
    const float* __restrict__ b_eln, const float* __restrict__ W_e,
    const float* __restrict__ b_e, int biasOffset)
{
    extern __shared__ float dsm[];
    int bid = blockIdx.x;
    if (bid < gemmBlocks) {
        gemm_body<128, EPI>(dsm, (bid/nTilesX)*128, (bid % nTilesX)*128,
                            A, B, C, Nd, Kd, bias, gate, goff, res);
    } else {
        bias_body(dsm, biasOffset + bid - gemmBlocks, p, g_eln, b_eln, W_e, b_e);
    }
}

// =====================================================================
// k_xmod: dst = LN(src_row)*(1 + m[:,sc]) + m[:,sh]    (row = 256 wide)
// =====================================================================
__global__ void k_xmod(const float* __restrict__ src, int sh_off, int sc_off,
                       float* __restrict__ dst)
{
    int row = blockIdx.x, t = threadIdx.x;
    float v = src[(size_t)row*EE + t];
    __shared__ float s1[8], s2[8], bc[2];
    float a = v, b = v*v;
    #pragma unroll
    for (int o = 16; o > 0; o >>= 1) {
        a += __shfl_xor_sync(0xffffffffu, a, o);
        b += __shfl_xor_sync(0xffffffffu, b, o);
    }
    if ((t & 31) == 0) { s1[t>>5] = a; s2[t>>5] = b; }
    __syncthreads();
    if (t == 0) {
        float x = 0, y = 0;
        for (int i = 0; i < 8; i++) { x += s1[i]; y += s2[i]; }
        bc[0] = x*(1.f/EE); bc[1] = y*(1.f/EE);
    }
    __syncthreads();
    float mu = bc[0], var = bc[1] - mu*mu;
    float n = (v - mu)*rsqrtf(var + 1e-5f);
    const float* mrow = g_m + (size_t)row*(6*EE);
    dst[(size_t)row*EE + t] = n*(1.f + mrow[sc_off + t]) + mrow[sh_off + t];
}

// =====================================================================
// k_ln_affine: dst = LN(src_row)*g + bt
// =====================================================================
__global__ void k_ln_affine(const float* __restrict__ src, const float* __restrict__ g,
                            const float* __restrict__ bt, float* __restrict__ dst)
{
    int row = blockIdx.x, t = threadIdx.x;
    float v = src[(size_t)row*EE + t];
    __shared__ float s1[8], s2[8], bc[2];
    float a = v, b = v*v;
    #pragma unroll
    for (int o = 16; o > 0; o >>= 1) {
        a += __shfl_xor_sync(0xffffffffu, a, o);
        b += __shfl_xor_sync(0xffffffffu, b, o);
    }
    if ((t & 31) == 0) { s1[t>>5] = a; s2[t>>5] = b; }
    __syncthreads();
    if (t == 0) {
        float x = 0, y = 0;
        for (int i = 0; i < 8; i++) { x += s1[i]; y += s2[i]; }
        bc[0] = x*(1.f/EE); bc[1] = y*(1.f/EE);
    }
    __syncthreads();
    float mu = bc[0], var = bc[1] - mu*mu;
    float n = (v - mu)*rsqrtf(var + 1e-5f);
    dst[(size_t)row*EE + t] = n*g[t] + bt[t];
}

// =====================================================================
// k_attn: fused flash attention per (b,h,l-tile of 64), f32x2 FMA
// =====================================================================
__global__ void __launch_bounds__(256) k_attn()
{
    __shared__ __align__(16) float Qs[HD][64];
    __shared__ __align__(16) float Ks[HD][64];
    __shared__ __align__(16) float Vs[64][HD];
    __shared__ __align__(16) float Ps[64][68];       // pad 68: 16B-aligned rows
    __shared__ float m_run[64], l_run[64], scl[64];

    int bh = blockIdx.y;
    int b = bh >> 3, h = bh & 7;
    int l0 = blockIdx.x*64;
    int tid = threadIdx.x;

    {   // load Q tile, transposed [d][l]
        int r = tid >> 2, c = (tid & 3)*8;
        const float* q = g_qkv + (size_t)(b*LL + l0 + r)*768 + h*HD + c;
        float4 v0 = *(const float4*)q, v1 = *(const float4*)(q+4);
        Qs[c+0][r]=v0.x; Qs[c+1][r]=v0.y; Qs[c+2][r]=v0.z; Qs[c+3][r]=v0.w;
        Qs[c+4][r]=v1.x; Qs[c+5][r]=v1.y; Qs[c+6][r]=v1.z; Qs[c+7][r]=v1.w;
    }
    if (tid < 64) { m_run[tid] = -1e30f; l_run[tid] = 0.f; }

    int tx = tid & 15, ty = tid >> 4;
    int tx2 = tid & 7, ty2 = tid >> 3;
    u64 o2[2][2] = {};                     // packed output accumulators
    const float sc = 0.17677669529663687f; // 1/sqrt(32)

    for (int m0 = 0; m0 < LL; m0 += 64) {
        __syncthreads();
        {   // load K (transposed) + V tiles
            int r = tid >> 2, c = (tid & 3)*8;
            const float* kp = g_qkv + (size_t)(b*LL + m0 + r)*768 + 256 + h*HD + c;
            float4 v0 = *(const float4*)kp, v1 = *(const float4*)(kp+4);
            Ks[c+0][r]=v0.x; Ks[c+1][r]=v0.y; Ks[c+2][r]=v0.z; Ks[c+3][r]=v0.w;
            Ks[c+4][r]=v1.x; Ks[c+5][r]=v1.y; Ks[c+6][r]=v1.z; Ks[c+7][r]=v1.w;
            const float* vp = g_qkv + (size_t)(b*LL + m0 + r)*768 + 512 + h*HD + c;
            *(float4*)&Vs[r][c]   = *(const float4*)vp;
            *(float4*)&Vs[r][c+4] = *(const float4*)(vp+4);
        }
        __syncthreads();

        // --- S tile: QK (f32x2) + bias ---
        float s[4][4];
        {
            u64 qk2[4][2] = {};
            #pragma unroll
            for (int d = 0; d < HD; d++) {
                float4 qa = *(const float4*)&Qs[d][ty*4];
                float4 kb = *(const float4*)&Ks[d][tx*4];
                u64 k01 = ((const u64*)&kb)[0];
                u64 k23 = ((const u64*)&kb)[1];
                float qv[4] = {qa.x, qa.y, qa.z, qa.w};
                #pragma unroll
                for (int i = 0; i < 4; i++) {
                    u64 qd = pk2(qv[i], qv[i]);
                    fma2(qk2[i][0], qd, k01);
                    fma2(qk2[i][1], qd, k23);
                }
            }
            const float* bptr = g_bias + ((size_t)((b*HH + h)*LL + l0 + ty*4))*LL + m0 + tx*4;
            #pragma unroll
            for (int i = 0; i < 4; i++) {
                float q0, q1, q2v, q3;
                unpk2(qk2[i][0], q0, q1);
                unpk2(qk2[i][1], q2v, q3);
                float4 bb = *(const float4*)(bptr + (size_t)i*LL);
                s[i][0] = q0*sc + bb.x;
                s[i][1] = q1*sc + bb.y;
                s[i][2] = q2v*sc + bb.z;
                s[i][3] = q3*sc + bb.w;
            }
        }

        // --- online softmax (per row, reduced over 16-lane tx group) ---
        #pragma unroll
        for (int i = 0; i < 4; i++) {
            int row = ty*4 + i;
            float rm = fmaxf(fmaxf(s[i][0], s[i][1]), fmaxf(s[i][2], s[i][3]));
            #pragma unroll
            for (int o = 8; o > 0; o >>= 1)
                rm = fmaxf(rm, __shfl_xor_sync(0xffffffffu, rm, o));
            float mold = m_run[row];
            float mnew = fmaxf(mold, rm);
            float p0 = __expf(s[i][0] - mnew);
            float p1 = __expf(s[i][1] - mnew);
            float p2 = __expf(s[i][2] - mnew);
            float p3 = __expf(s[i][3] - mnew);
            float rs = p0 + p1 + p2 + p3;
            #pragma unroll
            for (int o = 8; o > 0; o >>= 1)
                rs += __shfl_xor_sync(0xffffffffu, rs, o);
            if (tx == 0) {
                float f = __expf(mold - mnew);
                m_run[row] = mnew;
                l_run[row] = l_run[row]*f + rs;
                scl[row] = f;
            }
            float4 pv4; pv4.x = p0; pv4.y = p1; pv4.z = p2; pv4.w = p3;
            *(float4*)&Ps[row][tx*4] = pv4;
        }
        __syncthreads();

        // --- PV accumulate with running rescale (f32x2) ---
        {
            int r0 = ty2*2;
            u64 f0d = pk2(scl[r0],   scl[r0]);
            u64 f1d = pk2(scl[r0+1], scl[r0+1]);
            mul2(o2[0][0], f0d); mul2(o2[0][1], f0d);
            mul2(o2[1][0], f1d); mul2(o2[1][1], f1d);
            #pragma unroll
            for (int kk = 0; kk < 64; kk += 4) {
                float4 pa4 = *(const float4*)&Ps[r0][kk];
                float4 pb4 = *(const float4*)&Ps[r0+1][kk];
                float pa[4] = {pa4.x, pa4.y, pa4.z, pa4.w};
                float pb[4] = {pb4.x, pb4.y, pb4.z, pb4.w};
                #pragma unroll
                for (int u = 0; u < 4; u++) {
                    float4 vv = *(const float4*)&Vs[kk+u][tx2*4];
                    u64 v01 = ((const u64*)&vv)[0];
                    u64 v23 = ((const u64*)&vv)[1];
                    u64 pad = pk2(pa[u], pa[u]);
                    u64 pbd = pk2(pb[u], pb[u]);
                    fma2(o2[0][0], pad, v01); fma2(o2[0][1], pad, v23);
                    fma2(o2[1][0], pbd, v01); fma2(o2[1][1], pbd, v23);
                }
            }
        }
    }

    // finalize
    int r0 = ty2*2;
    float inv0 = 1.f/l_run[r0], inv1 = 1.f/l_run[r0+1];
    float4 o0, o1;
    unpk2(o2[0][0], o0.x, o0.y); unpk2(o2[0][1], o0.z, o0.w);
    unpk2(o2[1][0], o1.x, o1.y); unpk2(o2[1][1], o1.z, o1.w);
    o0.x *= inv0; o0.y *= inv0; o0.z *= inv0; o0.w *= inv0;
    o1.x *= inv1; o1.y *= inv1; o1.z *= inv1; o1.w *= inv1;
    *(float4*)&g_o[(size_t)(b*LL + l0 + r0    )*EE + h*HD + tx2*4] = o0;
    *(float4*)&g_o[(size_t)(b*LL + l0 + r0 + 1)*EE + h*HD + tx2*4] = o1;
}

// =====================================================================
// launch
// =====================================================================
extern "C" void kernel_launch(void* const* d_in, const int* in_sizes, int n_in,
                              void* d_out, int out_size)
{
    const float* h      = (const float*)d_in[0];
    const float* h_init = (const float*)d_in[1];
    const float* s_a    = (const float*)d_in[2];
    const float* s_t    = (const float*)d_in[3];
    const float* s_tem  = (const float*)d_in[4];
    const float* p      = (const float*)d_in[5];
    const float* W_bp   = (const float*)d_in[6];
    const float* b_bp   = (const float*)d_in[7];
    const float* W_ada  = (const float*)d_in[8];
    const float* b_ada  = (const float*)d_in[9];
    const float* g_eln  = (const float*)d_in[10];
    const float* b_eln  = (const float*)d_in[11];
    const float* W_e    = (const float*)d_in[12];
    const float* b_e    = (const float*)d_in[13];
    const float* W_in   = (const float*)d_in[14];
    const float* b_in   = (const float*)d_in[15];
    const float* W_out  = (const float*)d_in[16];
    const float* b_out  = (const float*)d_in[17];
    const float* W1     = (const float*)d_in[18];
    const float* b1     = (const float*)d_in[19];
    const float* W2     = (const float*)d_in[20];
    const float* b2     = (const float*)d_in[21];
    const float* W_tem  = (const float*)d_in[22];
    const float* b_tem  = (const float*)d_in[23];
    const float* g_tem  = (const float*)d_in[24];
    const float* bt_tem = (const float*)d_in[25];
    const float* W_init = (const float*)d_in[26];
    const float* b_init = (const float*)d_in[27];
    const float* g_init = (const float*)d_in[28];
    const float* bt_init= (const float*)d_in[29];
    float* out = (float*)d_out;

    float *pu, *pm, *px, *pqkv, *po, *ph1, *pt1, *ph2;
    cudaGetSymbolAddress((void**)&pu,   g_u);
    cudaGetSymbolAddress((void**)&pm,   g_m);
    cudaGetSymbolAddress((void**)&px,   g_x);
    cudaGetSymbolAddress((void**)&pqkv, g_qkv);
    cudaGetSymbolAddress((void**)&po,   g_o);
    cudaGetSymbolAddress((void**)&ph1,  g_h1);
    cudaGetSymbolAddress((void**)&pt1,  g_t1);
    cudaGetSymbolAddress((void**)&ph2,  g_h2);

    cudaFuncSetAttribute(k_fat<EPI_ADD_SILU>, cudaFuncAttributeMaxDynamicSharedMemorySize, FAT_SMEM);
    cudaFuncSetAttribute(k_fat<EPI_BIAS>,     cudaFuncAttributeMaxDynamicSharedMemorySize, FAT_SMEM);

    const int SM128 = (4096 + 2*16*128)*4;   // 32 KB
    const int SM64  = (4096 + 2*16*64)*4;    // 24 KB

    // bias block split across the three fat launches (total 4096)
    const int B1 = 320, B2 = 2240, B3 = 4096 - B1 - B2;

    // 1) cond1 GEMM (u = silu(s_a@W_bp^T + b_bp + s_t)) + bias part 1
    k_fat<EPI_ADD_SILU><<<2*32 + B1, 256, FAT_SMEM>>>(
        2, 2*32, s_a, W_bp, pu, TD_, BD_, b_bp, nullptr, 0, s_t,
        p, g_eln, b_eln, W_e, b_e, 0);

    // 2) ada GEMM + bias part 2
    k_fat<EPI_BIAS><<<12*32 + B2, 256, FAT_SMEM>>>(
        12, 12*32, pu, W_ada, pm, 6*EE, TD_, b_ada, nullptr, 0, nullptr,
        p, g_eln, b_eln, W_e, b_e, B1);

    // 3) attention branch
    k_xmod<<<NROWS, 256>>>(h, 0, EE, px);
    k_fat<EPI_BIAS><<<6*32 + B3, 256, FAT_SMEM>>>(       // qkv GEMM + bias part 3
        6, 6*32, px, W_in, pqkv, 3*EE, EE, b_in, nullptr, 0, nullptr,
        p, g_eln, b_eln, W_e, b_e, B1 + B2);
    k_attn<<<dim3(LL/64, BB*HH), 256>>>();
    k_gemmD<64, EPI_GATE_RES><<<dim3(EE/64, NROWS/128), 256, SM64>>>(
        po, W_out, ph1, EE, EE, b_out, pm, 2*EE, h);

    // 4) MLP branch
    k_xmod<<<NROWS, 256>>>(ph1, 3*EE, 4*EE, px);
    k_gemmD<128, EPI_SILU><<<dim3(MM_/128, NROWS/128), 256, SM128>>>(
        px, W1, pt1, MM_, EE, b1, nullptr, 0, nullptr);
    k_gemmD<64, EPI_GATE_RES><<<dim3(EE/64, NROWS/128), 256, SM64>>>(
        pt1, W2, ph2, EE, MM_, b2, pm, 5*EE, ph1);

    // 5) trailing conditioning LayerNorms
    k_gemmD<64, EPI_ADD_RES><<<dim3(EE/64, NROWS/128), 256, SM64>>>(
        s_tem, W_tem, px, EE, TE_, b_tem, nullptr, 0, ph2);
    k_ln_affine<<<NROWS, 256>>>(px, g_tem, bt_tem, ph1);
    k_gemmD<64, EPI_ADD_RES><<<dim3(EE/64, NROWS/128), 256, SM64>>>(
        h_init, W_init, px, EE, EE, b_init, nullptr, 0, ph1);
    k_ln_affine<<<NROWS, 256>>>(px, g_init, bt_init, out);
}

// round 10
// speedup vs baseline: 4.0637x; 1.3765x over previous
#include <cuda_runtime.h>
#include <cuda_bf16.h>
#include <math.h>
#include <stdint.h>

// ---- problem constants ----
#define BB 8
#define LL 512
#define EE 256
#define HH 8
#define HD 32
#define BD_ 64
#define TD_ 256
#define TE_ 128
#define ED_ 64
#define MM_ 512
#define NROWS (BB*LL)          // 4096 token rows

typedef unsigned long long u64;

// ---- packed fp32x2 helpers ----
__device__ __forceinline__ u64 pk2(float x, float y) {
    u64 r; asm("mov.b64 %0,{%1,%2};" : "=l"(r) : "f"(x), "f"(y)); return r;
}
__device__ __forceinline__ void fma2(u64& d, u64 a, u64 b) {
    asm("fma.rn.f32x2 %0,%1,%2,%0;" : "+l"(d) : "l"(a), "l"(b));
}
__device__ __forceinline__ void mul2(u64& d, u64 f) {
    asm("mul.rn.f32x2 %0,%0,%1;" : "+l"(d) : "l"(f));
}
__device__ __forceinline__ void unpk2(u64 v, float& x, float& y) {
    asm("mov.b64 {%0,%1},%2;" : "=f"(x), "=f"(y) : "l"(v));
}

// ---- HMMA helpers (baseline PTX; valid on compute_103) ----
__device__ __forceinline__ uint32_t smem_u32(const void* p) {
    uint32_t a;
    asm("{ .reg .u64 t; cvta.to.shared.u64 t, %1; cvt.u32.u64 %0, t; }" : "=r"(a) : "l"(p));
    return a;
}
__device__ __forceinline__ void ldsm4(uint32_t& r0, uint32_t& r1, uint32_t& r2, uint32_t& r3,
                                      uint32_t addr) {
    asm volatile("ldmatrix.sync.aligned.m8n8.x4.shared.b16 {%0,%1,%2,%3},[%4];"
                 : "=r"(r0), "=r"(r1), "=r"(r2), "=r"(r3) : "r"(addr));
}
__device__ __forceinline__ void mma16816(float* d, const uint32_t* a, const uint32_t* b) {
    asm volatile(
        "mma.sync.aligned.m16n8k16.row.col.f32.bf16.bf16.f32 "
        "{%0,%1,%2,%3},{%4,%5,%6,%7},{%8,%9},{%0,%1,%2,%3};"
        : "+f"(d[0]), "+f"(d[1]), "+f"(d[2]), "+f"(d[3])
        : "r"(a[0]), "r"(a[1]), "r"(a[2]), "r"(a[3]), "r"(b[0]), "r"(b[1]));
}

// split fp32 -> bf16 hi + bf16 lo (residual), packed as bf16x2 pairs
__device__ __forceinline__ void split4(float4 v, uint2& hi, uint2& lo) {
    __nv_bfloat162 h01 = __float22bfloat162_rn(make_float2(v.x, v.y));
    __nv_bfloat162 h23 = __float22bfloat162_rn(make_float2(v.z, v.w));
    float2 f01 = __bfloat1622float2(h01);
    float2 f23 = __bfloat1622float2(h23);
    __nv_bfloat162 l01 = __float22bfloat162_rn(make_float2(v.x - f01.x, v.y - f01.y));
    __nv_bfloat162 l23 = __float22bfloat162_rn(make_float2(v.z - f23.x, v.w - f23.y));
    hi.x = *(uint32_t*)&h01; hi.y = *(uint32_t*)&h23;
    lo.x = *(uint32_t*)&l01; lo.y = *(uint32_t*)&l23;
}

// ---- scratch ----
__device__ float g_u[NROWS*TD_];
__device__ float g_m[NROWS*6*EE];
__device__ float g_x[NROWS*EE];
__device__ float g_bias[(size_t)BB*HH*LL*LL];
__device__ float g_qkv[NROWS*3*EE];
__device__ float g_o[NROWS*EE];
__device__ float g_h1[NROWS*EE];
__device__ float g_t1[NROWS*MM_];
__device__ float g_h2[NROWS*EE];

#define EPI_BIAS     0
#define EPI_SILU     1
#define EPI_GATE_RES 2
#define EPI_ADD_RES  3
#define EPI_ADD_SILU 4

// =====================================================================
// HMMA GEMM body: C[M,N] = A[M,K] @ B[N,K]^T (+ epilogue)
// BM=128, BN=64, K-chunks of 64; split-bf16 (3 passes); 256 threads.
// Warps 4(M) x 2(N): each warp owns a 32x32 C tile in registers.
// smem (bf16, XOR-swizzled 16B chunks):
//   A_hi 16KB @0, A_lo 16KB @16384, B_hi 8KB @32768, B_lo 8KB @40960
// =====================================================================
#define OFF_AHI 0
#define OFF_ALO 16384
#define OFF_BHI 32768
#define OFF_BLO 40960
#define GEMM_SMEM 49152

template<int EPI>
__device__ __forceinline__ void hmma_gemm_body(
    char* sm, int bm, int bn,
    const float* __restrict__ A, const float* __restrict__ B, float* __restrict__ C,
    int Nd, int Kd,
    const float* __restrict__ bias,
    const float* __restrict__ gate, int goff,
    const float* __restrict__ res)
{
    uint32_t sb = smem_u32(sm);
    int tid = threadIdx.x, wid = tid >> 5, lane = tid & 31;
    int wm = (wid & 3)*32, wn = (wid >> 2)*32;

    float acc[2][4][4];
    #pragma unroll
    for (int mi = 0; mi < 2; mi++)
        #pragma unroll
        for (int ni = 0; ni < 4; ni++)
            #pragma unroll
            for (int c = 0; c < 4; c++) acc[mi][ni][c] = 0.f;

    // ldmatrix per-thread address components (logical, pre-swizzle)
    int arow = (lane & 15);                 // + wm + mi*16
    int acol = (lane >> 4);                 // + ks*2  (16B chunk idx)
    int brow = (lane & 7) + ((lane >> 4) << 3);   // + wn + nh*16
    int bcol = (lane >> 3) & 1;             // + ks*2

    int nch = Kd >> 6;
    for (int ch = 0; ch < nch; ch++) {
        __syncthreads();     // buffer reuse
        // stage A: 128 rows x 64 f32 -> split bf16 (8B groups, swizzled)
        const float* Ab = A + (size_t)bm*Kd + ch*64;
        #pragma unroll
        for (int i = 0; i < 8; i++) {
            int idx = tid + i*256;
            int r = idx >> 4, c4 = idx & 15;
            float4 v = *(const float4*)(Ab + (size_t)r*Kd + c4*4);
            uint2 hi, lo; split4(v, hi, lo);
            uint32_t off = (uint32_t)(r*128 + c4*8);
            uint32_t sw = off ^ (((uint32_t)(r & 7)) << 4);
            *(uint2*)(sm + OFF_AHI + sw) = hi;
            *(uint2*)(sm + OFF_ALO + sw) = lo;
        }
        // stage B: 64 rows x 64
        const float* Bb = B + (size_t)bn*Kd + ch*64;
        #pragma unroll
        for (int i = 0; i < 4; i++) {
            int idx = tid + i*256;
            int r = idx >> 4, c4 = idx & 15;
            float4 v = *(const float4*)(Bb + (size_t)r*Kd + c4*4);
            uint2 hi, lo; split4(v, hi, lo);
            uint32_t off = (uint32_t)(r*128 + c4*8);
            uint32_t sw = off ^ (((uint32_t)(r & 7)) << 4);
            *(uint2*)(sm + OFF_BHI + sw) = hi;
            *(uint2*)(sm + OFF_BLO + sw) = lo;
        }
        __syncthreads();

        #pragma unroll
        for (int ks = 0; ks < 4; ks++) {
            uint32_t ah[2][4], al[2][4], bh[2][4], bl[2][4];
            #pragma unroll
            for (int mi = 0; mi < 2; mi++) {
                int row = wm + mi*16 + arow;
                uint32_t off = (uint32_t)(row*128 + (ks*2 + acol)*16);
                uint32_t sw = off ^ (((uint32_t)(row & 7)) << 4);
                ldsm4(ah[mi][0], ah[mi][1], ah[mi][2], ah[mi][3], sb + OFF_AHI + sw);
                ldsm4(al[mi][0], al[mi][1], al[mi][2], al[mi][3], sb + OFF_ALO + sw);
            }
            #pragma unroll
            for (int nh = 0; nh < 2; nh++) {
                int row = wn + nh*16 + brow;
                uint32_t off = (uint32_t)(row*128 + (ks*2 + bcol)*16);
                uint32_t sw = off ^ (((uint32_t)(row & 7)) << 4);
                ldsm4(bh[nh][0], bh[nh][1], bh[nh][2], bh[nh][3], sb + OFF_BHI + sw);
                ldsm4(bl[nh][0], bl[nh][1], bl[nh][2], bl[nh][3], sb + OFF_BLO + sw);
            }
            #pragma unroll
            for (int mi = 0; mi < 2; mi++)
                #pragma unroll
                for (int ni = 0; ni < 4; ni++) {
                    const uint32_t* bph = &bh[ni >> 1][(ni & 1)*2];
                    const uint32_t* bpl = &bl[ni >> 1][(ni & 1)*2];
                    mma16816(acc[mi][ni], ah[mi], bph);   // Ahi*Bhi
                    mma16816(acc[mi][ni], ah[mi], bpl);   // Ahi*Blo
                    mma16816(acc[mi][ni], al[mi], bph);   // Alo*Bhi
                }
        }
    }

    // epilogue (fragment layout: rows g, g+8; cols 2*tig, 2*tig+1)
    int g = lane >> 2, tig = lane & 3;
    #pragma unroll
    for (int mi = 0; mi < 2; mi++) {
        #pragma unroll
        for (int ni = 0; ni < 4; ni++) {
            int n0 = bn + wn + ni*8 + tig*2;
            float2 b2 = *(const float2*)&bias[n0];
            #pragma unroll
            for (int rh = 0; rh < 2; rh++) {
                int m = bm + wm + mi*16 + g + rh*8;
                float x0 = acc[mi][ni][rh*2 + 0] + b2.x;
                float x1 = acc[mi][ni][rh*2 + 1] + b2.y;
                if (EPI == EPI_SILU) {
                    x0 = x0 / (1.f + __expf(-x0));
                    x1 = x1 / (1.f + __expf(-x1));
                }
                if (EPI == EPI_GATE_RES) {
                    float2 g2 = *(const float2*)&gate[(size_t)m*(6*EE) + goff + n0];
                    float2 r2 = *(const float2*)&res[(size_t)m*Nd + n0];
                    x0 = x0*g2.x + r2.x;
                    x1 = x1*g2.y + r2.y;
                }
                if (EPI == EPI_ADD_RES) {
                    float2 r2 = *(const float2*)&res[(size_t)m*Nd + n0];
                    x0 += r2.x; x1 += r2.y;
                }
                if (EPI == EPI_ADD_SILU) {
                    float2 r2 = *(const float2*)&res[(size_t)m*Nd + n0];
                    x0 += r2.x; x1 += r2.y;
                    x0 = x0 / (1.f + __expf(-x0));
                    x1 = x1 / (1.f + __expf(-x1));
                }
                *(float2*)&C[(size_t)m*Nd + n0] = make_float2(x0, x1);
            }
        }
    }
}

template<int EPI>
__global__ void __launch_bounds__(256) k_gemmH(
    const float* __restrict__ A, const float* __restrict__ B, float* __restrict__ C,
    int Nd, int Kd,
    const float* __restrict__ bias,
    const float* __restrict__ gate, int goff,
    const float* __restrict__ res)
{
    extern __shared__ char smh[];
    hmma_gemm_body<EPI>(smh, blockIdx.y*128, blockIdx.x*64, A, B, C, Nd, Kd, bias, gate, goff, res);
}

// =====================================================================
// bias body (unchanged): one (b,l), 512 rows, 2 chunks, XOR-swizzled
// 64KB staging, LN folded into GEMV.
// =====================================================================
#define FAT_SMEM ((256*64 + 512 + 16)*4)
__device__ __forceinline__ void bias_body(
        float* sm, int blk,
        const float* __restrict__ p, const float* __restrict__ g_eln,
        const float* __restrict__ b_eln, const float* __restrict__ W_e,
        const float* __restrict__ b_e)
{
    float* sW   = sm + 256*64;
    float* scs  = sW + 512;
    float* sct  = scs + 8;
    int tid = threadIdx.x;

    for (int i = tid; i < 512; i += 256) sW[i] = g_eln[i & 63]*W_e[i];
    if (tid < 8) {
        float ct = 0.f;
        for (int k = 0; k < 64; k++) ct += b_eln[k]*W_e[tid*64 + k];
        sct[tid] = ct + b_e[tid];
    }
    __syncthreads();
    if (tid < 8) {
        float cs = 0.f;
        for (int k = 0; k < 64; k++) cs += sW[tid*64 + k];
        scs[tid] = cs;
    }

    int b = blk >> 9, l = blk & 511;
    const float4* src = (const float4*)(p + (size_t)blk*512*64);
    u64 one2 = pk2(1.f, 1.f);
    int swz = tid & 15;

    for (int ch = 0; ch < 2; ch++) {
        __syncthreads();
        #pragma unroll
        for (int j = 0; j < 16; j++) {
            float4 v = src[ch*4096 + j*256 + tid];
            int lin = j*256 + tid;
            int r = lin >> 4, c = lin & 15;
            *(float4*)&sm[r*64 + ((c ^ (r & 15)) << 2)] = v;
        }
        __syncthreads();

        const float* base = sm + tid*64;
        u64 P2[8] = {};
        u64 s2 = 0, q2 = 0;
        #pragma unroll
        for (int c = 0; c < 16; c++) {
            float4 a4 = *(const float4*)&base[(c ^ swz) << 2];
            u64 a01 = ((const u64*)&a4)[0];
            u64 a23 = ((const u64*)&a4)[1];
            fma2(s2, a01, one2); fma2(s2, a23, one2);
            fma2(q2, a01, a01);  fma2(q2, a23, a23);
            #pragma unroll
            for (int hh = 0; hh < 8; hh++) {
                float4 w4 = *(const float4*)&sW[hh*64 + c*4];
                fma2(P2[hh], a01, ((const u64*)&w4)[0]);
                fma2(P2[hh], a23, ((const u64*)&w4)[1]);
            }
        }
        float sx, sy, qx, qy;
        unpk2(s2, sx, sy); unpk2(q2, qx, qy);
        float s = sx + sy, q = qx + qy;
        float mu = s*(1.f/64.f);
        float var = q*(1.f/64.f) - mu*mu;
        float rstd = rsqrtf(var + 1e-5f);

        int m = ch*256 + tid;
        #pragma unroll
        for (int hh = 0; hh < 8; hh++) {
            float px, py;
            unpk2(P2[hh], px, py);
            g_bias[(((size_t)b*HH + hh)*LL + l)*LL + m] = rstd*((px + py) - mu*scs[hh]) + sct[hh];
        }
    }
}

// FAT: HMMA gemm blocks + bias blocks in one launch
template<int EPI>
__global__ void __launch_bounds__(256) k_fatH(
    int nTilesX, int gemmBlocks,
    const float* __restrict__ A, const float* __restrict__ B, float* __restrict__ C,
    int Nd, int Kd,
    const float* __restrict__ bias,
    const float* __restrict__ gate, int goff,
    const float* __restrict__ res,
    const float* __restrict__ p, const float* __restrict__ g_eln,
    const float* __restrict__ b_eln, const float* __restrict__ W_e,
    const float* __restrict__ b_e, int biasOffset)
{
    extern __shared__ char smf[];
    int bid = blockIdx.x;
    if (bid < gemmBlocks)
        hmma_gemm_body<EPI>(smf, (bid/nTilesX)*128, (bid % nTilesX)*64,
                            A, B, C, Nd, Kd, bias, gate, goff, res);
    else
        bias_body((float*)smf, biasOffset + bid - gemmBlocks, p, g_eln, b_eln, W_e, b_e);
}

// =====================================================================
// k_xmod / k_ln_affine (unchanged)
// =====================================================================
__global__ void k_xmod(const float* __restrict__ src, int sh_off, int sc_off,
                       float* __restrict__ dst)
{
    int row = blockIdx.x, t = threadIdx.x;
    float v = src[(size_t)row*EE + t];
    __shared__ float s1[8], s2[8], bc[2];
    float a = v, b = v*v;
    #pragma unroll
    for (int o = 16; o > 0; o >>= 1) {
        a += __shfl_xor_sync(0xffffffffu, a, o);
        b += __shfl_xor_sync(0xffffffffu, b, o);
    }
    if ((t & 31) == 0) { s1[t>>5] = a; s2[t>>5] = b; }
    __syncthreads();
    if (t == 0) {
        float x = 0, y = 0;
        for (int i = 0; i < 8; i++) { x += s1[i]; y += s2[i]; }
        bc[0] = x*(1.f/EE); bc[1] = y*(1.f/EE);
    }
    __syncthreads();
    float mu = bc[0], var = bc[1] - mu*mu;
    float n = (v - mu)*rsqrtf(var + 1e-5f);
    const float* mrow = g_m + (size_t)row*(6*EE);
    dst[(size_t)row*EE + t] = n*(1.f + mrow[sc_off + t]) + mrow[sh_off + t];
}

__global__ void k_ln_affine(const float* __restrict__ src, const float* __restrict__ g,
                            const float* __restrict__ bt, float* __restrict__ dst)
{
    int row = blockIdx.x, t = threadIdx.x;
    float v = src[(size_t)row*EE + t];
    __shared__ float s1[8], s2[8], bc[2];
    float a = v, b = v*v;
    #pragma unroll
    for (int o = 16; o > 0; o >>= 1) {
        a += __shfl_xor_sync(0xffffffffu, a, o);
        b += __shfl_xor_sync(0xffffffffu, b, o);
    }
    if ((t & 31) == 0) { s1[t>>5] = a; s2[t>>5] = b; }
    __syncthreads();
    if (t == 0) {
        float x = 0, y = 0;
        for (int i = 0; i < 8; i++) { x += s1[i]; y += s2[i]; }
        bc[0] = x*(1.f/EE); bc[1] = y*(1.f/EE);
    }
    __syncthreads();
    float mu = bc[0], var = bc[1] - mu*mu;
    float n = (v - mu)*rsqrtf(var + 1e-5f);
    dst[(size_t)row*EE + t] = n*g[t] + bt[t];
}

// =====================================================================
// k_attn (unchanged, f32x2)
// =====================================================================
__global__ void __launch_bounds__(256) k_attn()
{
    __shared__ __align__(16) float Qs[HD][64];
    __shared__ __align__(16) float Ks[HD][64];
    __shared__ __align__(16) float Vs[64][HD];
    __shared__ __align__(16) float Ps[64][68];
    __shared__ float m_run[64], l_run[64], scl[64];

    int bh = blockIdx.y;
    int b = bh >> 3, h = bh & 7;
    int l0 = blockIdx.x*64;
    int tid = threadIdx.x;

    {
        int r = tid >> 2, c = (tid & 3)*8;
        const float* q = g_qkv + (size_t)(b*LL + l0 + r)*768 + h*HD + c;
        float4 v0 = *(const float4*)q, v1 = *(const float4*)(q+4);
        Qs[c+0][r]=v0.x; Qs[c+1][r]=v0.y; Qs[c+2][r]=v0.z; Qs[c+3][r]=v0.w;
        Qs[c+4][r]=v1.x; Qs[c+5][r]=v1.y; Qs[c+6][r]=v1.z; Qs[c+7][r]=v1.w;
    }
    if (tid < 64) { m_run[tid] = -1e30f; l_run[tid] = 0.f; }

    int tx = tid & 15, ty = tid >> 4;
    int tx2 = tid & 7, ty2 = tid >> 3;
    u64 o2[2][2] = {};
    const float sc = 0.17677669529663687f;

    for (int m0 = 0; m0 < LL; m0 += 64) {
        __syncthreads();
        {
            int r = tid >> 2, c = (tid & 3)*8;
            const float* kp = g_qkv + (size_t)(b*LL + m0 + r)*768 + 256 + h*HD + c;
            float4 v0 = *(const float4*)kp, v1 = *(const float4*)(kp+4);
            Ks[c+0][r]=v0.x; Ks[c+1][r]=v0.y; Ks[c+2][r]=v0.z; Ks[c+3][r]=v0.w;
            Ks[c+4][r]=v1.x; Ks[c+5][r]=v1.y; Ks[c+6][r]=v1.z; Ks[c+7][r]=v1.w;
            const float* vp = g_qkv + (size_t)(b*LL + m0 + r)*768 + 512 + h*HD + c;
            *(float4*)&Vs[r][c]   = *(const float4*)vp;
            *(float4*)&Vs[r][c+4] = *(const float4*)(vp+4);
        }
        __syncthreads();

        float s[4][4];
        {
            u64 qk2[4][2] = {};
            #pragma unroll
            for (int d = 0; d < HD; d++) {
                float4 qa = *(const float4*)&Qs[d][ty*4];
                float4 kb = *(const float4*)&Ks[d][tx*4];
                u64 k01 = ((const u64*)&kb)[0];
                u64 k23 = ((const u64*)&kb)[1];
                float qv[4] = {qa.x, qa.y, qa.z, qa.w};
                #pragma unroll
                for (int i = 0; i < 4; i++) {
                    u64 qd = pk2(qv[i], qv[i]);
                    fma2(qk2[i][0], qd, k01);
                    fma2(qk2[i][1], qd, k23);
                }
            }
            const float* bptr = g_bias + ((size_t)((b*HH + h)*LL + l0 + ty*4))*LL + m0 + tx*4;
            #pragma unroll
            for (int i = 0; i < 4; i++) {
                float q0, q1, q2v, q3;
                unpk2(qk2[i][0], q0, q1);
                unpk2(qk2[i][1], q2v, q3);
                float4 bb = *(const float4*)(bptr + (size_t)i*LL);
                s[i][0] = q0*sc + bb.x;  s[i][1] = q1*sc + bb.y;
                s[i][2] = q2v*sc + bb.z; s[i][3] = q3*sc + bb.w;
            }
        }

        #pragma unroll
        for (int i = 0; i < 4; i++) {
            int row = ty*4 + i;
            float rm = fmaxf(fmaxf(s[i][0], s[i][1]), fmaxf(s[i][2], s[i][3]));
            #pragma unroll
            for (int o = 8; o > 0; o >>= 1)
                rm = fmaxf(rm, __shfl_xor_sync(0xffffffffu, rm, o));
            float mold = m_run[row];
            float mnew = fmaxf(mold, rm);
            float p0 = __expf(s[i][0] - mnew);
            float p1 = __expf(s[i][1] - mnew);
            float p2 = __expf(s[i][2] - mnew);
            float p3 = __expf(s[i][3] - mnew);
            float rs = p0 + p1 + p2 + p3;
            #pragma unroll
            for (int o = 8; o > 0; o >>= 1)
                rs += __shfl_xor_sync(0xffffffffu, rs, o);
            if (tx == 0) {
                float f = __expf(mold - mnew);
                m_run[row] = mnew;
                l_run[row] = l_run[row]*f + rs;
                scl[row] = f;
            }
            float4 pv4; pv4.x = p0; pv4.y = p1; pv4.z = p2; pv4.w = p3;
            *(float4*)&Ps[row][tx*4] = pv4;
        }
        __syncthreads();

        {
            int r0 = ty2*2;
            u64 f0d = pk2(scl[r0],   scl[r0]);
            u64 f1d = pk2(scl[r0+1], scl[r0+1]);
            mul2(o2[0][0], f0d); mul2(o2[0][1], f0d);
            mul2(o2[1][0], f1d); mul2(o2[1][1], f1d);
            #pragma unroll
            for (int kk = 0; kk < 64; kk += 4) {
                float4 pa4 = *(const float4*)&Ps[r0][kk];
                float4 pb4 = *(const float4*)&Ps[r0+1][kk];
                float pa[4] = {pa4.x, pa4.y, pa4.z, pa4.w};
                float pb[4] = {pb4.x, pb4.y, pb4.z, pb4.w};
                #pragma unroll
                for (int u = 0; u < 4; u++) {
                    float4 vv = *(const float4*)&Vs[kk+u][tx2*4];
                    u64 v01 = ((const u64*)&vv)[0];
                    u64 v23 = ((const u64*)&vv)[1];
                    u64 pad = pk2(pa[u], pa[u]);
                    u64 pbd = pk2(pb[u], pb[u]);
                    fma2(o2[0][0], pad, v01); fma2(o2[0][1], pad, v23);
                    fma2(o2[1][0], pbd, v01); fma2(o2[1][1], pbd, v23);
                }
            }
        }
    }

    int r0 = ty2*2;
    float inv0 = 1.f/l_run[r0], inv1 = 1.f/l_run[r0+1];
    float4 o0, o1;
    unpk2(o2[0][0], o0.x, o0.y); unpk2(o2[0][1], o0.z, o0.w);
    unpk2(o2[1][0], o1.x, o1.y); unpk2(o2[1][1], o1.z, o1.w);
    o0.x *= inv0; o0.y *= inv0; o0.z *= inv0; o0.w *= inv0;
    o1.x *= inv1; o1.y *= inv1; o1.z *= inv1; o1.w *= inv1;
    *(float4*)&g_o[(size_t)(b*LL + l0 + r0    )*EE + h*HD + tx2*4] = o0;
    *(float4*)&g_o[(size_t)(b*LL + l0 + r0 + 1)*EE + h*HD + tx2*4] = o1;
}

// =====================================================================
// launch
// =====================================================================
extern "C" void kernel_launch(void* const* d_in, const int* in_sizes, int n_in,
                              void* d_out, int out_size)
{
    const float* h      = (const float*)d_in[0];
    const float* h_init = (const float*)d_in[1];
    const float* s_a    = (const float*)d_in[2];
    const float* s_t    = (const float*)d_in[3];
    const float* s_tem  = (const float*)d_in[4];
    const float* p      = (const float*)d_in[5];
    const float* W_bp   = (const float*)d_in[6];
    const float* b_bp   = (const float*)d_in[7];
    const float* W_ada  = (const float*)d_in[8];
    const float* b_ada  = (const float*)d_in[9];
    const float* g_eln  = (const float*)d_in[10];
    const float* b_eln  = (const float*)d_in[11];
    const float* W_e    = (const float*)d_in[12];
    const float* b_e    = (const float*)d_in[13];
    const float* W_in   = (const float*)d_in[14];
    const float* b_in   = (const float*)d_in[15];
    const float* W_out  = (const float*)d_in[16];
    const float* b_out  = (const float*)d_in[17];
    const float* W1     = (const float*)d_in[18];
    const float* b1     = (const float*)d_in[19];
    const float* W2     = (const float*)d_in[20];
    const float* b2     = (const float*)d_in[21];
    const float* W_tem  = (const float*)d_in[22];
    const float* b_tem  = (const float*)d_in[23];
    const float* g_tem  = (const float*)d_in[24];
    const float* bt_tem = (const float*)d_in[25];
    const float* W_init = (const float*)d_in[26];
    const float* b_init = (const float*)d_in[27];
    const float* g_init = (const float*)d_in[28];
    const float* bt_init= (const float*)d_in[29];
    float* out = (float*)d_out;

    float *pu, *pm, *px, *pqkv, *po, *ph1, *pt1, *ph2;
    cudaGetSymbolAddress((void**)&pu,   g_u);
    cudaGetSymbolAddress((void**)&pm,   g_m);
    cudaGetSymbolAddress((void**)&px,   g_x);
    cudaGetSymbolAddress((void**)&pqkv, g_qkv);
    cudaGetSymbolAddress((void**)&po,   g_o);
    cudaGetSymbolAddress((void**)&ph1,  g_h1);
    cudaGetSymbolAddress((void**)&pt1,  g_t1);
    cudaGetSymbolAddress((void**)&ph2,  g_h2);

    cudaFuncSetAttribute(k_fatH<EPI_ADD_SILU>, cudaFuncAttributeMaxDynamicSharedMemorySize, FAT_SMEM);
    cudaFuncSetAttribute(k_fatH<EPI_BIAS>,     cudaFuncAttributeMaxDynamicSharedMemorySize, FAT_SMEM);
    cudaFuncSetAttribute(k_gemmH<EPI_BIAS>,     cudaFuncAttributeMaxDynamicSharedMemorySize, GEMM_SMEM);
    cudaFuncSetAttribute(k_gemmH<EPI_SILU>,     cudaFuncAttributeMaxDynamicSharedMemorySize, GEMM_SMEM);
    cudaFuncSetAttribute(k_gemmH<EPI_GATE_RES>, cudaFuncAttributeMaxDynamicSharedMemorySize, GEMM_SMEM);
    cudaFuncSetAttribute(k_gemmH<EPI_ADD_RES>,  cudaFuncAttributeMaxDynamicSharedMemorySize, GEMM_SMEM);

    const int B1 = 1024, B2 = 4096 - B1;

    // 1) cond1 (u = silu(s_a@W_bp^T + b_bp + s_t)) + bias part 1
    k_fatH<EPI_ADD_SILU><<<4*32 + B1, 256, FAT_SMEM>>>(
        4, 4*32, s_a, W_bp, pu, TD_, BD_, b_bp, nullptr, 0, s_t,
        p, g_eln, b_eln, W_e, b_e, 0);

    // 2) ada GEMM + bias part 2
    k_fatH<EPI_BIAS><<<24*32 + B2, 256, FAT_SMEM>>>(
        24, 24*32, pu, W_ada, pm, 6*EE, TD_, b_ada, nullptr, 0, nullptr,
        p, g_eln, b_eln, W_e, b_e, B1);

    // 3) attention branch (qkv 4th -> ncu slot profiles the HMMA GEMM)
    k_xmod<<<NROWS, 256>>>(h, 0, EE, px);
    k_gemmH<EPI_BIAS><<<dim3(12, 32), 256, GEMM_SMEM>>>(
        px, W_in, pqkv, 3*EE, EE, b_in, nullptr, 0, nullptr);
    k_attn<<<dim3(LL/64, BB*HH), 256>>>();
    k_gemmH<EPI_GATE_RES><<<dim3(4, 32), 256, GEMM_SMEM>>>(
        po, W_out, ph1, EE, EE, b_out, pm, 2*EE, h);

    // 4) MLP branch
    k_xmod<<<NROWS, 256>>>(ph1, 3*EE, 4*EE, px);
    k_gemmH<EPI_SILU><<<dim3(8, 32), 256, GEMM_SMEM>>>(
        px, W1, pt1, MM_, EE, b1, nullptr, 0, nullptr);
    k_gemmH<EPI_GATE_RES><<<dim3(4, 32), 256, GEMM_SMEM>>>(
        pt1, W2, ph2, EE, MM_, b2, pm, 5*EE, ph1);

    // 5) trailing conditioning LayerNorms
    k_gemmH<EPI_ADD_RES><<<dim3(4, 32), 256, GEMM_SMEM>>>(
        s_tem, W_tem, px, EE, TE_, b_tem, nullptr, 0, ph2);
    k_ln_affine<<<NROWS, 256>>>(px, g_tem, bt_tem, ph1);
    k_gemmH<EPI_ADD_RES><<<dim3(4, 32), 256, GEMM_SMEM>>>(
        h_init, W_init, px, EE, EE, b_init, nullptr, 0, ph1);
    k_ln_affine<<<NROWS, 256>>>(px, g_init, bt_init, out);
}

// round 11
// speedup vs baseline: 4.6580x; 1.1463x over previous
#include <cuda_runtime.h>
#include <cuda_bf16.h>
#include <math.h>
#include <stdint.h>

// ---- problem constants ----
#define BB 8
#define LL 512
#define EE 256
#define HH 8
#define HD 32
#define BD_ 64
#define TD_ 256
#define TE_ 128
#define ED_ 64
#define MM_ 512
#define NROWS (BB*LL)          // 4096 token rows

typedef unsigned long long u64;

// ---- packed fp32x2 helpers ----
__device__ __forceinline__ u64 pk2(float x, float y) {
    u64 r; asm("mov.b64 %0,{%1,%2};" : "=l"(r) : "f"(x), "f"(y)); return r;
}
__device__ __forceinline__ void fma2(u64& d, u64 a, u64 b) {
    asm("fma.rn.f32x2 %0,%1,%2,%0;" : "+l"(d) : "l"(a), "l"(b));
}
__device__ __forceinline__ void unpk2(u64 v, float& x, float& y) {
    asm("mov.b64 {%0,%1},%2;" : "=f"(x), "=f"(y) : "l"(v));
}

// ---- HMMA helpers (baseline PTX; valid on compute_103) ----
__device__ __forceinline__ uint32_t smem_u32(const void* p) {
    uint32_t a;
    asm("{ .reg .u64 t; cvta.to.shared.u64 t, %1; cvt.u32.u64 %0, t; }" : "=r"(a) : "l"(p));
    return a;
}
__device__ __forceinline__ void ldsm4(uint32_t& r0, uint32_t& r1, uint32_t& r2, uint32_t& r3,
                                      uint32_t addr) {
    asm volatile("ldmatrix.sync.aligned.m8n8.x4.shared.b16 {%0,%1,%2,%3},[%4];"
                 : "=r"(r0), "=r"(r1), "=r"(r2), "=r"(r3) : "r"(addr));
}
__device__ __forceinline__ void mma16816(float* d, const uint32_t* a, const uint32_t* b) {
    asm volatile(
        "mma.sync.aligned.m16n8k16.row.col.f32.bf16.bf16.f32 "
        "{%0,%1,%2,%3},{%4,%5,%6,%7},{%8,%9},{%0,%1,%2,%3};"
        : "+f"(d[0]), "+f"(d[1]), "+f"(d[2]), "+f"(d[3])
        : "r"(a[0]), "r"(a[1]), "r"(a[2]), "r"(a[3]), "r"(b[0]), "r"(b[1]));
}

// split fp32 -> bf16 hi + bf16 lo (residual), packed as bf16x2 pairs
__device__ __forceinline__ void split4(float4 v, uint2& hi, uint2& lo) {
    __nv_bfloat162 h01 = __float22bfloat162_rn(make_float2(v.x, v.y));
    __nv_bfloat162 h23 = __float22bfloat162_rn(make_float2(v.z, v.w));
    float2 f01 = __bfloat1622float2(h01);
    float2 f23 = __bfloat1622float2(h23);
    __nv_bfloat162 l01 = __float22bfloat162_rn(make_float2(v.x - f01.x, v.y - f01.y));
    __nv_bfloat162 l23 = __float22bfloat162_rn(make_float2(v.z - f23.x, v.w - f23.y));
    hi.x = *(uint32_t*)&h01; hi.y = *(uint32_t*)&h23;
    lo.x = *(uint32_t*)&l01; lo.y = *(uint32_t*)&l23;
}
__device__ __forceinline__ void packsplit(float x, float y, uint32_t& hi, uint32_t& lo) {
    __nv_bfloat162 h = __float22bfloat162_rn(make_float2(x, y));
    float2 f = __bfloat1622float2(h);
    __nv_bfloat162 l = __float22bfloat162_rn(make_float2(x - f.x, y - f.y));
    hi = *(uint32_t*)&h; lo = *(uint32_t*)&l;
}

// ---- scratch ----
__device__ float g_u[NROWS*TD_];
__device__ float g_m[NROWS*6*EE];
__device__ float g_x[NROWS*EE];
__device__ float g_bias[(size_t)BB*HH*LL*LL];
__device__ float g_qkv[NROWS*3*EE];
__device__ float g_o[NROWS*EE];
__device__ float g_h1[NROWS*EE];
__device__ float g_t1[NROWS*MM_];
__device__ float g_h2[NROWS*EE];

#define EPI_BIAS     0
#define EPI_SILU     1
#define EPI_GATE_RES 2
#define EPI_ADD_RES  3
#define EPI_ADD_SILU 4

// =====================================================================
// HMMA GEMM body (unchanged from round 10)
// =====================================================================
#define OFF_AHI 0
#define OFF_ALO 16384
#define OFF_BHI 32768
#define OFF_BLO 40960
#define GEMM_SMEM 49152

template<int EPI>
__device__ __forceinline__ void hmma_gemm_body(
    char* sm, int bm, int bn,
    const float* __restrict__ A, const float* __restrict__ B, float* __restrict__ C,
    int Nd, int Kd,
    const float* __restrict__ bias,
    const float* __restrict__ gate, int goff,
    const float* __restrict__ res)
{
    uint32_t sb = smem_u32(sm);
    int tid = threadIdx.x, wid = tid >> 5, lane = tid & 31;
    int wm = (wid & 3)*32, wn = (wid >> 2)*32;

    float acc[2][4][4];
    #pragma unroll
    for (int mi = 0; mi < 2; mi++)
        #pragma unroll
        for (int ni = 0; ni < 4; ni++)
            #pragma unroll
            for (int c = 0; c < 4; c++) acc[mi][ni][c] = 0.f;

    int arow = (lane & 15);
    int acol = (lane >> 4);
    int brow = (lane & 7) + ((lane >> 4) << 3);
    int bcol = (lane >> 3) & 1;

    int nch = Kd >> 6;
    for (int ch = 0; ch < nch; ch++) {
        __syncthreads();
        const float* Ab = A + (size_t)bm*Kd + ch*64;
        #pragma unroll
        for (int i = 0; i < 8; i++) {
            int idx = tid + i*256;
            int r = idx >> 4, c4 = idx & 15;
            float4 v = *(const float4*)(Ab + (size_t)r*Kd + c4*4);
            uint2 hi, lo; split4(v, hi, lo);
            uint32_t off = (uint32_t)(r*128 + c4*8);
            uint32_t sw = off ^ (((uint32_t)(r & 7)) << 4);
            *(uint2*)(sm + OFF_AHI + sw) = hi;
            *(uint2*)(sm + OFF_ALO + sw) = lo;
        }
        const float* Bb = B + (size_t)bn*Kd + ch*64;
        #pragma unroll
        for (int i = 0; i < 4; i++) {
            int idx = tid + i*256;
            int r = idx >> 4, c4 = idx & 15;
            float4 v = *(const float4*)(Bb + (size_t)r*Kd + c4*4);
            uint2 hi, lo; split4(v, hi, lo);
            uint32_t off = (uint32_t)(r*128 + c4*8);
            uint32_t sw = off ^ (((uint32_t)(r & 7)) << 4);
            *(uint2*)(sm + OFF_BHI + sw) = hi;
            *(uint2*)(sm + OFF_BLO + sw) = lo;
        }
        __syncthreads();

        #pragma unroll
        for (int ks = 0; ks < 4; ks++) {
            uint32_t ah[2][4], al[2][4], bh[2][4], bl[2][4];
            #pragma unroll
            for (int mi = 0; mi < 2; mi++) {
                int row = wm + mi*16 + arow;
                uint32_t off = (uint32_t)(row*128 + (ks*2 + acol)*16);
                uint32_t sw = off ^ (((uint32_t)(row & 7)) << 4);
                ldsm4(ah[mi][0], ah[mi][1], ah[mi][2], ah[mi][3], sb + OFF_AHI + sw);
                ldsm4(al[mi][0], al[mi][1], al[mi][2], al[mi][3], sb + OFF_ALO + sw);
            }
            #pragma unroll
            for (int nh = 0; nh < 2; nh++) {
                int row = wn + nh*16 + brow;
                uint32_t off = (uint32_t)(row*128 + (ks*2 + bcol)*16);
                uint32_t sw = off ^ (((uint32_t)(row & 7)) << 4);
                ldsm4(bh[nh][0], bh[nh][1], bh[nh][2], bh[nh][3], sb + OFF_BHI + sw);
                ldsm4(bl[nh][0], bl[nh][1], bl[nh][2], bl[nh][3], sb + OFF_BLO + sw);
            }
            #pragma unroll
            for (int mi = 0; mi < 2; mi++)
                #pragma unroll
                for (int ni = 0; ni < 4; ni++) {
                    const uint32_t* bph = &bh[ni >> 1][(ni & 1)*2];
                    const uint32_t* bpl = &bl[ni >> 1][(ni & 1)*2];
                    mma16816(acc[mi][ni], ah[mi], bph);
                    mma16816(acc[mi][ni], ah[mi], bpl);
                    mma16816(acc[mi][ni], al[mi], bph);
                }
        }
    }

    int g = lane >> 2, tig = lane & 3;
    #pragma unroll
    for (int mi = 0; mi < 2; mi++) {
        #pragma unroll
        for (int ni = 0; ni < 4; ni++) {
            int n0 = bn + wn + ni*8 + tig*2;
            float2 b2 = *(const float2*)&bias[n0];
            #pragma unroll
            for (int rh = 0; rh < 2; rh++) {
                int m = bm + wm + mi*16 + g + rh*8;
                float x0 = acc[mi][ni][rh*2 + 0] + b2.x;
                float x1 = acc[mi][ni][rh*2 + 1] + b2.y;
                if (EPI == EPI_SILU) {
                    x0 = x0 / (1.f + __expf(-x0));
                    x1 = x1 / (1.f + __expf(-x1));
                }
                if (EPI == EPI_GATE_RES) {
                    float2 g2 = *(const float2*)&gate[(size_t)m*(6*EE) + goff + n0];
                    float2 r2 = *(const float2*)&res[(size_t)m*Nd + n0];
                    x0 = x0*g2.x + r2.x;
                    x1 = x1*g2.y + r2.y;
                }
                if (EPI == EPI_ADD_RES) {
                    float2 r2 = *(const float2*)&res[(size_t)m*Nd + n0];
                    x0 += r2.x; x1 += r2.y;
                }
                if (EPI == EPI_ADD_SILU) {
                    float2 r2 = *(const float2*)&res[(size_t)m*Nd + n0];
                    x0 += r2.x; x1 += r2.y;
                    x0 = x0 / (1.f + __expf(-x0));
                    x1 = x1 / (1.f + __expf(-x1));
                }
                *(float2*)&C[(size_t)m*Nd + n0] = make_float2(x0, x1);
            }
        }
    }
}

template<int EPI>
__global__ void __launch_bounds__(256) k_gemmH(
    const float* __restrict__ A, const float* __restrict__ B, float* __restrict__ C,
    int Nd, int Kd,
    const float* __restrict__ bias,
    const float* __restrict__ gate, int goff,
    const float* __restrict__ res)
{
    extern __shared__ char smh[];
    hmma_gemm_body<EPI>(smh, blockIdx.y*128, blockIdx.x*64, A, B, C, Nd, Kd, bias, gate, goff, res);
}

// =====================================================================
// bias body (unchanged)
// =====================================================================
#define FAT_SMEM ((256*64 + 512 + 16)*4)
__device__ __forceinline__ void bias_body(
        float* sm, int blk,
        const float* __restrict__ p, const float* __restrict__ g_eln,
        const float* __restrict__ b_eln, const float* __restrict__ W_e,
        const float* __restrict__ b_e)
{
    float* sW   = sm + 256*64;
    float* scs  = sW + 512;
    float* sct  = scs + 8;
    int tid = threadIdx.x;

    for (int i = tid; i < 512; i += 256) sW[i] = g_eln[i & 63]*W_e[i];
    if (tid < 8) {
        float ct = 0.f;
        for (int k = 0; k < 64; k++) ct += b_eln[k]*W_e[tid*64 + k];
        sct[tid] = ct + b_e[tid];
    }
    __syncthreads();
    if (tid < 8) {
        float cs = 0.f;
        for (int k = 0; k < 64; k++) cs += sW[tid*64 + k];
        scs[tid] = cs;
    }

    int b = blk >> 9, l = blk & 511;
    const float4* src = (const float4*)(p + (size_t)blk*512*64);
    u64 one2 = pk2(1.f, 1.f);
    int swz = tid & 15;

    for (int ch = 0; ch < 2; ch++) {
        __syncthreads();
        #pragma unroll
        for (int j = 0; j < 16; j++) {
            float4 v = src[ch*4096 + j*256 + tid];
            int lin = j*256 + tid;
            int r = lin >> 4, c = lin & 15;
            *(float4*)&sm[r*64 + ((c ^ (r & 15)) << 2)] = v;
        }
        __syncthreads();

        const float* base = sm + tid*64;
        u64 P2[8] = {};
        u64 s2 = 0, q2 = 0;
        #pragma unroll
        for (int c = 0; c < 16; c++) {
            float4 a4 = *(const float4*)&base[(c ^ swz) << 2];
            u64 a01 = ((const u64*)&a4)[0];
            u64 a23 = ((const u64*)&a4)[1];
            fma2(s2, a01, one2); fma2(s2, a23, one2);
            fma2(q2, a01, a01);  fma2(q2, a23, a23);
            #pragma unroll
            for (int hh = 0; hh < 8; hh++) {
                float4 w4 = *(const float4*)&sW[hh*64 + c*4];
                fma2(P2[hh], a01, ((const u64*)&w4)[0]);
                fma2(P2[hh], a23, ((const u64*)&w4)[1]);
            }
        }
        float sx, sy, qx, qy;
        unpk2(s2, sx, sy); unpk2(q2, qx, qy);
        float s = sx + sy, q = qx + qy;
        float mu = s*(1.f/64.f);
        float var = q*(1.f/64.f) - mu*mu;
        float rstd = rsqrtf(var + 1e-5f);

        int m = ch*256 + tid;
        #pragma unroll
        for (int hh = 0; hh < 8; hh++) {
            float px, py;
            unpk2(P2[hh], px, py);
            g_bias[(((size_t)b*HH + hh)*LL + l)*LL + m] = rstd*((px + py) - mu*scs[hh]) + sct[hh];
        }
    }
}

template<int EPI>
__global__ void __launch_bounds__(256) k_fatH(
    int nTilesX, int gemmBlocks,
    const float* __restrict__ A, const float* __restrict__ B, float* __restrict__ C,
    int Nd, int Kd,
    const float* __restrict__ bias,
    const float* __restrict__ gate, int goff,
    const float* __restrict__ res,
    const float* __restrict__ p, const float* __restrict__ g_eln,
    const float* __restrict__ b_eln, const float* __restrict__ W_e,
    const float* __restrict__ b_e, int biasOffset)
{
    extern __shared__ char smf[];
    int bid = blockIdx.x;
    if (bid < gemmBlocks)
        hmma_gemm_body<EPI>(smf, (bid/nTilesX)*128, (bid % nTilesX)*64,
                            A, B, C, Nd, Kd, bias, gate, goff, res);
    else
        bias_body((float*)smf, biasOffset + bid - gemmBlocks, p, g_eln, b_eln, W_e, b_e);
}

// =====================================================================
// k_xmod / k_ln_affine (unchanged)
// =====================================================================
__global__ void k_xmod(const float* __restrict__ src, int sh_off, int sc_off,
                       float* __restrict__ dst)
{
    int row = blockIdx.x, t = threadIdx.x;
    float v = src[(size_t)row*EE + t];
    __shared__ float s1[8], s2[8], bc[2];
    float a = v, b = v*v;
    #pragma unroll
    for (int o = 16; o > 0; o >>= 1) {
        a += __shfl_xor_sync(0xffffffffu, a, o);
        b += __shfl_xor_sync(0xffffffffu, b, o);
    }
    if ((t & 31) == 0) { s1[t>>5] = a; s2[t>>5] = b; }
    __syncthreads();
    if (t == 0) {
        float x = 0, y = 0;
        for (int i = 0; i < 8; i++) { x += s1[i]; y += s2[i]; }
        bc[0] = x*(1.f/EE); bc[1] = y*(1.f/EE);
    }
    __syncthreads();
    float mu = bc[0], var = bc[1] - mu*mu;
    float n = (v - mu)*rsqrtf(var + 1e-5f);
    const float* mrow = g_m + (size_t)row*(6*EE);
    dst[(size_t)row*EE + t] = n*(1.f + mrow[sc_off + t]) + mrow[sh_off + t];
}

__global__ void k_ln_affine(const float* __restrict__ src, const float* __restrict__ g,
                            const float* __restrict__ bt, float* __restrict__ dst)
{
    int row = blockIdx.x, t = threadIdx.x;
    float v = src[(size_t)row*EE + t];
    __shared__ float s1[8], s2[8], bc[2];
    float a = v, b = v*v;
    #pragma unroll
    for (int o = 16; o > 0; o >>= 1) {
        a += __shfl_xor_sync(0xffffffffu, a, o);
        b += __shfl_xor_sync(0xffffffffu, b, o);
    }
    if ((t & 31) == 0) { s1[t>>5] = a; s2[t>>5] = b; }
    __syncthreads();
    if (t == 0) {
        float x = 0, y = 0;
        for (int i = 0; i < 8; i++) { x += s1[i]; y += s2[i]; }
        bc[0] = x*(1.f/EE); bc[1] = y*(1.f/EE);
    }
    __syncthreads();
    float mu = bc[0], var = bc[1] - mu*mu;
    float n = (v - mu)*rsqrtf(var + 1e-5f);
    dst[(size_t)row*EE + t] = n*g[t] + bt[t];
}

// =====================================================================
// k_attnH: HMMA flash attention. Block = (b,h,l-tile 64), 128 threads,
// warp w owns l-rows [w*16, w*16+16). Split-bf16 3-pass for QK and PV.
// Softmax entirely on register fragments; P feeds PV mma directly.
// smem: Q/K split 64x32 bf16 (64B rows, chunk swz ^((r>>1)&3));
//       Vt split 32x64 bf16 (128B rows, chunk swz ^(r&7)).
// =====================================================================
__global__ void __launch_bounds__(128) k_attnH()
{
    __shared__ __align__(16) char sQh[4096], sQl[4096];
    __shared__ __align__(16) char sKh[4096], sKl[4096];
    __shared__ __align__(16) char sVh[8192], sVl[8192];

    int tid = threadIdx.x, lane = tid & 31, wid = tid >> 5;
    int bh = blockIdx.y;
    int b = bh >> 3, h = bh & 7;
    int l0 = blockIdx.x*64;
    int wm = wid*16;
    int g = lane >> 2, tig = lane & 3;

    // ---- stage Q (split bf16) ----
    #pragma unroll
    for (int i = 0; i < 4; i++) {
        int idx = tid + i*128;
        int r = idx >> 3, c4 = idx & 7;
        float4 v = *(const float4*)(g_qkv + (size_t)(b*LL + l0 + r)*768 + h*HD + c4*4);
        uint2 hi, lo; split4(v, hi, lo);
        int chunk = c4 >> 1, half = c4 & 1;
        int cs = chunk ^ ((r >> 1) & 3);
        int addr = r*64 + cs*16 + half*8;
        *(uint2*)(sQh + addr) = hi;
        *(uint2*)(sQl + addr) = lo;
    }
    __syncthreads();

    // ---- load Q fragments (kept in regs for whole kernel) ----
    uint32_t qh[2][4], ql[2][4];
    {
        int arow = lane & 15, acol = lane >> 4;
        int row = wm + arow;
        #pragma unroll
        for (int kt = 0; kt < 2; kt++) {
            int c = kt*2 + acol;
            int cs = c ^ ((row >> 1) & 3);
            uint32_t off = (uint32_t)(row*64 + cs*16);
            ldsm4(qh[kt][0], qh[kt][1], qh[kt][2], qh[kt][3], smem_u32(sQh) + off);
            ldsm4(ql[kt][0], ql[kt][1], ql[kt][2], ql[kt][3], smem_u32(sQl) + off);
        }
    }

    float of[4][4];
    #pragma unroll
    for (int nt = 0; nt < 4; nt++)
        #pragma unroll
        for (int c = 0; c < 4; c++) of[nt][c] = 0.f;
    float m_run[2] = {-1e30f, -1e30f};
    float l_run[2] = {0.f, 0.f};

    int brow = (lane & 7) + ((lane >> 4) << 3);
    int bcol = (lane >> 3) & 1;
    const float sc = 0.17677669529663687f;   // 1/sqrt(32)

    for (int ch = 0; ch < 8; ch++) {
        int m0 = ch*64;
        __syncthreads();   // K/V buffer reuse
        // ---- stage K (split bf16, same layout as Q) ----
        #pragma unroll
        for (int i = 0; i < 4; i++) {
            int idx = tid + i*128;
            int r = idx >> 3, c4 = idx & 7;
            float4 v = *(const float4*)(g_qkv + (size_t)(b*LL + m0 + r)*768 + 256 + h*HD + c4*4);
            uint2 hi, lo; split4(v, hi, lo);
            int chunk = c4 >> 1, half = c4 & 1;
            int cs = chunk ^ ((r >> 1) & 3);
            int addr = r*64 + cs*16 + half*8;
            *(uint2*)(sKh + addr) = hi;
            *(uint2*)(sKl + addr) = lo;
        }
        // ---- stage V transposed: Vt[hd][m] (split bf16) ----
        #pragma unroll
        for (int i = 0; i < 4; i++) {
            int idx = tid + i*128;
            int m = idx >> 3, c4 = idx & 7;
            float4 v = *(const float4*)(g_qkv + (size_t)(b*LL + m0 + m)*768 + 512 + h*HD + c4*4);
            float vf[4] = {v.x, v.y, v.z, v.w};
            #pragma unroll
            for (int j = 0; j < 4; j++) {
                int hd = c4*4 + j;
                __nv_bfloat16 hb = __float2bfloat16_rn(vf[j]);
                __nv_bfloat16 lb = __float2bfloat16_rn(vf[j] - __bfloat162float(hb));
                int cs = (m >> 3) ^ (hd & 7);
                int addr = hd*128 + cs*16 + (m & 7)*2;
                *(__nv_bfloat16*)(sVh + addr) = hb;
                *(__nv_bfloat16*)(sVl + addr) = lb;
            }
        }
        __syncthreads();

        // ---- S = Q K^T (split-bf16, 3 passes) ----
        float s[8][4];
        #pragma unroll
        for (int nt = 0; nt < 8; nt++)
            #pragma unroll
            for (int c = 0; c < 4; c++) s[nt][c] = 0.f;
        #pragma unroll
        for (int ng = 0; ng < 4; ng++) {
            int row = ng*16 + brow;
            #pragma unroll
            for (int kt = 0; kt < 2; kt++) {
                int c = kt*2 + bcol;
                int cs = c ^ ((row >> 1) & 3);
                uint32_t off = (uint32_t)(row*64 + cs*16);
                uint32_t kh[4], kl[4];
                ldsm4(kh[0], kh[1], kh[2], kh[3], smem_u32(sKh) + off);
                ldsm4(kl[0], kl[1], kl[2], kl[3], smem_u32(sKl) + off);
                mma16816(s[2*ng],   qh[kt], &kh[0]);
                mma16816(s[2*ng+1], qh[kt], &kh[2]);
                mma16816(s[2*ng],   qh[kt], &kl[0]);
                mma16816(s[2*ng+1], qh[kt], &kl[2]);
                mma16816(s[2*ng],   ql[kt], &kh[0]);
                mma16816(s[2*ng+1], ql[kt], &kh[2]);
            }
        }

        // ---- scale + bias ----
        {
            const float* bp = g_bias + (((size_t)(b*HH + h)*LL + l0 + wm + g))*LL + m0 + tig*2;
            #pragma unroll
            for (int nt = 0; nt < 8; nt++) {
                float2 b0 = *(const float2*)(bp + nt*8);
                float2 b1 = *(const float2*)(bp + 8*(size_t)LL + nt*8);
                s[nt][0] = s[nt][0]*sc + b0.x;
                s[nt][1] = s[nt][1]*sc + b0.y;
                s[nt][2] = s[nt][2]*sc + b1.x;
                s[nt][3] = s[nt][3]*sc + b1.y;
            }
        }

        // ---- online softmax per row-half (rows g, g+8) ----
        #pragma unroll
        for (int hf = 0; hf < 2; hf++) {
            int c0 = hf*2;
            float rm = -1e30f;
            #pragma unroll
            for (int nt = 0; nt < 8; nt++)
                rm = fmaxf(rm, fmaxf(s[nt][c0], s[nt][c0+1]));
            rm = fmaxf(rm, __shfl_xor_sync(0xffffffffu, rm, 1));
            rm = fmaxf(rm, __shfl_xor_sync(0xffffffffu, rm, 2));
            float mnew = fmaxf(m_run[hf], rm);
            float f = __expf(m_run[hf] - mnew);
            float rs = 0.f;
            #pragma unroll
            for (int nt = 0; nt < 8; nt++) {
                float p0 = __expf(s[nt][c0]   - mnew);
                float p1 = __expf(s[nt][c0+1] - mnew);
                s[nt][c0] = p0; s[nt][c0+1] = p1;
                rs += p0 + p1;
            }
            rs += __shfl_xor_sync(0xffffffffu, rs, 1);
            rs += __shfl_xor_sync(0xffffffffu, rs, 2);
            l_run[hf] = l_run[hf]*f + rs;
            m_run[hf] = mnew;
            #pragma unroll
            for (int nt = 0; nt < 4; nt++) { of[nt][c0] *= f; of[nt][c0+1] *= f; }
        }

        // ---- O += P V (split-bf16, 3 passes); P from S fragments ----
        #pragma unroll
        for (int jp = 0; jp < 4; jp++) {
            uint32_t ah[4], al[4];
            packsplit(s[2*jp][0],   s[2*jp][1],   ah[0], al[0]);
            packsplit(s[2*jp][2],   s[2*jp][3],   ah[1], al[1]);
            packsplit(s[2*jp+1][0], s[2*jp+1][1], ah[2], al[2]);
            packsplit(s[2*jp+1][2], s[2*jp+1][3], ah[3], al[3]);
            uint32_t vh[2][4], vl[2][4];
            #pragma unroll
            for (int nh = 0; nh < 2; nh++) {
                int row = nh*16 + brow;
                int c = jp*2 + bcol;
                int cs = c ^ (row & 7);
                uint32_t off = (uint32_t)(row*128 + cs*16);
                ldsm4(vh[nh][0], vh[nh][1], vh[nh][2], vh[nh][3], smem_u32(sVh) + off);
                ldsm4(vl[nh][0], vl[nh][1], vl[nh][2], vl[nh][3], smem_u32(sVl) + off);
            }
            #pragma unroll
            for (int nt = 0; nt < 4; nt++) {
                const uint32_t* bph = &vh[nt >> 1][(nt & 1)*2];
                const uint32_t* bpl = &vl[nt >> 1][(nt & 1)*2];
                mma16816(of[nt], ah, bph);
                mma16816(of[nt], ah, bpl);
                mma16816(of[nt], al, bph);
            }
        }
    }

    // ---- finalize & write ----
    float inv0 = 1.f/l_run[0], inv1 = 1.f/l_run[1];
    #pragma unroll
    for (int nt = 0; nt < 4; nt++) {
        int col = h*HD + nt*8 + tig*2;
        int r0 = b*LL + l0 + wm + g;
        *(float2*)&g_o[(size_t)r0*EE + col] =
            make_float2(of[nt][0]*inv0, of[nt][1]*inv0);
        *(float2*)&g_o[(size_t)(r0 + 8)*EE + col] =
            make_float2(of[nt][2]*inv1, of[nt][3]*inv1);
    }
}

// =====================================================================
// launch
// =====================================================================
extern "C" void kernel_launch(void* const* d_in, const int* in_sizes, int n_in,
                              void* d_out, int out_size)
{
    const float* h      = (const float*)d_in[0];
    const float* h_init = (const float*)d_in[1];
    const float* s_a    = (const float*)d_in[2];
    const float* s_t    = (const float*)d_in[3];
    const float* s_tem  = (const float*)d_in[4];
    const float* p      = (const float*)d_in[5];
    const float* W_bp   = (const float*)d_in[6];
    const float* b_bp   = (const float*)d_in[7];
    const float* W_ada  = (const float*)d_in[8];
    const float* b_ada  = (const float*)d_in[9];
    const float* g_eln  = (const float*)d_in[10];
    const float* b_eln  = (const float*)d_in[11];
    const float* W_e    = (const float*)d_in[12];
    const float* b_e    = (const float*)d_in[13];
    const float* W_in   = (const float*)d_in[14];
    const float* b_in   = (const float*)d_in[15];
    const float* W_out  = (const float*)d_in[16];
    const float* b_out  = (const float*)d_in[17];
    const float* W1     = (const float*)d_in[18];
    const float* b1     = (const float*)d_in[19];
    const float* W2     = (const float*)d_in[20];
    const float* b2     = (const float*)d_in[21];
    const float* W_tem  = (const float*)d_in[22];
    const float* b_tem  = (const float*)d_in[23];
    const float* g_tem  = (const float*)d_in[24];
    const float* bt_tem = (const float*)d_in[25];
    const float* W_init = (const float*)d_in[26];
    const float* b_init = (const float*)d_in[27];
    const float* g_init = (const float*)d_in[28];
    const float* bt_init= (const float*)d_in[29];
    float* out = (float*)d_out;

    float *pu, *pm, *px, *pqkv, *po, *ph1, *pt1, *ph2;
    cudaGetSymbolAddress((void**)&pu,   g_u);
    cudaGetSymbolAddress((void**)&pm,   g_m);
    cudaGetSymbolAddress((void**)&px,   g_x);
    cudaGetSymbolAddress((void**)&pqkv, g_qkv);
    cudaGetSymbolAddress((void**)&po,   g_o);
    cudaGetSymbolAddress((void**)&ph1,  g_h1);
    cudaGetSymbolAddress((void**)&pt1,  g_t1);
    cudaGetSymbolAddress((void**)&ph2,  g_h2);

    cudaFuncSetAttribute(k_fatH<EPI_ADD_SILU>, cudaFuncAttributeMaxDynamicSharedMemorySize, FAT_SMEM);
    cudaFuncSetAttribute(k_fatH<EPI_BIAS>,     cudaFuncAttributeMaxDynamicSharedMemorySize, FAT_SMEM);
    cudaFuncSetAttribute(k_gemmH<EPI_BIAS>,     cudaFuncAttributeMaxDynamicSharedMemorySize, GEMM_SMEM);
    cudaFuncSetAttribute(k_gemmH<EPI_SILU>,     cudaFuncAttributeMaxDynamicSharedMemorySize, GEMM_SMEM);
    cudaFuncSetAttribute(k_gemmH<EPI_GATE_RES>, cudaFuncAttributeMaxDynamicSharedMemorySize, GEMM_SMEM);
    cudaFuncSetAttribute(k_gemmH<EPI_ADD_RES>,  cudaFuncAttributeMaxDynamicSharedMemorySize, GEMM_SMEM);

    const int B1 = 1024, B2 = 4096 - B1;

    // 1) cond1 (u = silu(s_a@W_bp^T + b_bp + s_t)) + bias part 1
    k_fatH<EPI_ADD_SILU><<<4*32 + B1, 256, FAT_SMEM>>>(
        4, 4*32, s_a, W_bp, pu, TD_, BD_, b_bp, nullptr, 0, s_t,
        p, g_eln, b_eln, W_e, b_e, 0);

    // 2) ada GEMM + bias part 2
    k_fatH<EPI_BIAS><<<24*32 + B2, 256, FAT_SMEM>>>(
        24, 24*32, pu, W_ada, pm, 6*EE, TD_, b_ada, nullptr, 0, nullptr,
        p, g_eln, b_eln, W_e, b_e, B1);

    // 3) attention branch
    k_xmod<<<NROWS, 256>>>(h, 0, EE, px);
    k_gemmH<EPI_BIAS><<<dim3(12, 32), 256, GEMM_SMEM>>>(
        px, W_in, pqkv, 3*EE, EE, b_in, nullptr, 0, nullptr);
    k_attnH<<<dim3(LL/64, BB*HH), 128>>>();
    k_gemmH<EPI_GATE_RES><<<dim3(4, 32), 256, GEMM_SMEM>>>(
        po, W_out, ph1, EE, EE, b_out, pm, 2*EE, h);

    // 4) MLP branch
    k_xmod<<<NROWS, 256>>>(ph1, 3*EE, 4*EE, px);
    k_gemmH<EPI_SILU><<<dim3(8, 32), 256, GEMM_SMEM>>>(
        px, W1, pt1, MM_, EE, b1, nullptr, 0, nullptr);
    k_gemmH<EPI_GATE_RES><<<dim3(4, 32), 256, GEMM_SMEM>>>(
        pt1, W2, ph2, EE, MM_, b2, pm, 5*EE, ph1);

    // 5) trailing conditioning LayerNorms
    k_gemmH<EPI_ADD_RES><<<dim3(4, 32), 256, GEMM_SMEM>>>(
        s_tem, W_tem, px, EE, TE_, b_tem, nullptr, 0, ph2);
    k_ln_affine<<<NROWS, 256>>>(px, g_tem, bt_tem, ph1);
    k_gemmH<EPI_ADD_RES><<<dim3(4, 32), 256, GEMM_SMEM>>>(
        h_init, W_init, px, EE, EE, b_init, nullptr, 0, ph1);
    k_ln_affine<<<NROWS, 256>>>(px, g_init, bt_init, out);
}